// round 5
// baseline (speedup 1.0000x reference)
#include <cuda_runtime.h>
#include <cuda_bf16.h>
#include <math.h>
#include <stdint.h>

#define E_      32
#define KSEL    4
#define H_      1024
#define IDIM    768
#define T_      4096
#define NGROUP  8
#define TOPKG   4
#define CAP     1024
#define NASSIGN (T_ * KSEL)

// ---------------- scratch (device globals; no allocations) ----------------
__device__ __nv_bfloat16 g_bufh[(size_t)E_ * CAP * H_];
__device__ __nv_bfloat16 g_bufl[(size_t)E_ * CAP * H_];
__device__ __nv_bfloat16 g_acth[(size_t)E_ * CAP * IDIM];
__device__ __nv_bfloat16 g_actl[(size_t)E_ * CAP * IDIM];
__device__ __nv_bfloat16 g_w1h[(size_t)E_ * IDIM * H_];
__device__ __nv_bfloat16 g_w1l[(size_t)E_ * IDIM * H_];
__device__ __nv_bfloat16 g_w3h[(size_t)E_ * IDIM * H_];
__device__ __nv_bfloat16 g_w3l[(size_t)E_ * IDIM * H_];
__device__ __nv_bfloat16 g_w2h[(size_t)E_ * H_ * IDIM];
__device__ __nv_bfloat16 g_w2l[(size_t)E_ * H_ * IDIM];
__device__ int   g_cnt  [E_];
__device__ int   g_tok  [E_ * CAP];
__device__ float g_wslot[E_ * CAP];
__device__ int   g_expi [NASSIGN];
__device__ float g_gw   [NASSIGN];

// ---------------- helpers ----------------
__device__ __forceinline__ uint32_t smem_u32(const void* p) {
    uint32_t a;
    asm("{ .reg .u64 t; cvta.to.shared.u64 t, %1; cvt.u32.u64 %0, t; }" : "=r"(a) : "l"(p));
    return a;
}
__device__ __forceinline__ void cp16(uint32_t dst, const void* src) {
    asm volatile("cp.async.cg.shared.global [%0], [%1], 16;" :: "r"(dst), "l"(src));
}
__device__ __forceinline__ void cp_commit() { asm volatile("cp.async.commit_group;"); }
__device__ __forceinline__ void cp_wait1()  { asm volatile("cp.async.wait_group 1;"); }
#define LDSM4(r, a) \
    asm volatile("ldmatrix.sync.aligned.m8n8.x4.shared.b16 {%0,%1,%2,%3}, [%4];" \
        : "=r"((r)[0]), "=r"((r)[1]), "=r"((r)[2]), "=r"((r)[3]) : "r"(a))
__device__ __forceinline__ void mma16816(float* c, const uint32_t* a, uint32_t b0, uint32_t b1) {
    asm volatile(
        "mma.sync.aligned.m16n8k16.row.col.f32.bf16.bf16.f32 "
        "{%0,%1,%2,%3}, {%4,%5,%6,%7}, {%8,%9}, {%0,%1,%2,%3};"
        : "+f"(c[0]), "+f"(c[1]), "+f"(c[2]), "+f"(c[3])
        : "r"(a[0]), "r"(a[1]), "r"(a[2]), "r"(a[3]), "r"(b0), "r"(b1));
}
__device__ __forceinline__ void split2(float x, float y, uint32_t& h, uint32_t& l) {
    __nv_bfloat16 hx = __float2bfloat16(x), hy = __float2bfloat16(y);
    float rx = x - __bfloat162float(hx), ry = y - __bfloat162float(hy);
    __nv_bfloat16 lx = __float2bfloat16(rx), ly = __float2bfloat16(ry);
    h = (uint32_t)__bfloat16_as_ushort(hx) | ((uint32_t)__bfloat16_as_ushort(hy) << 16);
    l = (uint32_t)__bfloat16_as_ushort(lx) | ((uint32_t)__bfloat16_as_ushort(ly) << 16);
}

// ---------------- weight conversion ----------------
__global__ void cvt_kernel(const float4* __restrict__ src, uint2* __restrict__ hi,
                           uint2* __restrict__ lo, int n4) {
    for (int i = blockIdx.x * blockDim.x + threadIdx.x; i < n4; i += gridDim.x * blockDim.x) {
        float4 v = src[i];
        uint32_t h0, l0, h1, l1;
        split2(v.x, v.y, h0, l0);
        split2(v.z, v.w, h1, l1);
        hi[i] = make_uint2(h0, h1);
        lo[i] = make_uint2(l0, l1);
    }
}

// ---------------- router: 16 tokens/block, scores + serial top-k ----------------
#define RTOK 16
__global__ __launch_bounds__(256) void router2(const float* __restrict__ x,
                                               const float* __restrict__ gate_w,
                                               const float* __restrict__ bias) {
    extern __shared__ float rs[];           // xs[16*1024] then sc[16*32]
    float* xs = rs;
    float* sc = rs + RTOK * H_;
    int tid = threadIdx.x, lane = tid & 31, w = tid >> 5;
    int tb = blockIdx.x * RTOK;

    // stage 16 token rows (coalesced float4)
    const float4* xg = (const float4*)(x + (size_t)tb * H_);
    float4* xs4 = (float4*)xs;
    #pragma unroll
    for (int i = 0; i < RTOK; i++) xs4[tid + i * 256] = xg[tid + i * 256];
    __syncthreads();

    // warp w computes experts w*4 .. w*4+3 for all 16 tokens
    #pragma unroll
    for (int j = 0; j < 4; j++) {
        int e = w * 4 + j;
        const float4* g4 = (const float4*)(gate_w + (size_t)e * H_);
        float acc[RTOK];
        #pragma unroll
        for (int t = 0; t < RTOK; t++) acc[t] = 0.f;
        #pragma unroll
        for (int it = 0; it < 8; it++) {
            float4 gv = g4[it * 32 + lane];
            #pragma unroll
            for (int t = 0; t < RTOK; t++) {
                float4 xv = *(const float4*)&xs[t * H_ + (it * 32 + lane) * 4];
                acc[t] += gv.x * xv.x + gv.y * xv.y + gv.z * xv.z + gv.w * xv.w;
            }
        }
        #pragma unroll
        for (int t = 0; t < RTOK; t++) {
            float v = acc[t];
            #pragma unroll
            for (int o = 16; o; o >>= 1) v += __shfl_xor_sync(0xffffffffu, v, o);
            if (lane == 0) sc[t * E_ + e] = v;
        }
    }
    __syncthreads();

    // per-token serial routing (threads 0..15)
    if (tid < RTOK) {
        int t = tb + tid;
        float s[E_], sfc[E_];
        #pragma unroll
        for (int e = 0; e < E_; e++) {
            s[e]   = 1.f / (1.f + expf(-sc[tid * E_ + e]));
            sfc[e] = s[e] + bias[e];
        }
        float gs[NGROUP];
        #pragma unroll
        for (int g = 0; g < NGROUP; g++) {
            float m1 = -1e30f, m2 = -1e30f;
            #pragma unroll
            for (int j = 0; j < 4; j++) {
                float v = sfc[g * 4 + j];
                if (v > m1) { m2 = m1; m1 = v; }
                else if (v > m2) m2 = v;
            }
            gs[g] = m1 + m2;
        }
        bool gsel[NGROUP];
        #pragma unroll
        for (int g = 0; g < NGROUP; g++) gsel[g] = false;
        for (int it = 0; it < TOPKG; it++) {
            float best = -1e30f; int bi = 0;
            #pragma unroll
            for (int g = 0; g < NGROUP; g++)
                if (!gsel[g] && gs[g] > best) { best = gs[g]; bi = g; }
            gsel[bi] = true;
        }
        float tmp[E_];
        #pragma unroll
        for (int e = 0; e < E_; e++) tmp[e] = gsel[e >> 2] ? sfc[e] : 0.f;
        int sel[KSEL];
        for (int k = 0; k < KSEL; k++) {
            float best = -1e30f; int bi = 0;
            #pragma unroll
            for (int e = 0; e < E_; e++)
                if (tmp[e] > best) { best = tmp[e]; bi = e; }
            sel[k] = bi; tmp[bi] = -1e30f;
        }
        float rw[KSEL], rsum = 0.f;
        #pragma unroll
        for (int k = 0; k < KSEL; k++) { rw[k] = s[sel[k]]; rsum += rw[k]; }
        float inv = 1.f / rsum;
        #pragma unroll
        for (int k = 0; k < KSEL; k++) {
            int a = t * KSEL + k;
            g_expi[a] = sel[k];
            g_gw[a]   = rw[k] * inv;
        }
    }
}

// ---------------- deterministic slot assignment (stable token order) ----------------
__global__ __launch_bounds__(1024) void slot_kernel() {
    int e = blockIdx.x, tid = threadIdx.x;
    int lane = tid & 31, warp = tid >> 5;
    __shared__ int warp_sums[32];
    int base = 0;
    for (int c0 = 0; c0 < NASSIGN; c0 += 1024) {
        int a = c0 + tid;
        bool flag = (g_expi[a] == e);
        unsigned bal = __ballot_sync(0xffffffffu, flag);
        int wprefix = __popc(bal & ((1u << lane) - 1u));
        if (lane == 31) warp_sums[warp] = __popc(bal);
        __syncthreads();
        if (warp == 0) {
            int v = warp_sums[lane];
            #pragma unroll
            for (int o = 1; o < 32; o <<= 1) {
                int n = __shfl_up_sync(0xffffffffu, v, o);
                if (lane >= o) v += n;
            }
            warp_sums[lane] = v;
        }
        __syncthreads();
        int woff  = (warp == 0) ? 0 : warp_sums[warp - 1];
        int total = warp_sums[31];
        if (flag) {
            int slot = base + woff + wprefix;
            if (slot < CAP) {
                g_tok[e * CAP + slot]   = a >> 2;
                g_wslot[e * CAP + slot] = g_gw[a];
            }
        }
        base += total;
        __syncthreads();
    }
    if (tid == 0) g_cnt[e] = base < CAP ? base : CAP;
}

// gather: token rows -> per-expert bf16 hi/lo planes
__global__ void gather_kernel(const float* __restrict__ x) {
    int e = blockIdx.y, slot = blockIdx.x;
    if (slot >= g_cnt[e]) return;
    int t = g_tok[e * CAP + slot];
    const float4* src = (const float4*)(x + (size_t)t * H_);
    uint2* dh = (uint2*)(g_bufh + ((size_t)e * CAP + slot) * H_);
    uint2* dl = (uint2*)(g_bufl + ((size_t)e * CAP + slot) * H_);
    for (int i = threadIdx.x; i < H_ / 4; i += blockDim.x) {
        float4 v = src[i];
        uint32_t h0, l0, h1, l1;
        split2(v.x, v.y, h0, l0);
        split2(v.z, v.w, h1, l1);
        dh[i] = make_uint2(h0, h1);
        dl[i] = make_uint2(l0, l1);
    }
}

__global__ void zero_out(float4* o) {
    o[blockIdx.x * 256 + threadIdx.x] = make_float4(0.f, 0.f, 0.f, 0.f);
}

// ---------------- GEMM common ----------------
#define SROW   80            // smem bytes per 32-bf16 K-chunk row (padded)
#define PS     (128 * SROW)  // plane size = 10240 B

// ---------------- GEMM1: fused h1/h3 + SiLU, 3-pass bf16 mma + ldmatrix ----------------
#define G1_PLANES 6
#define G1_STAGE  (G1_PLANES * PS)
#define G1_SMEM   (3 * G1_STAGE)

__global__ __launch_bounds__(256) void gemm1_mma(void) {
    int e   = blockIdx.z;
    int cnt = g_cnt[e];
    int m0  = blockIdx.y * 128;
    if (m0 >= cnt) return;
    int n0  = blockIdx.x * 128;

    extern __shared__ char sm[];
    uint32_t sb = smem_u32(sm);
    int tid = threadIdx.x, lane = tid & 31, wid = tid >> 5;
    int wm = (wid & 1) * 64, wn = (wid >> 1) * 32;
    int g = lane >> 2, tg = lane & 3;
    int lane15 = lane & 15;
    uint32_t lhi  = (uint32_t)(lane >> 4) * 16u;
    uint32_t arow = (uint32_t)(wm + lane15) * SROW + lhi;
    uint32_t brow = (uint32_t)(wn + lane15) * SROW + lhi;

    const __nv_bfloat16* srcs[G1_PLANES] = {
        g_bufh + ((size_t)e * CAP  + m0) * H_,
        g_bufl + ((size_t)e * CAP  + m0) * H_,
        g_w1h  + ((size_t)e * IDIM + n0) * H_,
        g_w1l  + ((size_t)e * IDIM + n0) * H_,
        g_w3h  + ((size_t)e * IDIM + n0) * H_,
        g_w3l  + ((size_t)e * IDIM + n0) * H_
    };
    int lrow = tid >> 1;
    int lcb  = (tid & 1) * 2;
    uint32_t ldst = lrow * SROW + lcb * 16;

    #pragma unroll
    for (int st = 0; st < 2; st++) {
        uint32_t s = sb + st * G1_STAGE + ldst;
        int k0 = st * 32 + lcb * 8;
        #pragma unroll
        for (int p = 0; p < G1_PLANES; p++) {
            const __nv_bfloat16* gp = srcs[p] + (size_t)lrow * H_ + k0;
            cp16(s + p * PS,      gp);
            cp16(s + p * PS + 16, gp + 8);
        }
        cp_commit();
    }

    float c1[4][4][4] = {}, c3[4][4][4] = {};

    const int NK = H_ / 32;
    for (int kt = 0; kt < NK; kt++) {
        cp_wait1();
        __syncthreads();
        if (kt + 2 < NK) {
            uint32_t s = sb + ((kt + 2) % 3) * G1_STAGE + ldst;
            int k0 = (kt + 2) * 32 + lcb * 8;
            #pragma unroll
            for (int p = 0; p < G1_PLANES; p++) {
                const __nv_bfloat16* gp = srcs[p] + (size_t)lrow * H_ + k0;
                cp16(s + p * PS,      gp);
                cp16(s + p * PS + 16, gp + 8);
            }
        }
        cp_commit();

        uint32_t bs = sb + (kt % 3) * G1_STAGE;
        #pragma unroll
        for (int kb = 0; kb < 2; kb++) {
            uint32_t ko = kb * 32;
            #pragma unroll
            for (int p = 0; p < 3; p++) {
                uint32_t ap = (p == 1) ? PS : 0;
                uint32_t bp = (p == 2) ? PS : 0;
                uint32_t A_[4][4];
                #pragma unroll
                for (int mi = 0; mi < 4; mi++)
                    LDSM4(A_[mi], bs + ap + arow + mi * (16 * SROW) + ko);
                uint32_t B1f[4][2], B3f[4][2];
                #pragma unroll
                for (int n2 = 0; n2 < 2; n2++) {
                    uint32_t t_[4];
                    LDSM4(t_, bs + 2 * PS + bp + brow + n2 * (16 * SROW) + ko);
                    B1f[2 * n2][0] = t_[0]; B1f[2 * n2][1] = t_[2];
                    B1f[2 * n2 + 1][0] = t_[1]; B1f[2 * n2 + 1][1] = t_[3];
                    LDSM4(t_, bs + 4 * PS + bp + brow + n2 * (16 * SROW) + ko);
                    B3f[2 * n2][0] = t_[0]; B3f[2 * n2][1] = t_[2];
                    B3f[2 * n2 + 1][0] = t_[1]; B3f[2 * n2 + 1][1] = t_[3];
                }
                #pragma unroll
                for (int mi = 0; mi < 4; mi++)
                    #pragma unroll
                    for (int ni = 0; ni < 4; ni++) {
                        mma16816(c1[mi][ni], A_[mi], B1f[ni][0], B1f[ni][1]);
                        mma16816(c3[mi][ni], A_[mi], B3f[ni][0], B3f[ni][1]);
                    }
            }
        }
    }

    // epilogue: act = silu(h1)*h3 -> bf16 hi/lo
    #pragma unroll
    for (int mi = 0; mi < 4; mi++) {
        int r0 = m0 + wm + mi * 16 + g;
        #pragma unroll
        for (int ni = 0; ni < 4; ni++) {
            int cb = n0 + wn + ni * 8 + tg * 2;
            float h1a = c1[mi][ni][0], h1b = c1[mi][ni][1];
            float v0 = h1a / (1.f + expf(-h1a)) * c3[mi][ni][0];
            float v1 = h1b / (1.f + expf(-h1b)) * c3[mi][ni][1];
            float h1c = c1[mi][ni][2], h1d = c1[mi][ni][3];
            float v2 = h1c / (1.f + expf(-h1c)) * c3[mi][ni][2];
            float v3 = h1d / (1.f + expf(-h1d)) * c3[mi][ni][3];
            uint32_t h, l;
            size_t o0 = ((size_t)e * CAP + r0) * IDIM + cb;
            split2(v0, v1, h, l);
            *(uint32_t*)(g_acth + o0) = h;
            *(uint32_t*)(g_actl + o0) = l;
            size_t o1 = ((size_t)e * CAP + r0 + 8) * IDIM + cb;
            split2(v2, v3, h, l);
            *(uint32_t*)(g_acth + o1) = h;
            *(uint32_t*)(g_actl + o1) = l;
        }
    }
}

// ---------------- GEMM2: y = act @ w2^T, fused weighted scatter into out ----------------
#define G2_PLANES 4
#define G2_STAGE  (G2_PLANES * PS)
#define G2_SMEM   (3 * G2_STAGE)

__global__ __launch_bounds__(256) void gemm2_mma(float* __restrict__ out) {
    int e   = blockIdx.z;
    int cnt = g_cnt[e];
    int m0  = blockIdx.y * 128;
    if (m0 >= cnt) return;
    int n0  = blockIdx.x * 128;

    extern __shared__ char sm[];
    uint32_t sb = smem_u32(sm);
    int tid = threadIdx.x, lane = tid & 31, wid = tid >> 5;
    int wm = (wid & 1) * 64, wn = (wid >> 1) * 32;
    int g = lane >> 2, tg = lane & 3;
    int lane15 = lane & 15;
    uint32_t lhi  = (uint32_t)(lane >> 4) * 16u;
    uint32_t arow = (uint32_t)(wm + lane15) * SROW + lhi;
    uint32_t brow = (uint32_t)(wn + lane15) * SROW + lhi;

    const __nv_bfloat16* srcs[G2_PLANES] = {
        g_acth + ((size_t)e * CAP + m0) * IDIM,
        g_actl + ((size_t)e * CAP + m0) * IDIM,
        g_w2h  + ((size_t)e * H_  + n0) * IDIM,
        g_w2l  + ((size_t)e * H_  + n0) * IDIM
    };
    int lrow = tid >> 1;
    int lcb  = (tid & 1) * 2;
    uint32_t ldst = lrow * SROW + lcb * 16;

    #pragma unroll
    for (int st = 0; st < 2; st++) {
        uint32_t s = sb + st * G2_STAGE + ldst;
        int k0 = st * 32 + lcb * 8;
        #pragma unroll
        for (int p = 0; p < G2_PLANES; p++) {
            const __nv_bfloat16* gp = srcs[p] + (size_t)lrow * IDIM + k0;
            cp16(s + p * PS,      gp);
            cp16(s + p * PS + 16, gp + 8);
        }
        cp_commit();
    }

    float cc[4][4][4] = {};

    const int NK = IDIM / 32;
    for (int kt = 0; kt < NK; kt++) {
        cp_wait1();
        __syncthreads();
        if (kt + 2 < NK) {
            uint32_t s = sb + ((kt + 2) % 3) * G2_STAGE + ldst;
            int k0 = (kt + 2) * 32 + lcb * 8;
            #pragma unroll
            for (int p = 0; p < G2_PLANES; p++) {
                const __nv_bfloat16* gp = srcs[p] + (size_t)lrow * IDIM + k0;
                cp16(s + p * PS,      gp);
                cp16(s + p * PS + 16, gp + 8);
            }
        }
        cp_commit();

        uint32_t bs = sb + (kt % 3) * G2_STAGE;
        #pragma unroll
        for (int kb = 0; kb < 2; kb++) {
            uint32_t ko = kb * 32;
            #pragma unroll
            for (int p = 0; p < 3; p++) {
                uint32_t ap = (p == 1) ? PS : 0;
                uint32_t bp = (p == 2) ? PS : 0;
                uint32_t A_[4][4];
                #pragma unroll
                for (int mi = 0; mi < 4; mi++)
                    LDSM4(A_[mi], bs + ap + arow + mi * (16 * SROW) + ko);
                uint32_t Bf[4][2];
                #pragma unroll
                for (int n2 = 0; n2 < 2; n2++) {
                    uint32_t t_[4];
                    LDSM4(t_, bs + 2 * PS + bp + brow + n2 * (16 * SROW) + ko);
                    Bf[2 * n2][0] = t_[0]; Bf[2 * n2][1] = t_[2];
                    Bf[2 * n2 + 1][0] = t_[1]; Bf[2 * n2 + 1][1] = t_[3];
                }
                #pragma unroll
                for (int mi = 0; mi < 4; mi++)
                    #pragma unroll
                    for (int ni = 0; ni < 4; ni++)
                        mma16816(cc[mi][ni], A_[mi], Bf[ni][0], Bf[ni][1]);
            }
        }
    }

    // fused combine: out[token] += w * y  (atomicAdd; order noise << 1e-3)
    #pragma unroll
    for (int mi = 0; mi < 4; mi++) {
        int r0 = m0 + wm + mi * 16 + g;
        int r1 = r0 + 8;
        bool v0 = r0 < cnt, v1 = r1 < cnt;
        int   t0 = 0, t1 = 0;
        float w0 = 0.f, w1 = 0.f;
        if (v0) { t0 = g_tok[e * CAP + r0]; w0 = g_wslot[e * CAP + r0]; }
        if (v1) { t1 = g_tok[e * CAP + r1]; w1 = g_wslot[e * CAP + r1]; }
        #pragma unroll
        for (int ni = 0; ni < 4; ni++) {
            int cb = n0 + wn + ni * 8 + tg * 2;
            if (v0) {
                atomicAdd(out + (size_t)t0 * H_ + cb,     w0 * cc[mi][ni][0]);
                atomicAdd(out + (size_t)t0 * H_ + cb + 1, w0 * cc[mi][ni][1]);
            }
            if (v1) {
                atomicAdd(out + (size_t)t1 * H_ + cb,     w1 * cc[mi][ni][2]);
                atomicAdd(out + (size_t)t1 * H_ + cb + 1, w1 * cc[mi][ni][3]);
            }
        }
    }
}

// ---------------- launch ----------------
extern "C" void kernel_launch(void* const* d_in, const int* in_sizes, int n_in,
                              void* d_out, int out_size) {
    (void)in_sizes; (void)n_in; (void)out_size;
    const float* x      = (const float*)d_in[0];
    const float* gate_w = (const float*)d_in[1];
    const float* w1     = (const float*)d_in[2];
    const float* w3     = (const float*)d_in[3];
    const float* w2     = (const float*)d_in[4];
    const float* bias   = (const float*)d_in[5];
    float*       out    = (float*)d_out;

    const int RSMEM = (RTOK * H_ + RTOK * E_) * 4;
    cudaFuncSetAttribute(router2,   cudaFuncAttributeMaxDynamicSharedMemorySize, RSMEM);
    cudaFuncSetAttribute(gemm1_mma, cudaFuncAttributeMaxDynamicSharedMemorySize, G1_SMEM);
    cudaFuncSetAttribute(gemm2_mma, cudaFuncAttributeMaxDynamicSharedMemorySize, G2_SMEM);

    void *p_w1h, *p_w1l, *p_w3h, *p_w3l, *p_w2h, *p_w2l;
    cudaGetSymbolAddress(&p_w1h, g_w1h);
    cudaGetSymbolAddress(&p_w1l, g_w1l);
    cudaGetSymbolAddress(&p_w3h, g_w3h);
    cudaGetSymbolAddress(&p_w3l, g_w3l);
    cudaGetSymbolAddress(&p_w2h, g_w2h);
    cudaGetSymbolAddress(&p_w2l, g_w2l);

    const int n4 = E_ * IDIM * H_ / 4;
    cvt_kernel<<<4096, 256>>>((const float4*)w1, (uint2*)p_w1h, (uint2*)p_w1l, n4);
    cvt_kernel<<<4096, 256>>>((const float4*)w3, (uint2*)p_w3h, (uint2*)p_w3l, n4);
    cvt_kernel<<<4096, 256>>>((const float4*)w2, (uint2*)p_w2h, (uint2*)p_w2l, n4);

    router2<<<T_ / RTOK, 256, RSMEM>>>(x, gate_w, bias);
    slot_kernel<<<E_, 1024>>>();
    gather_kernel<<<dim3(CAP, E_), 256>>>(x);
    zero_out<<<T_ * H_ / 4 / 256, 256>>>((float4*)out);
    gemm1_mma<<<dim3(IDIM / 128, CAP / 128, E_), 256, G1_SMEM>>>();
    gemm2_mma<<<dim3(H_ / 128, CAP / 128, E_), 256, G2_SMEM>>>(out);
}

// round 6
// speedup vs baseline: 1.1508x; 1.1508x over previous
#include <cuda_runtime.h>
#include <cuda_bf16.h>
#include <math.h>
#include <stdint.h>

#define E_      32
#define KSEL    4
#define H_      1024
#define IDIM    768
#define T_      4096
#define NGROUP  8
#define TOPKG   4
#define CAP     1024
#define NASSIGN (T_ * KSEL)

// ---------------- scratch (device globals; no allocations) ----------------
__device__ __nv_bfloat16 g_bufh[(size_t)E_ * CAP * H_];
__device__ __nv_bfloat16 g_bufl[(size_t)E_ * CAP * H_];
__device__ __nv_bfloat16 g_acth[(size_t)E_ * CAP * IDIM];
__device__ __nv_bfloat16 g_actl[(size_t)E_ * CAP * IDIM];
__device__ __nv_bfloat16 g_w1h[(size_t)E_ * IDIM * H_];
__device__ __nv_bfloat16 g_w1l[(size_t)E_ * IDIM * H_];
__device__ __nv_bfloat16 g_w3h[(size_t)E_ * IDIM * H_];
__device__ __nv_bfloat16 g_w3l[(size_t)E_ * IDIM * H_];
__device__ __nv_bfloat16 g_w2h[(size_t)E_ * H_ * IDIM];
__device__ __nv_bfloat16 g_w2l[(size_t)E_ * H_ * IDIM];
__device__ float g_y[(size_t)E_ * CAP * H_];
__device__ float g_sc[(size_t)T_ * E_];
__device__ int   g_cnt [E_];
__device__ int   g_tok [E_ * CAP];
__device__ int   g_expi[NASSIGN];
__device__ int   g_slot[NASSIGN];
__device__ float g_gw  [NASSIGN];

// ---------------- helpers ----------------
__device__ __forceinline__ uint32_t smem_u32(const void* p) {
    uint32_t a;
    asm("{ .reg .u64 t; cvta.to.shared.u64 t, %1; cvt.u32.u64 %0, t; }" : "=r"(a) : "l"(p));
    return a;
}
__device__ __forceinline__ void cp16(uint32_t dst, const void* src) {
    asm volatile("cp.async.cg.shared.global [%0], [%1], 16;" :: "r"(dst), "l"(src));
}
__device__ __forceinline__ void cp_commit() { asm volatile("cp.async.commit_group;"); }
__device__ __forceinline__ void cp_wait1()  { asm volatile("cp.async.wait_group 1;"); }
#define LDSM4(r, a) \
    asm volatile("ldmatrix.sync.aligned.m8n8.x4.shared.b16 {%0,%1,%2,%3}, [%4];" \
        : "=r"((r)[0]), "=r"((r)[1]), "=r"((r)[2]), "=r"((r)[3]) : "r"(a))
__device__ __forceinline__ void mma16816(float* c, const uint32_t* a, uint32_t b0, uint32_t b1) {
    asm volatile(
        "mma.sync.aligned.m16n8k16.row.col.f32.bf16.bf16.f32 "
        "{%0,%1,%2,%3}, {%4,%5,%6,%7}, {%8,%9}, {%0,%1,%2,%3};"
        : "+f"(c[0]), "+f"(c[1]), "+f"(c[2]), "+f"(c[3])
        : "r"(a[0]), "r"(a[1]), "r"(a[2]), "r"(a[3]), "r"(b0), "r"(b1));
}
__device__ __forceinline__ void split2(float x, float y, uint32_t& h, uint32_t& l) {
    __nv_bfloat16 hx = __float2bfloat16(x), hy = __float2bfloat16(y);
    float rx = x - __bfloat162float(hx), ry = y - __bfloat162float(hy);
    __nv_bfloat16 lx = __float2bfloat16(rx), ly = __float2bfloat16(ry);
    h = (uint32_t)__bfloat16_as_ushort(hx) | ((uint32_t)__bfloat16_as_ushort(hy) << 16);
    l = (uint32_t)__bfloat16_as_ushort(lx) | ((uint32_t)__bfloat16_as_ushort(ly) << 16);
}

// ---------------- weight conversion ----------------
__global__ void cvt_kernel(const float4* __restrict__ src, uint2* __restrict__ hi,
                           uint2* __restrict__ lo, int n4) {
    for (int i = blockIdx.x * blockDim.x + threadIdx.x; i < n4; i += gridDim.x * blockDim.x) {
        float4 v = src[i];
        uint32_t h0, l0, h1, l1;
        split2(v.x, v.y, h0, l0);
        split2(v.z, v.w, h1, l1);
        hi[i] = make_uint2(h0, h1);
        lo[i] = make_uint2(l0, l1);
    }
}

// ---------------- router stage 1: gate scores (16 tokens/block, gate_w reuse) ----
#define RTOK 16
__global__ __launch_bounds__(256) void score_kernel(const float* __restrict__ x,
                                                    const float* __restrict__ gate_w) {
    extern __shared__ float xs[];          // 16 * 1024 floats
    int tid = threadIdx.x, lane = tid & 31, w = tid >> 5;
    int tb = blockIdx.x * RTOK;

    const float4* xg = (const float4*)(x + (size_t)tb * H_);
    float4* xs4 = (float4*)xs;
    #pragma unroll
    for (int i = 0; i < RTOK; i++) xs4[tid + i * 256] = xg[tid + i * 256];
    __syncthreads();

    #pragma unroll
    for (int j = 0; j < 4; j++) {
        int e = w * 4 + j;
        const float4* g4 = (const float4*)(gate_w + (size_t)e * H_);
        float acc[RTOK];
        #pragma unroll
        for (int t = 0; t < RTOK; t++) acc[t] = 0.f;
        #pragma unroll
        for (int it = 0; it < 8; it++) {
            float4 gv = g4[it * 32 + lane];
            #pragma unroll
            for (int t = 0; t < RTOK; t++) {
                float4 xv = *(const float4*)&xs[t * H_ + (it * 32 + lane) * 4];
                acc[t] += gv.x * xv.x + gv.y * xv.y + gv.z * xv.z + gv.w * xv.w;
            }
        }
        #pragma unroll
        for (int t = 0; t < RTOK; t++) {
            float v = acc[t];
            #pragma unroll
            for (int o = 16; o; o >>= 1) v += __shfl_xor_sync(0xffffffffu, v, o);
            if (lane == 0) g_sc[(size_t)(tb + t) * E_ + e] = v;
        }
    }
}

// ---------------- router stage 2: top-k, one thread per token, register-only ----
// Bitmask selection: no data-dependent array indexing -> no local-mem spills.
__global__ __launch_bounds__(256) void route_kernel(const float* __restrict__ bias) {
    int t = blockIdx.x * blockDim.x + threadIdx.x;
    if (t >= T_) return;

    float s[E_], sfc[E_];
    #pragma unroll
    for (int e = 0; e < E_; e++) {
        float v = g_sc[(size_t)t * E_ + e];
        s[e]   = 1.f / (1.f + expf(-v));
        sfc[e] = s[e] + bias[e];
    }
    // group scores = sum of top-2 within group of 4
    float gs[NGROUP];
    #pragma unroll
    for (int g = 0; g < NGROUP; g++) {
        float m1 = -1e30f, m2 = -1e30f;
        #pragma unroll
        for (int j = 0; j < 4; j++) {
            float v = sfc[g * 4 + j];
            if (v > m1) { m2 = m1; m1 = v; }
            else if (v > m2) m2 = v;
        }
        gs[g] = m1 + m2;
    }
    // top-4 groups via bitmask (strict > => lower index wins ties)
    uint32_t gmask = 0;
    #pragma unroll
    for (int it = 0; it < TOPKG; it++) {
        float best = -1e30f; int bi = 0;
        #pragma unroll
        for (int g = 0; g < NGROUP; g++) {
            bool c = !((gmask >> g) & 1u) && gs[g] > best;
            if (c) { best = gs[g]; bi = g; }
        }
        gmask |= 1u << bi;
    }
    // top-4 experts among selected groups via bitmask; capture raw score at select time
    uint32_t emask = 0;
    int   sel[KSEL];
    float rw[KSEL];
    #pragma unroll
    for (int k = 0; k < KSEL; k++) {
        float best = -1e30f, braw = 0.f; int bi = 0;
        #pragma unroll
        for (int e = 0; e < E_; e++) {
            float v = ((gmask >> (e >> 2)) & 1u) ? sfc[e] : 0.f;
            bool c = !((emask >> e) & 1u) && v > best;
            if (c) { best = v; bi = e; braw = s[e]; }
        }
        emask |= 1u << bi;
        sel[k] = bi;
        rw[k]  = braw;
    }
    float rsum = rw[0] + rw[1] + rw[2] + rw[3];
    float inv = 1.f / rsum;
    #pragma unroll
    for (int k = 0; k < KSEL; k++) {
        int a = t * KSEL + k;
        g_expi[a] = sel[k];
        g_gw[a]   = rw[k] * inv;
    }
}

// ---------------- deterministic slot assignment (stable token order) ----------------
__global__ __launch_bounds__(1024) void slot_kernel() {
    int e = blockIdx.x, tid = threadIdx.x;
    int lane = tid & 31, warp = tid >> 5;
    __shared__ int warp_sums[32];
    int base = 0;
    for (int c0 = 0; c0 < NASSIGN; c0 += 1024) {
        int a = c0 + tid;
        bool flag = (g_expi[a] == e);
        unsigned bal = __ballot_sync(0xffffffffu, flag);
        int wprefix = __popc(bal & ((1u << lane) - 1u));
        if (lane == 31) warp_sums[warp] = __popc(bal);
        __syncthreads();
        if (warp == 0) {
            int v = warp_sums[lane];
            #pragma unroll
            for (int o = 1; o < 32; o <<= 1) {
                int n = __shfl_up_sync(0xffffffffu, v, o);
                if (lane >= o) v += n;
            }
            warp_sums[lane] = v;
        }
        __syncthreads();
        int woff  = (warp == 0) ? 0 : warp_sums[warp - 1];
        int total = warp_sums[31];
        if (flag) {
            int slot = base + woff + wprefix;
            if (slot < CAP) {
                g_slot[a] = slot;
                g_tok[e * CAP + slot] = a >> 2;
            } else {
                g_slot[a] = -1;
            }
        }
        base += total;
        __syncthreads();
    }
    if (tid == 0) g_cnt[e] = base < CAP ? base : CAP;
}

// gather: token rows -> per-expert bf16 hi/lo planes
__global__ void gather_kernel(const float* __restrict__ x) {
    int e = blockIdx.y, slot = blockIdx.x;
    if (slot >= g_cnt[e]) return;
    int t = g_tok[e * CAP + slot];
    const float4* src = (const float4*)(x + (size_t)t * H_);
    uint2* dh = (uint2*)(g_bufh + ((size_t)e * CAP + slot) * H_);
    uint2* dl = (uint2*)(g_bufl + ((size_t)e * CAP + slot) * H_);
    for (int i = threadIdx.x; i < H_ / 4; i += blockDim.x) {
        float4 v = src[i];
        uint32_t h0, l0, h1, l1;
        split2(v.x, v.y, h0, l0);
        split2(v.z, v.w, h1, l1);
        dh[i] = make_uint2(h0, h1);
        dl[i] = make_uint2(l0, l1);
    }
}

// ---------------- GEMM common ----------------
#define SROW   80            // smem bytes per 32-bf16 K-chunk row (padded)
#define PS     (128 * SROW)  // plane size = 10240 B

// ---------------- GEMM1: fused h1/h3 + SiLU, 3-pass bf16 mma + ldmatrix ----------------
#define G1_PLANES 6
#define G1_STAGE  (G1_PLANES * PS)
#define G1_SMEM   (3 * G1_STAGE)

__global__ __launch_bounds__(256) void gemm1_mma(void) {
    int e   = blockIdx.z;
    int cnt = g_cnt[e];
    int m0  = blockIdx.y * 128;
    if (m0 >= cnt) return;
    int n0  = blockIdx.x * 128;

    extern __shared__ char sm[];
    uint32_t sb = smem_u32(sm);
    int tid = threadIdx.x, lane = tid & 31, wid = tid >> 5;
    int wm = (wid & 1) * 64, wn = (wid >> 1) * 32;
    int g = lane >> 2, tg = lane & 3;
    int lane15 = lane & 15;
    uint32_t lhi  = (uint32_t)(lane >> 4) * 16u;
    uint32_t arow = (uint32_t)(wm + lane15) * SROW + lhi;
    uint32_t brow = (uint32_t)(wn + lane15) * SROW + lhi;

    const __nv_bfloat16* srcs[G1_PLANES] = {
        g_bufh + ((size_t)e * CAP  + m0) * H_,
        g_bufl + ((size_t)e * CAP  + m0) * H_,
        g_w1h  + ((size_t)e * IDIM + n0) * H_,
        g_w1l  + ((size_t)e * IDIM + n0) * H_,
        g_w3h  + ((size_t)e * IDIM + n0) * H_,
        g_w3l  + ((size_t)e * IDIM + n0) * H_
    };
    int lrow = tid >> 1;
    int lcb  = (tid & 1) * 2;
    uint32_t ldst = lrow * SROW + lcb * 16;

    #pragma unroll
    for (int st = 0; st < 2; st++) {
        uint32_t s = sb + st * G1_STAGE + ldst;
        int k0 = st * 32 + lcb * 8;
        #pragma unroll
        for (int p = 0; p < G1_PLANES; p++) {
            const __nv_bfloat16* gp = srcs[p] + (size_t)lrow * H_ + k0;
            cp16(s + p * PS,      gp);
            cp16(s + p * PS + 16, gp + 8);
        }
        cp_commit();
    }

    float c1[4][4][4] = {}, c3[4][4][4] = {};

    const int NK = H_ / 32;
    for (int kt = 0; kt < NK; kt++) {
        cp_wait1();
        __syncthreads();
        if (kt + 2 < NK) {
            uint32_t s = sb + ((kt + 2) % 3) * G1_STAGE + ldst;
            int k0 = (kt + 2) * 32 + lcb * 8;
            #pragma unroll
            for (int p = 0; p < G1_PLANES; p++) {
                const __nv_bfloat16* gp = srcs[p] + (size_t)lrow * H_ + k0;
                cp16(s + p * PS,      gp);
                cp16(s + p * PS + 16, gp + 8);
            }
        }
        cp_commit();

        uint32_t bs = sb + (kt % 3) * G1_STAGE;
        #pragma unroll
        for (int kb = 0; kb < 2; kb++) {
            uint32_t ko = kb * 32;
            #pragma unroll
            for (int p = 0; p < 3; p++) {
                uint32_t ap = (p == 1) ? PS : 0;
                uint32_t bp = (p == 2) ? PS : 0;
                uint32_t A_[4][4];
                #pragma unroll
                for (int mi = 0; mi < 4; mi++)
                    LDSM4(A_[mi], bs + ap + arow + mi * (16 * SROW) + ko);
                uint32_t B1f[4][2], B3f[4][2];
                #pragma unroll
                for (int n2 = 0; n2 < 2; n2++) {
                    uint32_t t_[4];
                    LDSM4(t_, bs + 2 * PS + bp + brow + n2 * (16 * SROW) + ko);
                    B1f[2 * n2][0] = t_[0]; B1f[2 * n2][1] = t_[2];
                    B1f[2 * n2 + 1][0] = t_[1]; B1f[2 * n2 + 1][1] = t_[3];
                    LDSM4(t_, bs + 4 * PS + bp + brow + n2 * (16 * SROW) + ko);
                    B3f[2 * n2][0] = t_[0]; B3f[2 * n2][1] = t_[2];
                    B3f[2 * n2 + 1][0] = t_[1]; B3f[2 * n2 + 1][1] = t_[3];
                }
                #pragma unroll
                for (int mi = 0; mi < 4; mi++)
                    #pragma unroll
                    for (int ni = 0; ni < 4; ni++) {
                        mma16816(c1[mi][ni], A_[mi], B1f[ni][0], B1f[ni][1]);
                        mma16816(c3[mi][ni], A_[mi], B3f[ni][0], B3f[ni][1]);
                    }
            }
        }
    }

    // epilogue: act = silu(h1)*h3 -> bf16 hi/lo
    #pragma unroll
    for (int mi = 0; mi < 4; mi++) {
        int r0 = m0 + wm + mi * 16 + g;
        #pragma unroll
        for (int ni = 0; ni < 4; ni++) {
            int cb = n0 + wn + ni * 8 + tg * 2;
            float h1a = c1[mi][ni][0], h1b = c1[mi][ni][1];
            float v0 = h1a / (1.f + expf(-h1a)) * c3[mi][ni][0];
            float v1 = h1b / (1.f + expf(-h1b)) * c3[mi][ni][1];
            float h1c = c1[mi][ni][2], h1d = c1[mi][ni][3];
            float v2 = h1c / (1.f + expf(-h1c)) * c3[mi][ni][2];
            float v3 = h1d / (1.f + expf(-h1d)) * c3[mi][ni][3];
            uint32_t h, l;
            size_t o0 = ((size_t)e * CAP + r0) * IDIM + cb;
            split2(v0, v1, h, l);
            *(uint32_t*)(g_acth + o0) = h;
            *(uint32_t*)(g_actl + o0) = l;
            size_t o1 = ((size_t)e * CAP + r0 + 8) * IDIM + cb;
            split2(v2, v3, h, l);
            *(uint32_t*)(g_acth + o1) = h;
            *(uint32_t*)(g_actl + o1) = l;
        }
    }
}

// ---------------- GEMM2: y = act @ w2^T ----------------
#define G2_PLANES 4
#define G2_STAGE  (G2_PLANES * PS)
#define G2_SMEM   (3 * G2_STAGE)

__global__ __launch_bounds__(256) void gemm2_mma(void) {
    int e   = blockIdx.z;
    int cnt = g_cnt[e];
    int m0  = blockIdx.y * 128;
    if (m0 >= cnt) return;
    int n0  = blockIdx.x * 128;

    extern __shared__ char sm[];
    uint32_t sb = smem_u32(sm);
    int tid = threadIdx.x, lane = tid & 31, wid = tid >> 5;
    int wm = (wid & 1) * 64, wn = (wid >> 1) * 32;
    int g = lane >> 2, tg = lane & 3;
    int lane15 = lane & 15;
    uint32_t lhi  = (uint32_t)(lane >> 4) * 16u;
    uint32_t arow = (uint32_t)(wm + lane15) * SROW + lhi;
    uint32_t brow = (uint32_t)(wn + lane15) * SROW + lhi;

    const __nv_bfloat16* srcs[G2_PLANES] = {
        g_acth + ((size_t)e * CAP + m0) * IDIM,
        g_actl + ((size_t)e * CAP + m0) * IDIM,
        g_w2h  + ((size_t)e * H_  + n0) * IDIM,
        g_w2l  + ((size_t)e * H_  + n0) * IDIM
    };
    int lrow = tid >> 1;
    int lcb  = (tid & 1) * 2;
    uint32_t ldst = lrow * SROW + lcb * 16;

    #pragma unroll
    for (int st = 0; st < 2; st++) {
        uint32_t s = sb + st * G2_STAGE + ldst;
        int k0 = st * 32 + lcb * 8;
        #pragma unroll
        for (int p = 0; p < G2_PLANES; p++) {
            const __nv_bfloat16* gp = srcs[p] + (size_t)lrow * IDIM + k0;
            cp16(s + p * PS,      gp);
            cp16(s + p * PS + 16, gp + 8);
        }
        cp_commit();
    }

    float cc[4][4][4] = {};

    const int NK = IDIM / 32;
    for (int kt = 0; kt < NK; kt++) {
        cp_wait1();
        __syncthreads();
        if (kt + 2 < NK) {
            uint32_t s = sb + ((kt + 2) % 3) * G2_STAGE + ldst;
            int k0 = (kt + 2) * 32 + lcb * 8;
            #pragma unroll
            for (int p = 0; p < G2_PLANES; p++) {
                const __nv_bfloat16* gp = srcs[p] + (size_t)lrow * IDIM + k0;
                cp16(s + p * PS,      gp);
                cp16(s + p * PS + 16, gp + 8);
            }
        }
        cp_commit();

        uint32_t bs = sb + (kt % 3) * G2_STAGE;
        #pragma unroll
        for (int kb = 0; kb < 2; kb++) {
            uint32_t ko = kb * 32;
            #pragma unroll
            for (int p = 0; p < 3; p++) {
                uint32_t ap = (p == 1) ? PS : 0;
                uint32_t bp = (p == 2) ? PS : 0;
                uint32_t A_[4][4];
                #pragma unroll
                for (int mi = 0; mi < 4; mi++)
                    LDSM4(A_[mi], bs + ap + arow + mi * (16 * SROW) + ko);
                uint32_t Bf[4][2];
                #pragma unroll
                for (int n2 = 0; n2 < 2; n2++) {
                    uint32_t t_[4];
                    LDSM4(t_, bs + 2 * PS + bp + brow + n2 * (16 * SROW) + ko);
                    Bf[2 * n2][0] = t_[0]; Bf[2 * n2][1] = t_[2];
                    Bf[2 * n2 + 1][0] = t_[1]; Bf[2 * n2 + 1][1] = t_[3];
                }
                #pragma unroll
                for (int mi = 0; mi < 4; mi++)
                    #pragma unroll
                    for (int ni = 0; ni < 4; ni++)
                        mma16816(cc[mi][ni], A_[mi], Bf[ni][0], Bf[ni][1]);
            }
        }
    }

    #pragma unroll
    for (int mi = 0; mi < 4; mi++) {
        int r0 = m0 + wm + mi * 16 + g;
        #pragma unroll
        for (int ni = 0; ni < 4; ni++) {
            int cb = n0 + wn + ni * 8 + tg * 2;
            *(float2*)(g_y + ((size_t)e * CAP + r0) * H_ + cb) =
                make_float2(cc[mi][ni][0], cc[mi][ni][1]);
            *(float2*)(g_y + ((size_t)e * CAP + r0 + 8) * H_ + cb) =
                make_float2(cc[mi][ni][2], cc[mi][ni][3]);
        }
    }
}

// ---------------- combine: out[t] = sum_k w * y[e,slot] (deterministic) ----------------
__global__ void combine_kernel(float* __restrict__ out) {
    int t = blockIdx.x;
    int i = threadIdx.x;
    float4 acc = make_float4(0.f, 0.f, 0.f, 0.f);
    #pragma unroll
    for (int k = 0; k < KSEL; k++) {
        int a = t * KSEL + k;
        int slot = g_slot[a];
        if (slot < 0) continue;
        int e = g_expi[a];
        float w = g_gw[a];
        const float4* yr = (const float4*)(g_y + ((size_t)e * CAP + slot) * H_);
        float4 v = yr[i];
        acc.x += w * v.x; acc.y += w * v.y; acc.z += w * v.z; acc.w += w * v.w;
    }
    ((float4*)(out + (size_t)t * H_))[i] = acc;
}

// ---------------- launch ----------------
extern "C" void kernel_launch(void* const* d_in, const int* in_sizes, int n_in,
                              void* d_out, int out_size) {
    (void)in_sizes; (void)n_in; (void)out_size;
    const float* x      = (const float*)d_in[0];
    const float* gate_w = (const float*)d_in[1];
    const float* w1     = (const float*)d_in[2];
    const float* w3     = (const float*)d_in[3];
    const float* w2     = (const float*)d_in[4];
    const float* bias   = (const float*)d_in[5];
    float*       out    = (float*)d_out;

    const int RSMEM = RTOK * H_ * 4;
    cudaFuncSetAttribute(score_kernel, cudaFuncAttributeMaxDynamicSharedMemorySize, RSMEM);
    cudaFuncSetAttribute(gemm1_mma, cudaFuncAttributeMaxDynamicSharedMemorySize, G1_SMEM);
    cudaFuncSetAttribute(gemm2_mma, cudaFuncAttributeMaxDynamicSharedMemorySize, G2_SMEM);

    void *p_w1h, *p_w1l, *p_w3h, *p_w3l, *p_w2h, *p_w2l;
    cudaGetSymbolAddress(&p_w1h, g_w1h);
    cudaGetSymbolAddress(&p_w1l, g_w1l);
    cudaGetSymbolAddress(&p_w3h, g_w3h);
    cudaGetSymbolAddress(&p_w3l, g_w3l);
    cudaGetSymbolAddress(&p_w2h, g_w2h);
    cudaGetSymbolAddress(&p_w2l, g_w2l);

    const int n4 = E_ * IDIM * H_ / 4;
    cvt_kernel<<<4096, 256>>>((const float4*)w1, (uint2*)p_w1h, (uint2*)p_w1l, n4);
    cvt_kernel<<<4096, 256>>>((const float4*)w3, (uint2*)p_w3h, (uint2*)p_w3l, n4);
    cvt_kernel<<<4096, 256>>>((const float4*)w2, (uint2*)p_w2h, (uint2*)p_w2l, n4);

    score_kernel<<<T_ / RTOK, 256, RSMEM>>>(x, gate_w);
    route_kernel<<<T_ / 256, 256>>>(bias);
    slot_kernel<<<E_, 1024>>>();
    gather_kernel<<<dim3(CAP, E_), 256>>>(x);
    gemm1_mma<<<dim3(IDIM / 128, CAP / 128, E_), 256, G1_SMEM>>>();
    gemm2_mma<<<dim3(H_ / 128, CAP / 128, E_), 256, G2_SMEM>>>();
    combine_kernel<<<T_, 256>>>(out);
}

// round 8
// speedup vs baseline: 1.2558x; 1.0912x over previous
#include <cuda_runtime.h>
#include <cuda_bf16.h>
#include <math.h>
#include <stdint.h>

#define E_      32
#define KSEL    4
#define H_      1024
#define IDIM    768
#define T_      4096
#define NGROUP  8
#define TOPKG   4
#define CAP     1024
#define NASSIGN (T_ * KSEL)

// ---------------- scratch (device globals; no allocations) ----------------
__device__ __nv_bfloat16 g_bufh[(size_t)E_ * CAP * H_];
__device__ __nv_bfloat16 g_bufl[(size_t)E_ * CAP * H_];
__device__ __nv_bfloat16 g_acth[(size_t)E_ * CAP * IDIM];
__device__ __nv_bfloat16 g_actl[(size_t)E_ * CAP * IDIM];
__device__ __nv_bfloat16 g_w1h[(size_t)E_ * IDIM * H_];
__device__ __nv_bfloat16 g_w1l[(size_t)E_ * IDIM * H_];
__device__ __nv_bfloat16 g_w3h[(size_t)E_ * IDIM * H_];
__device__ __nv_bfloat16 g_w3l[(size_t)E_ * IDIM * H_];
__device__ __nv_bfloat16 g_w2h[(size_t)E_ * H_ * IDIM];
__device__ __nv_bfloat16 g_w2l[(size_t)E_ * H_ * IDIM];
__device__ float g_y[(size_t)E_ * CAP * H_];
__device__ float g_sc[(size_t)T_ * E_];
__device__ int   g_cnt [E_];
__device__ int   g_tok [E_ * CAP];
__device__ int   g_expi[NASSIGN];
__device__ int   g_slot[NASSIGN];
__device__ float g_gw  [NASSIGN];

// ---------------- helpers ----------------
__device__ __forceinline__ uint32_t smem_u32(const void* p) {
    uint32_t a;
    asm("{ .reg .u64 t; cvta.to.shared.u64 t, %1; cvt.u32.u64 %0, t; }" : "=r"(a) : "l"(p));
    return a;
}
__device__ __forceinline__ void cp16(uint32_t dst, const void* src) {
    asm volatile("cp.async.cg.shared.global [%0], [%1], 16;" :: "r"(dst), "l"(src));
}
__device__ __forceinline__ void cp_commit() { asm volatile("cp.async.commit_group;"); }
__device__ __forceinline__ void cp_wait2()  { asm volatile("cp.async.wait_group 2;"); }
#define LDSM4(r, a) \
    asm volatile("ldmatrix.sync.aligned.m8n8.x4.shared.b16 {%0,%1,%2,%3}, [%4];" \
        : "=r"((r)[0]), "=r"((r)[1]), "=r"((r)[2]), "=r"((r)[3]) : "r"(a))
__device__ __forceinline__ void mma16816(float* c, const uint32_t* a, uint32_t b0, uint32_t b1) {
    asm volatile(
        "mma.sync.aligned.m16n8k16.row.col.f32.bf16.bf16.f32 "
        "{%0,%1,%2,%3}, {%4,%5,%6,%7}, {%8,%9}, {%0,%1,%2,%3};"
        : "+f"(c[0]), "+f"(c[1]), "+f"(c[2]), "+f"(c[3])
        : "r"(a[0]), "r"(a[1]), "r"(a[2]), "r"(a[3]), "r"(b0), "r"(b1));
}
__device__ __forceinline__ void split2(float x, float y, uint32_t& h, uint32_t& l) {
    __nv_bfloat16 hx = __float2bfloat16(x), hy = __float2bfloat16(y);
    float rx = x - __bfloat162float(hx), ry = y - __bfloat162float(hy);
    __nv_bfloat16 lx = __float2bfloat16(rx), ly = __float2bfloat16(ry);
    h = (uint32_t)__bfloat16_as_ushort(hx) | ((uint32_t)__bfloat16_as_ushort(hy) << 16);
    l = (uint32_t)__bfloat16_as_ushort(lx) | ((uint32_t)__bfloat16_as_ushort(ly) << 16);
}
// XOR-swizzled smem address: 128 rows x 64B; chunk = 16B unit index within row.
// chunk' = chunk ^ ((row>>1)&3): applied identically on store & load -> self-consistent.
__device__ __forceinline__ uint32_t swz(uint32_t base, int row, int chunk) {
    return base + (uint32_t)row * 64u + ((uint32_t)(chunk ^ ((row >> 1) & 3)) << 4);
}

// ---------------- weight conversion ----------------
__global__ void cvt_kernel(const float4* __restrict__ src, uint2* __restrict__ hi,
                           uint2* __restrict__ lo, int n4) {
    for (int i = blockIdx.x * blockDim.x + threadIdx.x; i < n4; i += gridDim.x * blockDim.x) {
        float4 v = src[i];
        uint32_t h0, l0, h1, l1;
        split2(v.x, v.y, h0, l0);
        split2(v.z, v.w, h1, l1);
        hi[i] = make_uint2(h0, h1);
        lo[i] = make_uint2(l0, l1);
    }
}

// ---------------- router stage 1: gate scores (8 tokens/block) ----------------
#define RTOK 8
#define RSTAGE_ITERS (RTOK * (H_ / 4) / 256)   // = 8 float4 copy iterations (FIXED)
__global__ __launch_bounds__(256) void score_kernel(const float* __restrict__ x,
                                                    const float* __restrict__ gate_w) {
    extern __shared__ float xs[];          // 8 * 1024 floats
    int tid = threadIdx.x, lane = tid & 31, w = tid >> 5;
    int tb = blockIdx.x * RTOK;

    const float4* xg = (const float4*)(x + (size_t)tb * H_);
    float4* xs4 = (float4*)xs;
    #pragma unroll
    for (int i = 0; i < RSTAGE_ITERS; i++) xs4[tid + i * 256] = xg[tid + i * 256];
    __syncthreads();

    #pragma unroll
    for (int j = 0; j < 4; j++) {
        int e = w * 4 + j;
        const float4* g4 = (const float4*)(gate_w + (size_t)e * H_);
        float acc[RTOK];
        #pragma unroll
        for (int t = 0; t < RTOK; t++) acc[t] = 0.f;
        #pragma unroll
        for (int it = 0; it < 8; it++) {
            float4 gv = g4[it * 32 + lane];
            #pragma unroll
            for (int t = 0; t < RTOK; t++) {
                float4 xv = *(const float4*)&xs[t * H_ + (it * 32 + lane) * 4];
                acc[t] += gv.x * xv.x + gv.y * xv.y + gv.z * xv.z + gv.w * xv.w;
            }
        }
        #pragma unroll
        for (int t = 0; t < RTOK; t++) {
            float v = acc[t];
            #pragma unroll
            for (int o = 16; o; o >>= 1) v += __shfl_xor_sync(0xffffffffu, v, o);
            if (lane == 0) g_sc[(size_t)(tb + t) * E_ + e] = v;
        }
    }
}

// ---------------- router stage 2: top-k, register-only bitmask selection ----------------
__global__ __launch_bounds__(256) void route_kernel(const float* __restrict__ bias) {
    int t = blockIdx.x * blockDim.x + threadIdx.x;
    if (t >= T_) return;

    float s[E_], sfc[E_];
    #pragma unroll
    for (int e = 0; e < E_; e++) {
        float v = g_sc[(size_t)t * E_ + e];
        s[e]   = 1.f / (1.f + expf(-v));
        sfc[e] = s[e] + bias[e];
    }
    float gs[NGROUP];
    #pragma unroll
    for (int g = 0; g < NGROUP; g++) {
        float m1 = -1e30f, m2 = -1e30f;
        #pragma unroll
        for (int j = 0; j < 4; j++) {
            float v = sfc[g * 4 + j];
            if (v > m1) { m2 = m1; m1 = v; }
            else if (v > m2) m2 = v;
        }
        gs[g] = m1 + m2;
    }
    uint32_t gmask = 0;
    #pragma unroll
    for (int it = 0; it < TOPKG; it++) {
        float best = -1e30f; int bi = 0;
        #pragma unroll
        for (int g = 0; g < NGROUP; g++) {
            bool c = !((gmask >> g) & 1u) && gs[g] > best;
            if (c) { best = gs[g]; bi = g; }
        }
        gmask |= 1u << bi;
    }
    uint32_t emask = 0;
    int   sel[KSEL];
    float rw[KSEL];
    #pragma unroll
    for (int k = 0; k < KSEL; k++) {
        float best = -1e30f, braw = 0.f; int bi = 0;
        #pragma unroll
        for (int e = 0; e < E_; e++) {
            float v = ((gmask >> (e >> 2)) & 1u) ? sfc[e] : 0.f;
            bool c = !((emask >> e) & 1u) && v > best;
            if (c) { best = v; bi = e; braw = s[e]; }
        }
        emask |= 1u << bi;
        sel[k] = bi;
        rw[k]  = braw;
    }
    float inv = 1.f / (rw[0] + rw[1] + rw[2] + rw[3]);
    #pragma unroll
    for (int k = 0; k < KSEL; k++) {
        int a = t * KSEL + k;
        g_expi[a] = sel[k];
        g_gw[a]   = rw[k] * inv;
    }
}

// ---------------- deterministic slot assignment ----------------
__global__ __launch_bounds__(1024) void slot_kernel() {
    int e = blockIdx.x, tid = threadIdx.x;
    int lane = tid & 31, warp = tid >> 5;
    __shared__ int warp_sums[32];
    int base = 0;
    for (int c0 = 0; c0 < NASSIGN; c0 += 1024) {
        int a = c0 + tid;
        bool flag = (g_expi[a] == e);
        unsigned bal = __ballot_sync(0xffffffffu, flag);
        int wprefix = __popc(bal & ((1u << lane) - 1u));
        if (lane == 31) warp_sums[warp] = __popc(bal);
        __syncthreads();
        if (warp == 0) {
            int v = warp_sums[lane];
            #pragma unroll
            for (int o = 1; o < 32; o <<= 1) {
                int n = __shfl_up_sync(0xffffffffu, v, o);
                if (lane >= o) v += n;
            }
            warp_sums[lane] = v;
        }
        __syncthreads();
        int woff  = (warp == 0) ? 0 : warp_sums[warp - 1];
        int total = warp_sums[31];
        if (flag) {
            int slot = base + woff + wprefix;
            if (slot < CAP) {
                g_slot[a] = slot;
                g_tok[e * CAP + slot] = a >> 2;
            } else {
                g_slot[a] = -1;
            }
        }
        base += total;
        __syncthreads();
    }
    if (tid == 0) g_cnt[e] = base < CAP ? base : CAP;
}

// gather: token rows -> per-expert bf16 hi/lo planes
__global__ void gather_kernel(const float* __restrict__ x) {
    int e = blockIdx.y, slot = blockIdx.x;
    if (slot >= g_cnt[e]) return;
    int t = g_tok[e * CAP + slot];
    const float4* src = (const float4*)(x + (size_t)t * H_);
    uint2* dh = (uint2*)(g_bufh + ((size_t)e * CAP + slot) * H_);
    uint2* dl = (uint2*)(g_bufl + ((size_t)e * CAP + slot) * H_);
    for (int i = threadIdx.x; i < H_ / 4; i += blockDim.x) {
        float4 v = src[i];
        uint32_t h0, l0, h1, l1;
        split2(v.x, v.y, h0, l0);
        split2(v.z, v.w, h1, l1);
        dh[i] = make_uint2(h0, h1);
        dl[i] = make_uint2(l0, l1);
    }
}

// ---------------- GEMM common ----------------
#define PS      8192          // plane: 128 rows x 64B (32 bf16), XOR-swizzled
#define NSTG    4

// ---------------- GEMM1: fused h1/h3 + SiLU ----------------
#define G1_PLANES 6
#define G1_STAGE  (G1_PLANES * PS)   // 49152
#define G1_SMEM   (NSTG * G1_STAGE)  // 196608

__global__ __launch_bounds__(256) void gemm1_mma(void) {
    int e   = blockIdx.z;
    int cnt = g_cnt[e];
    int m0  = blockIdx.y * 128;
    if (m0 >= cnt) return;
    int n0  = blockIdx.x * 128;

    extern __shared__ char sm[];
    uint32_t sb = smem_u32(sm);
    int tid = threadIdx.x, lane = tid & 31, wid = tid >> 5;
    int wm = (wid & 1) * 64, wn = (wid >> 1) * 32;
    int g = lane >> 2, tg = lane & 3;
    int lane15 = lane & 15;
    int lchunk = lane >> 4;

    const __nv_bfloat16* srcs[G1_PLANES] = {
        g_bufh + ((size_t)e * CAP  + m0) * H_,
        g_bufl + ((size_t)e * CAP  + m0) * H_,
        g_w1h  + ((size_t)e * IDIM + n0) * H_,
        g_w1l  + ((size_t)e * IDIM + n0) * H_,
        g_w3h  + ((size_t)e * IDIM + n0) * H_,
        g_w3l  + ((size_t)e * IDIM + n0) * H_
    };
    int lrow = tid >> 1;
    int lc0  = (tid & 1) * 2;

    #pragma unroll
    for (int st = 0; st < NSTG - 1; st++) {
        uint32_t s0 = sb + st * G1_STAGE;
        int k0 = st * 32 + lc0 * 8;
        #pragma unroll
        for (int p = 0; p < G1_PLANES; p++) {
            const __nv_bfloat16* gp = srcs[p] + (size_t)lrow * H_ + k0;
            cp16(swz(s0 + p * PS, lrow, lc0),     gp);
            cp16(swz(s0 + p * PS, lrow, lc0 + 1), gp + 8);
        }
        cp_commit();
    }

    float c1[4][4][4] = {}, c3[4][4][4] = {};

    const int NK = H_ / 32;
    for (int kt = 0; kt < NK; kt++) {
        cp_wait2();
        __syncthreads();
        if (kt + NSTG - 1 < NK) {
            uint32_t s0 = sb + ((kt + NSTG - 1) % NSTG) * G1_STAGE;
            int k0 = (kt + NSTG - 1) * 32 + lc0 * 8;
            #pragma unroll
            for (int p = 0; p < G1_PLANES; p++) {
                const __nv_bfloat16* gp = srcs[p] + (size_t)lrow * H_ + k0;
                cp16(swz(s0 + p * PS, lrow, lc0),     gp);
                cp16(swz(s0 + p * PS, lrow, lc0 + 1), gp + 8);
            }
        }
        cp_commit();

        uint32_t bs = sb + (kt % NSTG) * G1_STAGE;
        #pragma unroll
        for (int kb = 0; kb < 2; kb++) {
            int ch = kb * 2 + lchunk;
            uint32_t Ah[4][4], Al[4][4];
            #pragma unroll
            for (int mi = 0; mi < 4; mi++) {
                int r = wm + lane15 + mi * 16;
                LDSM4(Ah[mi], swz(bs,      r, ch));
                LDSM4(Al[mi], swz(bs + PS, r, ch));
            }
            uint32_t t_[4], Bf[4][2];
            #pragma unroll
            for (int n2 = 0; n2 < 2; n2++) {
                LDSM4(t_, swz(bs + 2 * PS, wn + lane15 + n2 * 16, ch));
                Bf[2 * n2][0] = t_[0]; Bf[2 * n2][1] = t_[2];
                Bf[2 * n2 + 1][0] = t_[1]; Bf[2 * n2 + 1][1] = t_[3];
            }
            #pragma unroll
            for (int mi = 0; mi < 4; mi++)
                #pragma unroll
                for (int ni = 0; ni < 4; ni++) {
                    mma16816(c1[mi][ni], Ah[mi], Bf[ni][0], Bf[ni][1]);
                    mma16816(c1[mi][ni], Al[mi], Bf[ni][0], Bf[ni][1]);
                }
            #pragma unroll
            for (int n2 = 0; n2 < 2; n2++) {
                LDSM4(t_, swz(bs + 3 * PS, wn + lane15 + n2 * 16, ch));
                Bf[2 * n2][0] = t_[0]; Bf[2 * n2][1] = t_[2];
                Bf[2 * n2 + 1][0] = t_[1]; Bf[2 * n2 + 1][1] = t_[3];
            }
            #pragma unroll
            for (int mi = 0; mi < 4; mi++)
                #pragma unroll
                for (int ni = 0; ni < 4; ni++)
                    mma16816(c1[mi][ni], Ah[mi], Bf[ni][0], Bf[ni][1]);
            #pragma unroll
            for (int n2 = 0; n2 < 2; n2++) {
                LDSM4(t_, swz(bs + 4 * PS, wn + lane15 + n2 * 16, ch));
                Bf[2 * n2][0] = t_[0]; Bf[2 * n2][1] = t_[2];
                Bf[2 * n2 + 1][0] = t_[1]; Bf[2 * n2 + 1][1] = t_[3];
            }
            #pragma unroll
            for (int mi = 0; mi < 4; mi++)
                #pragma unroll
                for (int ni = 0; ni < 4; ni++) {
                    mma16816(c3[mi][ni], Ah[mi], Bf[ni][0], Bf[ni][1]);
                    mma16816(c3[mi][ni], Al[mi], Bf[ni][0], Bf[ni][1]);
                }
            #pragma unroll
            for (int n2 = 0; n2 < 2; n2++) {
                LDSM4(t_, swz(bs + 5 * PS, wn + lane15 + n2 * 16, ch));
                Bf[2 * n2][0] = t_[0]; Bf[2 * n2][1] = t_[2];
                Bf[2 * n2 + 1][0] = t_[1]; Bf[2 * n2 + 1][1] = t_[3];
            }
            #pragma unroll
            for (int mi = 0; mi < 4; mi++)
                #pragma unroll
                for (int ni = 0; ni < 4; ni++)
                    mma16816(c3[mi][ni], Ah[mi], Bf[ni][0], Bf[ni][1]);
        }
    }

    #pragma unroll
    for (int mi = 0; mi < 4; mi++) {
        int r0 = m0 + wm + mi * 16 + g;
        #pragma unroll
        for (int ni = 0; ni < 4; ni++) {
            int cb = n0 + wn + ni * 8 + tg * 2;
            float h1a = c1[mi][ni][0], h1b = c1[mi][ni][1];
            float v0 = h1a / (1.f + expf(-h1a)) * c3[mi][ni][0];
            float v1 = h1b / (1.f + expf(-h1b)) * c3[mi][ni][1];
            float h1c = c1[mi][ni][2], h1d = c1[mi][ni][3];
            float v2 = h1c / (1.f + expf(-h1c)) * c3[mi][ni][2];
            float v3 = h1d / (1.f + expf(-h1d)) * c3[mi][ni][3];
            uint32_t h, l;
            size_t o0 = ((size_t)e * CAP + r0) * IDIM + cb;
            split2(v0, v1, h, l);
            *(uint32_t*)(g_acth + o0) = h;
            *(uint32_t*)(g_actl + o0) = l;
            size_t o1 = ((size_t)e * CAP + r0 + 8) * IDIM + cb;
            split2(v2, v3, h, l);
            *(uint32_t*)(g_acth + o1) = h;
            *(uint32_t*)(g_actl + o1) = l;
        }
    }
}

// ---------------- GEMM2: y = act @ w2^T ----------------
#define G2_PLANES 4
#define G2_STAGE  (G2_PLANES * PS)
#define G2_SMEM   (NSTG * G2_STAGE)

__global__ __launch_bounds__(256) void gemm2_mma(void) {
    int e   = blockIdx.z;
    int cnt = g_cnt[e];
    int m0  = blockIdx.y * 128;
    if (m0 >= cnt) return;
    int n0  = blockIdx.x * 128;

    extern __shared__ char sm[];
    uint32_t sb = smem_u32(sm);
    int tid = threadIdx.x, lane = tid & 31, wid = tid >> 5;
    int wm = (wid & 1) * 64, wn = (wid >> 1) * 32;
    int g = lane >> 2, tg = lane & 3;
    int lane15 = lane & 15;
    int lchunk = lane >> 4;

    const __nv_bfloat16* srcs[G2_PLANES] = {
        g_acth + ((size_t)e * CAP + m0) * IDIM,
        g_actl + ((size_t)e * CAP + m0) * IDIM,
        g_w2h  + ((size_t)e * H_  + n0) * IDIM,
        g_w2l  + ((size_t)e * H_  + n0) * IDIM
    };
    int lrow = tid >> 1;
    int lc0  = (tid & 1) * 2;

    #pragma unroll
    for (int st = 0; st < NSTG - 1; st++) {
        uint32_t s0 = sb + st * G2_STAGE;
        int k0 = st * 32 + lc0 * 8;
        #pragma unroll
        for (int p = 0; p < G2_PLANES; p++) {
            const __nv_bfloat16* gp = srcs[p] + (size_t)lrow * IDIM + k0;
            cp16(swz(s0 + p * PS, lrow, lc0),     gp);
            cp16(swz(s0 + p * PS, lrow, lc0 + 1), gp + 8);
        }
        cp_commit();
    }

    float cc[4][4][4] = {};

    const int NK = IDIM / 32;
    for (int kt = 0; kt < NK; kt++) {
        cp_wait2();
        __syncthreads();
        if (kt + NSTG - 1 < NK) {
            uint32_t s0 = sb + ((kt + NSTG - 1) % NSTG) * G2_STAGE;
            int k0 = (kt + NSTG - 1) * 32 + lc0 * 8;
            #pragma unroll
            for (int p = 0; p < G2_PLANES; p++) {
                const __nv_bfloat16* gp = srcs[p] + (size_t)lrow * IDIM + k0;
                cp16(swz(s0 + p * PS, lrow, lc0),     gp);
                cp16(swz(s0 + p * PS, lrow, lc0 + 1), gp + 8);
            }
        }
        cp_commit();

        uint32_t bs = sb + (kt % NSTG) * G2_STAGE;
        #pragma unroll
        for (int kb = 0; kb < 2; kb++) {
            int ch = kb * 2 + lchunk;
            uint32_t Ah[4][4], Al[4][4];
            #pragma unroll
            for (int mi = 0; mi < 4; mi++) {
                int r = wm + lane15 + mi * 16;
                LDSM4(Ah[mi], swz(bs,      r, ch));
                LDSM4(Al[mi], swz(bs + PS, r, ch));
            }
            uint32_t t_[4], Bf[4][2];
            #pragma unroll
            for (int n2 = 0; n2 < 2; n2++) {
                LDSM4(t_, swz(bs + 2 * PS, wn + lane15 + n2 * 16, ch));
                Bf[2 * n2][0] = t_[0]; Bf[2 * n2][1] = t_[2];
                Bf[2 * n2 + 1][0] = t_[1]; Bf[2 * n2 + 1][1] = t_[3];
            }
            #pragma unroll
            for (int mi = 0; mi < 4; mi++)
                #pragma unroll
                for (int ni = 0; ni < 4; ni++) {
                    mma16816(cc[mi][ni], Ah[mi], Bf[ni][0], Bf[ni][1]);
                    mma16816(cc[mi][ni], Al[mi], Bf[ni][0], Bf[ni][1]);
                }
            #pragma unroll
            for (int n2 = 0; n2 < 2; n2++) {
                LDSM4(t_, swz(bs + 3 * PS, wn + lane15 + n2 * 16, ch));
                Bf[2 * n2][0] = t_[0]; Bf[2 * n2][1] = t_[2];
                Bf[2 * n2 + 1][0] = t_[1]; Bf[2 * n2 + 1][1] = t_[3];
            }
            #pragma unroll
            for (int mi = 0; mi < 4; mi++)
                #pragma unroll
                for (int ni = 0; ni < 4; ni++)
                    mma16816(cc[mi][ni], Ah[mi], Bf[ni][0], Bf[ni][1]);
        }
    }

    #pragma unroll
    for (int mi = 0; mi < 4; mi++) {
        int r0 = m0 + wm + mi * 16 + g;
        #pragma unroll
        for (int ni = 0; ni < 4; ni++) {
            int cb = n0 + wn + ni * 8 + tg * 2;
            *(float2*)(g_y + ((size_t)e * CAP + r0) * H_ + cb) =
                make_float2(cc[mi][ni][0], cc[mi][ni][1]);
            *(float2*)(g_y + ((size_t)e * CAP + r0 + 8) * H_ + cb) =
                make_float2(cc[mi][ni][2], cc[mi][ni][3]);
        }
    }
}

// ---------------- combine ----------------
__global__ void combine_kernel(float* __restrict__ out) {
    int t = blockIdx.x;
    int i = threadIdx.x;
    float4 acc = make_float4(0.f, 0.f, 0.f, 0.f);
    #pragma unroll
    for (int k = 0; k < KSEL; k++) {
        int a = t * KSEL + k;
        int slot = g_slot[a];
        if (slot < 0) continue;
        int e = g_expi[a];
        float w = g_gw[a];
        const float4* yr = (const float4*)(g_y + ((size_t)e * CAP + slot) * H_);
        float4 v = yr[i];
        acc.x += w * v.x; acc.y += w * v.y; acc.z += w * v.z; acc.w += w * v.w;
    }
    ((float4*)(out + (size_t)t * H_))[i] = acc;
}

// ---------------- launch ----------------
extern "C" void kernel_launch(void* const* d_in, const int* in_sizes, int n_in,
                              void* d_out, int out_size) {
    (void)in_sizes; (void)n_in; (void)out_size;
    const float* x      = (const float*)d_in[0];
    const float* gate_w = (const float*)d_in[1];
    const float* w1     = (const float*)d_in[2];
    const float* w3     = (const float*)d_in[3];
    const float* w2     = (const float*)d_in[4];
    const float* bias   = (const float*)d_in[5];
    float*       out    = (float*)d_out;

    const int RSMEM = RTOK * H_ * 4;
    cudaFuncSetAttribute(score_kernel, cudaFuncAttributeMaxDynamicSharedMemorySize, RSMEM);
    cudaFuncSetAttribute(gemm1_mma, cudaFuncAttributeMaxDynamicSharedMemorySize, G1_SMEM);
    cudaFuncSetAttribute(gemm2_mma, cudaFuncAttributeMaxDynamicSharedMemorySize, G2_SMEM);

    void *p_w1h, *p_w1l, *p_w3h, *p_w3l, *p_w2h, *p_w2l;
    cudaGetSymbolAddress(&p_w1h, g_w1h);
    cudaGetSymbolAddress(&p_w1l, g_w1l);
    cudaGetSymbolAddress(&p_w3h, g_w3h);
    cudaGetSymbolAddress(&p_w3l, g_w3l);
    cudaGetSymbolAddress(&p_w2h, g_w2h);
    cudaGetSymbolAddress(&p_w2l, g_w2l);

    const int n4 = E_ * IDIM * H_ / 4;
    cvt_kernel<<<4096, 256>>>((const float4*)w1, (uint2*)p_w1h, (uint2*)p_w1l, n4);
    cvt_kernel<<<4096, 256>>>((const float4*)w3, (uint2*)p_w3h, (uint2*)p_w3l, n4);
    cvt_kernel<<<4096, 256>>>((const float4*)w2, (uint2*)p_w2h, (uint2*)p_w2l, n4);

    score_kernel<<<T_ / RTOK, 256, RSMEM>>>(x, gate_w);
    route_kernel<<<T_ / 256, 256>>>(bias);
    slot_kernel<<<E_, 1024>>>();
    gather_kernel<<<dim3(CAP, E_), 256>>>(x);
    gemm1_mma<<<dim3(IDIM / 128, CAP / 128, E_), 256, G1_SMEM>>>();
    gemm2_mma<<<dim3(H_ / 128, CAP / 128, E_), 256, G2_SMEM>>>();
    combine_kernel<<<T_, 256>>>(out);
}

// round 9
// speedup vs baseline: 1.5694x; 1.2497x over previous
#include <cuda_runtime.h>
#include <cuda_bf16.h>
#include <math.h>
#include <stdint.h>

#define E_      32
#define KSEL    4
#define H_      1024
#define IDIM    768
#define T_      4096
#define NGROUP  8
#define TOPKG   4
#define CAP     1024
#define NASSIGN (T_ * KSEL)

// ---------------- scratch (device globals; no allocations) ----------------
__device__ float g_buft[(size_t)E_ * CAP * H_];     // gathered tokens, tf32-rounded
__device__ float g_actt[(size_t)E_ * CAP * IDIM];   // act, tf32-rounded
__device__ float g_w1t[(size_t)E_ * IDIM * H_];
__device__ float g_w3t[(size_t)E_ * IDIM * H_];
__device__ float g_w2t[(size_t)E_ * H_ * IDIM];
__device__ float g_y[(size_t)E_ * CAP * H_];
__device__ float g_sc[(size_t)T_ * E_];
__device__ int   g_cnt [E_];
__device__ int   g_tok [E_ * CAP];
__device__ int   g_expi[NASSIGN];
__device__ int   g_slot[NASSIGN];
__device__ float g_gw  [NASSIGN];

// ---------------- helpers ----------------
__device__ __forceinline__ uint32_t smem_u32(const void* p) {
    uint32_t a;
    asm("{ .reg .u64 t; cvta.to.shared.u64 t, %1; cvt.u32.u64 %0, t; }" : "=r"(a) : "l"(p));
    return a;
}
__device__ __forceinline__ void cp16(uint32_t dst, const void* src) {
    asm volatile("cp.async.cg.shared.global [%0], [%1], 16;" :: "r"(dst), "l"(src));
}
__device__ __forceinline__ void cp_commit() { asm volatile("cp.async.commit_group;"); }
__device__ __forceinline__ void cp_wait2()  { asm volatile("cp.async.wait_group 2;"); }
#define LDSM4(r, a) \
    asm volatile("ldmatrix.sync.aligned.m8n8.x4.shared.b16 {%0,%1,%2,%3}, [%4];" \
        : "=r"((r)[0]), "=r"((r)[1]), "=r"((r)[2]), "=r"((r)[3]) : "r"(a))
// tf32 mma: D(16x8) += A(16x8) * B(8x8)
__device__ __forceinline__ void mma_tf32(float* c, const uint32_t* a, uint32_t b0, uint32_t b1) {
    asm volatile(
        "mma.sync.aligned.m16n8k8.row.col.f32.tf32.tf32.f32 "
        "{%0,%1,%2,%3}, {%4,%5,%6,%7}, {%8,%9}, {%0,%1,%2,%3};"
        : "+f"(c[0]), "+f"(c[1]), "+f"(c[2]), "+f"(c[3])
        : "r"(a[0]), "r"(a[1]), "r"(a[2]), "r"(a[3]), "r"(b0), "r"(b1));
}
// round-to-nearest tf32 (keeps fp32 bit layout, low 13 mantissa bits zero)
__device__ __forceinline__ float f2tf(float x) {
    uint32_t u;
    asm("cvt.rna.tf32.f32 %0, %1;" : "=r"(u) : "f"(x));
    return __uint_as_float(u);
}
// XOR-swizzled smem address: 128 rows x 128B; chunk = 16B unit (0..7) within row.
// chunk' = chunk ^ (row & 7): conflict-free per 8-lane ldmatrix phase; store & load
// both address through this, so it is self-consistent.
__device__ __forceinline__ uint32_t swz(uint32_t base, int row, int chunk) {
    return base + (uint32_t)row * 128u + ((uint32_t)(chunk ^ (row & 7)) << 4);
}

// ---------------- weight conversion: fp32 -> tf32-rounded fp32 ----------------
__global__ void cvt_tf32(const float4* __restrict__ src, float4* __restrict__ dst, int n4) {
    for (int i = blockIdx.x * blockDim.x + threadIdx.x; i < n4; i += gridDim.x * blockDim.x) {
        float4 v = src[i];
        dst[i] = make_float4(f2tf(v.x), f2tf(v.y), f2tf(v.z), f2tf(v.w));
    }
}

// ---------------- router stage 1: gate scores (8 tokens/block) ----------------
#define RTOK 8
#define RSTAGE_ITERS (RTOK * (H_ / 4) / 256)
__global__ __launch_bounds__(256) void score_kernel(const float* __restrict__ x,
                                                    const float* __restrict__ gate_w) {
    extern __shared__ float xs[];
    int tid = threadIdx.x, lane = tid & 31, w = tid >> 5;
    int tb = blockIdx.x * RTOK;

    const float4* xg = (const float4*)(x + (size_t)tb * H_);
    float4* xs4 = (float4*)xs;
    #pragma unroll
    for (int i = 0; i < RSTAGE_ITERS; i++) xs4[tid + i * 256] = xg[tid + i * 256];
    __syncthreads();

    #pragma unroll
    for (int j = 0; j < 4; j++) {
        int e = w * 4 + j;
        const float4* g4 = (const float4*)(gate_w + (size_t)e * H_);
        float acc[RTOK];
        #pragma unroll
        for (int t = 0; t < RTOK; t++) acc[t] = 0.f;
        for (int it = 0; it < 8; it++) {   // not unrolled: keep regs sane
            float4 gv = g4[it * 32 + lane];
            #pragma unroll
            for (int t = 0; t < RTOK; t++) {
                float4 xv = *(const float4*)&xs[t * H_ + (it * 32 + lane) * 4];
                acc[t] += gv.x * xv.x + gv.y * xv.y + gv.z * xv.z + gv.w * xv.w;
            }
        }
        #pragma unroll
        for (int t = 0; t < RTOK; t++) {
            float v = acc[t];
            #pragma unroll
            for (int o = 16; o; o >>= 1) v += __shfl_xor_sync(0xffffffffu, v, o);
            if (lane == 0) g_sc[(size_t)(tb + t) * E_ + e] = v;
        }
    }
}

// ---------------- router stage 2: top-k, register-only bitmask selection ----------------
__global__ __launch_bounds__(256) void route_kernel(const float* __restrict__ bias) {
    int t = blockIdx.x * blockDim.x + threadIdx.x;
    if (t >= T_) return;

    float s[E_], sfc[E_];
    #pragma unroll
    for (int e = 0; e < E_; e++) {
        float v = g_sc[(size_t)t * E_ + e];
        s[e]   = 1.f / (1.f + expf(-v));
        sfc[e] = s[e] + bias[e];
    }
    float gs[NGROUP];
    #pragma unroll
    for (int g = 0; g < NGROUP; g++) {
        float m1 = -1e30f, m2 = -1e30f;
        #pragma unroll
        for (int j = 0; j < 4; j++) {
            float v = sfc[g * 4 + j];
            if (v > m1) { m2 = m1; m1 = v; }
            else if (v > m2) m2 = v;
        }
        gs[g] = m1 + m2;
    }
    uint32_t gmask = 0;
    #pragma unroll
    for (int it = 0; it < TOPKG; it++) {
        float best = -1e30f; int bi = 0;
        #pragma unroll
        for (int g = 0; g < NGROUP; g++) {
            bool c = !((gmask >> g) & 1u) && gs[g] > best;
            if (c) { best = gs[g]; bi = g; }
        }
        gmask |= 1u << bi;
    }
    uint32_t emask = 0;
    int   sel[KSEL];
    float rw[KSEL];
    #pragma unroll
    for (int k = 0; k < KSEL; k++) {
        float best = -1e30f, braw = 0.f; int bi = 0;
        #pragma unroll
        for (int e = 0; e < E_; e++) {
            float v = ((gmask >> (e >> 2)) & 1u) ? sfc[e] : 0.f;
            bool c = !((emask >> e) & 1u) && v > best;
            if (c) { best = v; bi = e; braw = s[e]; }
        }
        emask |= 1u << bi;
        sel[k] = bi;
        rw[k]  = braw;
    }
    float inv = 1.f / (rw[0] + rw[1] + rw[2] + rw[3]);
    #pragma unroll
    for (int k = 0; k < KSEL; k++) {
        int a = t * KSEL + k;
        g_expi[a] = sel[k];
        g_gw[a]   = rw[k] * inv;
    }
}

// ---------------- deterministic slot assignment ----------------
__global__ __launch_bounds__(1024) void slot_kernel() {
    int e = blockIdx.x, tid = threadIdx.x;
    int lane = tid & 31, warp = tid >> 5;
    __shared__ int warp_sums[32];
    int base = 0;
    for (int c0 = 0; c0 < NASSIGN; c0 += 1024) {
        int a = c0 + tid;
        bool flag = (g_expi[a] == e);
        unsigned bal = __ballot_sync(0xffffffffu, flag);
        int wprefix = __popc(bal & ((1u << lane) - 1u));
        if (lane == 31) warp_sums[warp] = __popc(bal);
        __syncthreads();
        if (warp == 0) {
            int v = warp_sums[lane];
            #pragma unroll
            for (int o = 1; o < 32; o <<= 1) {
                int n = __shfl_up_sync(0xffffffffu, v, o);
                if (lane >= o) v += n;
            }
            warp_sums[lane] = v;
        }
        __syncthreads();
        int woff  = (warp == 0) ? 0 : warp_sums[warp - 1];
        int total = warp_sums[31];
        if (flag) {
            int slot = base + woff + wprefix;
            if (slot < CAP) {
                g_slot[a] = slot;
                g_tok[e * CAP + slot] = a >> 2;
            } else {
                g_slot[a] = -1;
            }
        }
        base += total;
        __syncthreads();
    }
    if (tid == 0) g_cnt[e] = base < CAP ? base : CAP;
}

// gather: token rows -> per-expert tf32-rounded buffers
__global__ void gather_kernel(const float* __restrict__ x) {
    int e = blockIdx.y, slot = blockIdx.x;
    if (slot >= g_cnt[e]) return;
    int t = g_tok[e * CAP + slot];
    const float4* src = (const float4*)(x + (size_t)t * H_);
    float4* dst = (float4*)(g_buft + ((size_t)e * CAP + slot) * H_);
    for (int i = threadIdx.x; i < H_ / 4; i += blockDim.x) {
        float4 v = src[i];
        dst[i] = make_float4(f2tf(v.x), f2tf(v.y), f2tf(v.z), f2tf(v.w));
    }
}

// ---------------- GEMM common ----------------
#define PS32   16384          // plane: 128 rows x 128B (32 tf32), XOR-swizzled
#define NSTG   4

// ---------------- GEMM1: h1/h3 single-pass tf32 + fused SiLU ----------------
#define G1_STAGE  (3 * PS32)         // 49152
#define G1_SMEM   (NSTG * G1_STAGE)  // 196608

__global__ __launch_bounds__(256) void gemm1_mma(void) {
    int e   = blockIdx.z;
    int cnt = g_cnt[e];
    int m0  = blockIdx.y * 128;
    if (m0 >= cnt) return;
    int n0  = blockIdx.x * 128;

    extern __shared__ char sm[];
    uint32_t sb = smem_u32(sm);
    int tid = threadIdx.x, lane = tid & 31, wid = tid >> 5;
    int wm = (wid & 1) * 64, wn = (wid >> 1) * 32;
    int g = lane >> 2, tg = lane & 3;
    int lane15 = lane & 15;
    int lchunk = lane >> 4;

    const float* srcs[3] = {
        g_buft + ((size_t)e * CAP  + m0) * H_,
        g_w1t  + ((size_t)e * IDIM + n0) * H_,
        g_w3t  + ((size_t)e * IDIM + n0) * H_
    };
    int lrow = tid >> 1;
    int half = tid & 1;

    #pragma unroll
    for (int st = 0; st < NSTG - 1; st++) {
        uint32_t s0 = sb + st * G1_STAGE;
        #pragma unroll
        for (int p = 0; p < 3; p++) {
            const float* gp = srcs[p] + (size_t)lrow * H_ + st * 32;
            #pragma unroll
            for (int j = 0; j < 4; j++) {
                int ch = half * 4 + j;
                cp16(swz(s0 + p * PS32, lrow, ch), gp + ch * 4);
            }
        }
        cp_commit();
    }

    float c1[4][4][4] = {}, c3[4][4][4] = {};

    const int NK = H_ / 32;  // 32
    for (int kt = 0; kt < NK; kt++) {
        cp_wait2();
        __syncthreads();
        if (kt + NSTG - 1 < NK) {
            uint32_t s0 = sb + ((kt + NSTG - 1) % NSTG) * G1_STAGE;
            #pragma unroll
            for (int p = 0; p < 3; p++) {
                const float* gp = srcs[p] + (size_t)lrow * H_ + (kt + NSTG - 1) * 32;
                #pragma unroll
                for (int j = 0; j < 4; j++) {
                    int ch = half * 4 + j;
                    cp16(swz(s0 + p * PS32, lrow, ch), gp + ch * 4);
                }
            }
        }
        cp_commit();

        uint32_t bs = sb + (kt % NSTG) * G1_STAGE;
        #pragma unroll
        for (int ks = 0; ks < 4; ks++) {
            int cb = ks * 2 + lchunk;
            uint32_t Af[4][4];
            #pragma unroll
            for (int mi = 0; mi < 4; mi++)
                LDSM4(Af[mi], swz(bs, wm + lane15 + mi * 16, cb));
            uint32_t t_[4], Bf[4][2];
            #pragma unroll
            for (int n2 = 0; n2 < 2; n2++) {
                LDSM4(t_, swz(bs + PS32, wn + lane15 + n2 * 16, cb));
                Bf[2 * n2][0] = t_[0]; Bf[2 * n2][1] = t_[2];
                Bf[2 * n2 + 1][0] = t_[1]; Bf[2 * n2 + 1][1] = t_[3];
            }
            #pragma unroll
            for (int mi = 0; mi < 4; mi++)
                #pragma unroll
                for (int ni = 0; ni < 4; ni++)
                    mma_tf32(c1[mi][ni], Af[mi], Bf[ni][0], Bf[ni][1]);
            #pragma unroll
            for (int n2 = 0; n2 < 2; n2++) {
                LDSM4(t_, swz(bs + 2 * PS32, wn + lane15 + n2 * 16, cb));
                Bf[2 * n2][0] = t_[0]; Bf[2 * n2][1] = t_[2];
                Bf[2 * n2 + 1][0] = t_[1]; Bf[2 * n2 + 1][1] = t_[3];
            }
            #pragma unroll
            for (int mi = 0; mi < 4; mi++)
                #pragma unroll
                for (int ni = 0; ni < 4; ni++)
                    mma_tf32(c3[mi][ni], Af[mi], Bf[ni][0], Bf[ni][1]);
        }
    }

    // epilogue: act = silu(h1)*h3 -> tf32-rounded fp32
    #pragma unroll
    for (int mi = 0; mi < 4; mi++) {
        int r0 = m0 + wm + mi * 16 + g;
        #pragma unroll
        for (int ni = 0; ni < 4; ni++) {
            int cb = n0 + wn + ni * 8 + tg * 2;
            float h1a = c1[mi][ni][0], h1b = c1[mi][ni][1];
            float v0 = h1a / (1.f + expf(-h1a)) * c3[mi][ni][0];
            float v1 = h1b / (1.f + expf(-h1b)) * c3[mi][ni][1];
            float h1c = c1[mi][ni][2], h1d = c1[mi][ni][3];
            float v2 = h1c / (1.f + expf(-h1c)) * c3[mi][ni][2];
            float v3 = h1d / (1.f + expf(-h1d)) * c3[mi][ni][3];
            size_t o0 = ((size_t)e * CAP + r0) * IDIM + cb;
            *(float2*)(g_actt + o0) = make_float2(f2tf(v0), f2tf(v1));
            size_t o1 = ((size_t)e * CAP + r0 + 8) * IDIM + cb;
            *(float2*)(g_actt + o1) = make_float2(f2tf(v2), f2tf(v3));
        }
    }
}

// ---------------- GEMM2: y = act @ w2^T, single-pass tf32 ----------------
#define G2_STAGE  (2 * PS32)         // 32768
#define G2_SMEM   (NSTG * G2_STAGE)  // 131072

__global__ __launch_bounds__(256) void gemm2_mma(void) {
    int e   = blockIdx.z;
    int cnt = g_cnt[e];
    int m0  = blockIdx.y * 128;
    if (m0 >= cnt) return;
    int n0  = blockIdx.x * 128;

    extern __shared__ char sm[];
    uint32_t sb = smem_u32(sm);
    int tid = threadIdx.x, lane = tid & 31, wid = tid >> 5;
    int wm = (wid & 1) * 64, wn = (wid >> 1) * 32;
    int g = lane >> 2, tg = lane & 3;
    int lane15 = lane & 15;
    int lchunk = lane >> 4;

    const float* srcs[2] = {
        g_actt + ((size_t)e * CAP + m0) * IDIM,
        g_w2t  + ((size_t)e * H_  + n0) * IDIM
    };
    int lrow = tid >> 1;
    int half = tid & 1;

    #pragma unroll
    for (int st = 0; st < NSTG - 1; st++) {
        uint32_t s0 = sb + st * G2_STAGE;
        #pragma unroll
        for (int p = 0; p < 2; p++) {
            const float* gp = srcs[p] + (size_t)lrow * IDIM + st * 32;
            #pragma unroll
            for (int j = 0; j < 4; j++) {
                int ch = half * 4 + j;
                cp16(swz(s0 + p * PS32, lrow, ch), gp + ch * 4);
            }
        }
        cp_commit();
    }

    float cc[4][4][4] = {};

    const int NK = IDIM / 32;  // 24
    for (int kt = 0; kt < NK; kt++) {
        cp_wait2();
        __syncthreads();
        if (kt + NSTG - 1 < NK) {
            uint32_t s0 = sb + ((kt + NSTG - 1) % NSTG) * G2_STAGE;
            #pragma unroll
            for (int p = 0; p < 2; p++) {
                const float* gp = srcs[p] + (size_t)lrow * IDIM + (kt + NSTG - 1) * 32;
                #pragma unroll
                for (int j = 0; j < 4; j++) {
                    int ch = half * 4 + j;
                    cp16(swz(s0 + p * PS32, lrow, ch), gp + ch * 4);
                }
            }
        }
        cp_commit();

        uint32_t bs = sb + (kt % NSTG) * G2_STAGE;
        #pragma unroll
        for (int ks = 0; ks < 4; ks++) {
            int cb = ks * 2 + lchunk;
            uint32_t Af[4][4];
            #pragma unroll
            for (int mi = 0; mi < 4; mi++)
                LDSM4(Af[mi], swz(bs, wm + lane15 + mi * 16, cb));
            uint32_t t_[4], Bf[4][2];
            #pragma unroll
            for (int n2 = 0; n2 < 2; n2++) {
                LDSM4(t_, swz(bs + PS32, wn + lane15 + n2 * 16, cb));
                Bf[2 * n2][0] = t_[0]; Bf[2 * n2][1] = t_[2];
                Bf[2 * n2 + 1][0] = t_[1]; Bf[2 * n2 + 1][1] = t_[3];
            }
            #pragma unroll
            for (int mi = 0; mi < 4; mi++)
                #pragma unroll
                for (int ni = 0; ni < 4; ni++)
                    mma_tf32(cc[mi][ni], Af[mi], Bf[ni][0], Bf[ni][1]);
        }
    }

    #pragma unroll
    for (int mi = 0; mi < 4; mi++) {
        int r0 = m0 + wm + mi * 16 + g;
        #pragma unroll
        for (int ni = 0; ni < 4; ni++) {
            int cb = n0 + wn + ni * 8 + tg * 2;
            *(float2*)(g_y + ((size_t)e * CAP + r0) * H_ + cb) =
                make_float2(cc[mi][ni][0], cc[mi][ni][1]);
            *(float2*)(g_y + ((size_t)e * CAP + r0 + 8) * H_ + cb) =
                make_float2(cc[mi][ni][2], cc[mi][ni][3]);
        }
    }
}

// ---------------- combine ----------------
__global__ void combine_kernel(float* __restrict__ out) {
    int t = blockIdx.x;
    int i = threadIdx.x;
    float4 acc = make_float4(0.f, 0.f, 0.f, 0.f);
    #pragma unroll
    for (int k = 0; k < KSEL; k++) {
        int a = t * KSEL + k;
        int slot = g_slot[a];
        if (slot < 0) continue;
        int e = g_expi[a];
        float w = g_gw[a];
        const float4* yr = (const float4*)(g_y + ((size_t)e * CAP + slot) * H_);
        float4 v = yr[i];
        acc.x += w * v.x; acc.y += w * v.y; acc.z += w * v.z; acc.w += w * v.w;
    }
    ((float4*)(out + (size_t)t * H_))[i] = acc;
}

// ---------------- launch ----------------
extern "C" void kernel_launch(void* const* d_in, const int* in_sizes, int n_in,
                              void* d_out, int out_size) {
    (void)in_sizes; (void)n_in; (void)out_size;
    const float* x      = (const float*)d_in[0];
    const float* gate_w = (const float*)d_in[1];
    const float* w1     = (const float*)d_in[2];
    const float* w3     = (const float*)d_in[3];
    const float* w2     = (const float*)d_in[4];
    const float* bias   = (const float*)d_in[5];
    float*       out    = (float*)d_out;

    const int RSMEM = RTOK * H_ * 4;
    cudaFuncSetAttribute(score_kernel, cudaFuncAttributeMaxDynamicSharedMemorySize, RSMEM);
    cudaFuncSetAttribute(gemm1_mma, cudaFuncAttributeMaxDynamicSharedMemorySize, G1_SMEM);
    cudaFuncSetAttribute(gemm2_mma, cudaFuncAttributeMaxDynamicSharedMemorySize, G2_SMEM);

    void *p_w1t, *p_w3t, *p_w2t;
    cudaGetSymbolAddress(&p_w1t, g_w1t);
    cudaGetSymbolAddress(&p_w3t, g_w3t);
    cudaGetSymbolAddress(&p_w2t, g_w2t);

    const int n4 = E_ * IDIM * H_ / 4;
    cvt_tf32<<<4096, 256>>>((const float4*)w1, (float4*)p_w1t, n4);
    cvt_tf32<<<4096, 256>>>((const float4*)w3, (float4*)p_w3t, n4);
    cvt_tf32<<<4096, 256>>>((const float4*)w2, (float4*)p_w2t, n4);

    score_kernel<<<T_ / RTOK, 256, RSMEM>>>(x, gate_w);
    route_kernel<<<T_ / 256, 256>>>(bias);
    slot_kernel<<<E_, 1024>>>();
    gather_kernel<<<dim3(CAP, E_), 256>>>(x);
    gemm1_mma<<<dim3(IDIM / 128, CAP / 128, E_), 256, G1_SMEM>>>();
    gemm2_mma<<<dim3(H_ / 128, CAP / 128, E_), 256, G2_SMEM>>>();
    combine_kernel<<<T_, 256>>>(out);
}

// round 10
// speedup vs baseline: 2.6178x; 1.6680x over previous
#include <cuda_runtime.h>
#include <cuda_fp16.h>
#include <math.h>
#include <stdint.h>

#define E_      32
#define KSEL    4
#define H_      1024
#define IDIM    768
#define T_      4096
#define NGROUP  8
#define TOPKG   4
#define CAP     1024
#define NASSIGN (T_ * KSEL)

// ---------------- scratch (device globals; no allocations) ----------------
__device__ __half g_bufh[(size_t)E_ * CAP * H_];    // gathered tokens (fp16)
__device__ __half g_acth[(size_t)E_ * CAP * IDIM];  // act (fp16)
__device__ __half g_w1h[(size_t)E_ * IDIM * H_];
__device__ __half g_w3h[(size_t)E_ * IDIM * H_];
__device__ __half g_w2h[(size_t)E_ * H_ * IDIM];
__device__ float  g_y[(size_t)E_ * CAP * H_];
__device__ float  g_sc[(size_t)T_ * E_];
__device__ int    g_cnt [E_];
__device__ int    g_tok [E_ * CAP];
__device__ int    g_expi[NASSIGN];
__device__ int    g_slot[NASSIGN];
__device__ float  g_gw  [NASSIGN];

// ---------------- helpers ----------------
__device__ __forceinline__ uint32_t smem_u32(const void* p) {
    uint32_t a;
    asm("{ .reg .u64 t; cvta.to.shared.u64 t, %1; cvt.u32.u64 %0, t; }" : "=r"(a) : "l"(p));
    return a;
}
__device__ __forceinline__ void cp16(uint32_t dst, const void* src) {
    asm volatile("cp.async.cg.shared.global [%0], [%1], 16;" :: "r"(dst), "l"(src));
}
__device__ __forceinline__ void cp_commit() { asm volatile("cp.async.commit_group;"); }
__device__ __forceinline__ void cp_wait2()  { asm volatile("cp.async.wait_group 2;"); }
#define LDSM4(r, a) \
    asm volatile("ldmatrix.sync.aligned.m8n8.x4.shared.b16 {%0,%1,%2,%3}, [%4];" \
        : "=r"((r)[0]), "=r"((r)[1]), "=r"((r)[2]), "=r"((r)[3]) : "r"(a))
// fp16 mma with fp32 accumulate: D(16x8) += A(16x16) * B(16x8)
__device__ __forceinline__ void mma_f16(float* c, const uint32_t* a, uint32_t b0, uint32_t b1) {
    asm volatile(
        "mma.sync.aligned.m16n8k16.row.col.f32.f16.f16.f32 "
        "{%0,%1,%2,%3}, {%4,%5,%6,%7}, {%8,%9}, {%0,%1,%2,%3};"
        : "+f"(c[0]), "+f"(c[1]), "+f"(c[2]), "+f"(c[3])
        : "r"(a[0]), "r"(a[1]), "r"(a[2]), "r"(a[3]), "r"(b0), "r"(b1));
}
__device__ __forceinline__ uint32_t pack_h2(float x, float y) {
    __half2 h = __floats2half2_rn(x, y);
    return *(uint32_t*)&h;
}
// XOR-swizzled smem address: 128 rows x 64B; chunk = 16B unit (0..3) within row.
// chunk' = chunk ^ ((row>>1)&3). Same layout R8 validated at rel_err 9.5e-6.
__device__ __forceinline__ uint32_t swz(uint32_t base, int row, int chunk) {
    return base + (uint32_t)row * 64u + ((uint32_t)(chunk ^ ((row >> 1) & 3)) << 4);
}

// ---------------- weight conversion: fp32 -> fp16 ----------------
__global__ void cvt_f16(const float4* __restrict__ src, uint2* __restrict__ dst, int n4) {
    for (int i = blockIdx.x * blockDim.x + threadIdx.x; i < n4; i += gridDim.x * blockDim.x) {
        float4 v = src[i];
        dst[i] = make_uint2(pack_h2(v.x, v.y), pack_h2(v.z, v.w));
    }
}

// ---------------- router stage 1: gate scores (8 tokens/block) ----------------
#define RTOK 8
#define RSTAGE_ITERS (RTOK * (H_ / 4) / 256)
__global__ __launch_bounds__(256) void score_kernel(const float* __restrict__ x,
                                                    const float* __restrict__ gate_w) {
    extern __shared__ float xs[];
    int tid = threadIdx.x, lane = tid & 31, w = tid >> 5;
    int tb = blockIdx.x * RTOK;

    const float4* xg = (const float4*)(x + (size_t)tb * H_);
    float4* xs4 = (float4*)xs;
    #pragma unroll
    for (int i = 0; i < RSTAGE_ITERS; i++) xs4[tid + i * 256] = xg[tid + i * 256];
    __syncthreads();

    #pragma unroll
    for (int j = 0; j < 4; j++) {
        int e = w * 4 + j;
        const float4* g4 = (const float4*)(gate_w + (size_t)e * H_);
        float acc[RTOK];
        #pragma unroll
        for (int t = 0; t < RTOK; t++) acc[t] = 0.f;
        for (int it = 0; it < 8; it++) {
            float4 gv = g4[it * 32 + lane];
            #pragma unroll
            for (int t = 0; t < RTOK; t++) {
                float4 xv = *(const float4*)&xs[t * H_ + (it * 32 + lane) * 4];
                acc[t] += gv.x * xv.x + gv.y * xv.y + gv.z * xv.z + gv.w * xv.w;
            }
        }
        #pragma unroll
        for (int t = 0; t < RTOK; t++) {
            float v = acc[t];
            #pragma unroll
            for (int o = 16; o; o >>= 1) v += __shfl_xor_sync(0xffffffffu, v, o);
            if (lane == 0) g_sc[(size_t)(tb + t) * E_ + e] = v;
        }
    }
}

// ---------------- router stage 2: top-k, register-only bitmask selection ----------------
__global__ __launch_bounds__(256) void route_kernel(const float* __restrict__ bias) {
    int t = blockIdx.x * blockDim.x + threadIdx.x;
    if (t >= T_) return;

    float s[E_], sfc[E_];
    #pragma unroll
    for (int e = 0; e < E_; e++) {
        float v = g_sc[(size_t)t * E_ + e];
        s[e]   = 1.f / (1.f + expf(-v));
        sfc[e] = s[e] + bias[e];
    }
    float gs[NGROUP];
    #pragma unroll
    for (int g = 0; g < NGROUP; g++) {
        float m1 = -1e30f, m2 = -1e30f;
        #pragma unroll
        for (int j = 0; j < 4; j++) {
            float v = sfc[g * 4 + j];
            if (v > m1) { m2 = m1; m1 = v; }
            else if (v > m2) m2 = v;
        }
        gs[g] = m1 + m2;
    }
    uint32_t gmask = 0;
    #pragma unroll
    for (int it = 0; it < TOPKG; it++) {
        float best = -1e30f; int bi = 0;
        #pragma unroll
        for (int g = 0; g < NGROUP; g++) {
            bool c = !((gmask >> g) & 1u) && gs[g] > best;
            if (c) { best = gs[g]; bi = g; }
        }
        gmask |= 1u << bi;
    }
    uint32_t emask = 0;
    int   sel[KSEL];
    float rw[KSEL];
    #pragma unroll
    for (int k = 0; k < KSEL; k++) {
        float best = -1e30f, braw = 0.f; int bi = 0;
        #pragma unroll
        for (int e = 0; e < E_; e++) {
            float v = ((gmask >> (e >> 2)) & 1u) ? sfc[e] : 0.f;
            bool c = !((emask >> e) & 1u) && v > best;
            if (c) { best = v; bi = e; braw = s[e]; }
        }
        emask |= 1u << bi;
        sel[k] = bi;
        rw[k]  = braw;
    }
    float inv = 1.f / (rw[0] + rw[1] + rw[2] + rw[3]);
    #pragma unroll
    for (int k = 0; k < KSEL; k++) {
        int a = t * KSEL + k;
        g_expi[a] = sel[k];
        g_gw[a]   = rw[k] * inv;
    }
}

// ---------------- deterministic slot assignment ----------------
__global__ __launch_bounds__(1024) void slot_kernel() {
    int e = blockIdx.x, tid = threadIdx.x;
    int lane = tid & 31, warp = tid >> 5;
    __shared__ int warp_sums[32];
    int base = 0;
    for (int c0 = 0; c0 < NASSIGN; c0 += 1024) {
        int a = c0 + tid;
        bool flag = (g_expi[a] == e);
        unsigned bal = __ballot_sync(0xffffffffu, flag);
        int wprefix = __popc(bal & ((1u << lane) - 1u));
        if (lane == 31) warp_sums[warp] = __popc(bal);
        __syncthreads();
        if (warp == 0) {
            int v = warp_sums[lane];
            #pragma unroll
            for (int o = 1; o < 32; o <<= 1) {
                int n = __shfl_up_sync(0xffffffffu, v, o);
                if (lane >= o) v += n;
            }
            warp_sums[lane] = v;
        }
        __syncthreads();
        int woff  = (warp == 0) ? 0 : warp_sums[warp - 1];
        int total = warp_sums[31];
        if (flag) {
            int slot = base + woff + wprefix;
            if (slot < CAP) {
                g_slot[a] = slot;
                g_tok[e * CAP + slot] = a >> 2;
            } else {
                g_slot[a] = -1;
            }
        }
        base += total;
        __syncthreads();
    }
    if (tid == 0) g_cnt[e] = base < CAP ? base : CAP;
}

// gather: token rows -> per-expert fp16 buffers
__global__ void gather_kernel(const float* __restrict__ x) {
    int e = blockIdx.y, slot = blockIdx.x;
    if (slot >= g_cnt[e]) return;
    int t = g_tok[e * CAP + slot];
    const float4* src = (const float4*)(x + (size_t)t * H_);
    uint2* dst = (uint2*)(g_bufh + ((size_t)e * CAP + slot) * H_);
    for (int i = threadIdx.x; i < H_ / 4; i += blockDim.x) {
        float4 v = src[i];
        dst[i] = make_uint2(pack_h2(v.x, v.y), pack_h2(v.z, v.w));
    }
}

// ---------------- GEMM common ----------------
#define PS      8192          // plane: 128 rows x 64B (32 fp16), XOR-swizzled
#define NSTG    4

// ---------------- GEMM1: h1/h3 single-pass fp16 + fused SiLU ----------------
#define G1_STAGE  (3 * PS)           // 24576
#define G1_SMEM   (NSTG * G1_STAGE)  // 98304

__global__ __launch_bounds__(256) void gemm1_mma(void) {
    int e   = blockIdx.z;
    int cnt = g_cnt[e];
    int m0  = blockIdx.y * 128;
    if (m0 >= cnt) return;
    int n0  = blockIdx.x * 128;

    extern __shared__ char sm[];
    uint32_t sb = smem_u32(sm);
    int tid = threadIdx.x, lane = tid & 31, wid = tid >> 5;
    int wm = (wid & 1) * 64, wn = (wid >> 1) * 32;
    int g = lane >> 2, tg = lane & 3;
    int lane15 = lane & 15;
    int lchunk = lane >> 4;

    const __half* srcs[3] = {
        g_bufh + ((size_t)e * CAP  + m0) * H_,
        g_w1h  + ((size_t)e * IDIM + n0) * H_,
        g_w3h  + ((size_t)e * IDIM + n0) * H_
    };
    int lrow = tid >> 1;
    int lc0  = (tid & 1) * 2;

    #pragma unroll
    for (int st = 0; st < NSTG - 1; st++) {
        uint32_t s0 = sb + st * G1_STAGE;
        int k0 = st * 32 + lc0 * 8;
        #pragma unroll
        for (int p = 0; p < 3; p++) {
            const __half* gp = srcs[p] + (size_t)lrow * H_ + k0;
            cp16(swz(s0 + p * PS, lrow, lc0),     gp);
            cp16(swz(s0 + p * PS, lrow, lc0 + 1), gp + 8);
        }
        cp_commit();
    }

    float c1[4][4][4] = {}, c3[4][4][4] = {};

    const int NK = H_ / 32;  // 32
    for (int kt = 0; kt < NK; kt++) {
        cp_wait2();
        __syncthreads();
        if (kt + NSTG - 1 < NK) {
            uint32_t s0 = sb + ((kt + NSTG - 1) % NSTG) * G1_STAGE;
            int k0 = (kt + NSTG - 1) * 32 + lc0 * 8;
            #pragma unroll
            for (int p = 0; p < 3; p++) {
                const __half* gp = srcs[p] + (size_t)lrow * H_ + k0;
                cp16(swz(s0 + p * PS, lrow, lc0),     gp);
                cp16(swz(s0 + p * PS, lrow, lc0 + 1), gp + 8);
            }
        }
        cp_commit();

        uint32_t bs = sb + (kt % NSTG) * G1_STAGE;
        #pragma unroll
        for (int kb = 0; kb < 2; kb++) {
            int ch = kb * 2 + lchunk;
            uint32_t Af[4][4];
            #pragma unroll
            for (int mi = 0; mi < 4; mi++)
                LDSM4(Af[mi], swz(bs, wm + lane15 + mi * 16, ch));
            uint32_t t_[4], Bf[4][2];
            #pragma unroll
            for (int n2 = 0; n2 < 2; n2++) {
                LDSM4(t_, swz(bs + PS, wn + lane15 + n2 * 16, ch));
                Bf[2 * n2][0] = t_[0]; Bf[2 * n2][1] = t_[2];
                Bf[2 * n2 + 1][0] = t_[1]; Bf[2 * n2 + 1][1] = t_[3];
            }
            #pragma unroll
            for (int mi = 0; mi < 4; mi++)
                #pragma unroll
                for (int ni = 0; ni < 4; ni++)
                    mma_f16(c1[mi][ni], Af[mi], Bf[ni][0], Bf[ni][1]);
            #pragma unroll
            for (int n2 = 0; n2 < 2; n2++) {
                LDSM4(t_, swz(bs + 2 * PS, wn + lane15 + n2 * 16, ch));
                Bf[2 * n2][0] = t_[0]; Bf[2 * n2][1] = t_[2];
                Bf[2 * n2 + 1][0] = t_[1]; Bf[2 * n2 + 1][1] = t_[3];
            }
            #pragma unroll
            for (int mi = 0; mi < 4; mi++)
                #pragma unroll
                for (int ni = 0; ni < 4; ni++)
                    mma_f16(c3[mi][ni], Af[mi], Bf[ni][0], Bf[ni][1]);
        }
    }

    // epilogue: act = silu(h1)*h3 -> fp16
    #pragma unroll
    for (int mi = 0; mi < 4; mi++) {
        int r0 = m0 + wm + mi * 16 + g;
        #pragma unroll
        for (int ni = 0; ni < 4; ni++) {
            int cb = n0 + wn + ni * 8 + tg * 2;
            float h1a = c1[mi][ni][0], h1b = c1[mi][ni][1];
            float v0 = h1a / (1.f + expf(-h1a)) * c3[mi][ni][0];
            float v1 = h1b / (1.f + expf(-h1b)) * c3[mi][ni][1];
            float h1c = c1[mi][ni][2], h1d = c1[mi][ni][3];
            float v2 = h1c / (1.f + expf(-h1c)) * c3[mi][ni][2];
            float v3 = h1d / (1.f + expf(-h1d)) * c3[mi][ni][3];
            size_t o0 = ((size_t)e * CAP + r0) * IDIM + cb;
            *(uint32_t*)(g_acth + o0) = pack_h2(v0, v1);
            size_t o1 = ((size_t)e * CAP + r0 + 8) * IDIM + cb;
            *(uint32_t*)(g_acth + o1) = pack_h2(v2, v3);
        }
    }
}

// ---------------- GEMM2: y = act @ w2^T, single-pass fp16 ----------------
#define G2_STAGE  (2 * PS)           // 16384
#define G2_SMEM   (NSTG * G2_STAGE)  // 65536

__global__ __launch_bounds__(256) void gemm2_mma(void) {
    int e   = blockIdx.z;
    int cnt = g_cnt[e];
    int m0  = blockIdx.y * 128;
    if (m0 >= cnt) return;
    int n0  = blockIdx.x * 128;

    extern __shared__ char sm[];
    uint32_t sb = smem_u32(sm);
    int tid = threadIdx.x, lane = tid & 31, wid = tid >> 5;
    int wm = (wid & 1) * 64, wn = (wid >> 1) * 32;
    int g = lane >> 2, tg = lane & 3;
    int lane15 = lane & 15;
    int lchunk = lane >> 4;

    const __half* srcs[2] = {
        g_acth + ((size_t)e * CAP + m0) * IDIM,
        g_w2h  + ((size_t)e * H_  + n0) * IDIM
    };
    int lrow = tid >> 1;
    int lc0  = (tid & 1) * 2;

    #pragma unroll
    for (int st = 0; st < NSTG - 1; st++) {
        uint32_t s0 = sb + st * G2_STAGE;
        int k0 = st * 32 + lc0 * 8;
        #pragma unroll
        for (int p = 0; p < 2; p++) {
            const __half* gp = srcs[p] + (size_t)lrow * IDIM + k0;
            cp16(swz(s0 + p * PS, lrow, lc0),     gp);
            cp16(swz(s0 + p * PS, lrow, lc0 + 1), gp + 8);
        }
        cp_commit();
    }

    float cc[4][4][4] = {};

    const int NK = IDIM / 32;  // 24
    for (int kt = 0; kt < NK; kt++) {
        cp_wait2();
        __syncthreads();
        if (kt + NSTG - 1 < NK) {
            uint32_t s0 = sb + ((kt + NSTG - 1) % NSTG) * G2_STAGE;
            int k0 = (kt + NSTG - 1) * 32 + lc0 * 8;
            #pragma unroll
            for (int p = 0; p < 2; p++) {
                const __half* gp = srcs[p] + (size_t)lrow * IDIM + k0;
                cp16(swz(s0 + p * PS, lrow, lc0),     gp);
                cp16(swz(s0 + p * PS, lrow, lc0 + 1), gp + 8);
            }
        }
        cp_commit();

        uint32_t bs = sb + (kt % NSTG) * G2_STAGE;
        #pragma unroll
        for (int kb = 0; kb < 2; kb++) {
            int ch = kb * 2 + lchunk;
            uint32_t Af[4][4];
            #pragma unroll
            for (int mi = 0; mi < 4; mi++)
                LDSM4(Af[mi], swz(bs, wm + lane15 + mi * 16, ch));
            uint32_t t_[4], Bf[4][2];
            #pragma unroll
            for (int n2 = 0; n2 < 2; n2++) {
                LDSM4(t_, swz(bs + PS, wn + lane15 + n2 * 16, ch));
                Bf[2 * n2][0] = t_[0]; Bf[2 * n2][1] = t_[2];
                Bf[2 * n2 + 1][0] = t_[1]; Bf[2 * n2 + 1][1] = t_[3];
            }
            #pragma unroll
            for (int mi = 0; mi < 4; mi++)
                #pragma unroll
                for (int ni = 0; ni < 4; ni++)
                    mma_f16(cc[mi][ni], Af[mi], Bf[ni][0], Bf[ni][1]);
        }
    }

    #pragma unroll
    for (int mi = 0; mi < 4; mi++) {
        int r0 = m0 + wm + mi * 16 + g;
        #pragma unroll
        for (int ni = 0; ni < 4; ni++) {
            int cb = n0 + wn + ni * 8 + tg * 2;
            *(float2*)(g_y + ((size_t)e * CAP + r0) * H_ + cb) =
                make_float2(cc[mi][ni][0], cc[mi][ni][1]);
            *(float2*)(g_y + ((size_t)e * CAP + r0 + 8) * H_ + cb) =
                make_float2(cc[mi][ni][2], cc[mi][ni][3]);
        }
    }
}

// ---------------- combine ----------------
__global__ void combine_kernel(float* __restrict__ out) {
    int t = blockIdx.x;
    int i = threadIdx.x;
    float4 acc = make_float4(0.f, 0.f, 0.f, 0.f);
    #pragma unroll
    for (int k = 0; k < KSEL; k++) {
        int a = t * KSEL + k;
        int slot = g_slot[a];
        if (slot < 0) continue;
        int e = g_expi[a];
        float w = g_gw[a];
        const float4* yr = (const float4*)(g_y + ((size_t)e * CAP + slot) * H_);
        float4 v = yr[i];
        acc.x += w * v.x; acc.y += w * v.y; acc.z += w * v.z; acc.w += w * v.w;
    }
    ((float4*)(out + (size_t)t * H_))[i] = acc;
}

// ---------------- launch ----------------
extern "C" void kernel_launch(void* const* d_in, const int* in_sizes, int n_in,
                              void* d_out, int out_size) {
    (void)in_sizes; (void)n_in; (void)out_size;
    const float* x      = (const float*)d_in[0];
    const float* gate_w = (const float*)d_in[1];
    const float* w1     = (const float*)d_in[2];
    const float* w3     = (const float*)d_in[3];
    const float* w2     = (const float*)d_in[4];
    const float* bias   = (const float*)d_in[5];
    float*       out    = (float*)d_out;

    const int RSMEM = RTOK * H_ * 4;
    cudaFuncSetAttribute(score_kernel, cudaFuncAttributeMaxDynamicSharedMemorySize, RSMEM);
    cudaFuncSetAttribute(gemm1_mma, cudaFuncAttributeMaxDynamicSharedMemorySize, G1_SMEM);
    cudaFuncSetAttribute(gemm2_mma, cudaFuncAttributeMaxDynamicSharedMemorySize, G2_SMEM);

    void *p_w1h, *p_w3h, *p_w2h;
    cudaGetSymbolAddress(&p_w1h, g_w1h);
    cudaGetSymbolAddress(&p_w3h, g_w3h);
    cudaGetSymbolAddress(&p_w2h, g_w2h);

    const int n4 = E_ * IDIM * H_ / 4;
    cvt_f16<<<4096, 256>>>((const float4*)w1, (uint2*)p_w1h, n4);
    cvt_f16<<<4096, 256>>>((const float4*)w3, (uint2*)p_w3h, n4);
    cvt_f16<<<4096, 256>>>((const float4*)w2, (uint2*)p_w2h, n4);

    score_kernel<<<T_ / RTOK, 256, RSMEM>>>(x, gate_w);
    route_kernel<<<T_ / 256, 256>>>(bias);
    slot_kernel<<<E_, 1024>>>();
    gather_kernel<<<dim3(CAP, E_), 256>>>(x);
    gemm1_mma<<<dim3(IDIM / 128, CAP / 128, E_), 256, G1_SMEM>>>();
    gemm2_mma<<<dim3(H_ / 128, CAP / 128, E_), 256, G2_SMEM>>>();
    combine_kernel<<<T_, 256>>>(out);
}

// round 11
// speedup vs baseline: 2.6670x; 1.0188x over previous
#include <cuda_runtime.h>
#include <cuda_fp16.h>
#include <math.h>
#include <stdint.h>

#define E_      32
#define KSEL    4
#define H_      1024
#define IDIM    768
#define T_      4096
#define NGROUP  8
#define TOPKG   4
#define CAP     1024
#define NASSIGN (T_ * KSEL)

// ---------------- scratch (device globals; no allocations) ----------------
__device__ __half g_bufh[(size_t)E_ * CAP * H_];    // gathered tokens (fp16)
__device__ __half g_acth[(size_t)E_ * CAP * IDIM];  // act (fp16)
__device__ __half g_w1h[(size_t)E_ * IDIM * H_];
__device__ __half g_w3h[(size_t)E_ * IDIM * H_];
__device__ __half g_w2h[(size_t)E_ * H_ * IDIM];
__device__ float  g_y[(size_t)E_ * CAP * H_];
__device__ float  g_sc[(size_t)T_ * E_];
__device__ int    g_cnt [E_];
__device__ int    g_tok [E_ * CAP];
__device__ int    g_expi[NASSIGN];
__device__ int    g_slot[NASSIGN];
__device__ float  g_gw  [NASSIGN];

// ---------------- helpers ----------------
__device__ __forceinline__ uint32_t smem_u32(const void* p) {
    uint32_t a;
    asm("{ .reg .u64 t; cvta.to.shared.u64 t, %1; cvt.u32.u64 %0, t; }" : "=r"(a) : "l"(p));
    return a;
}
__device__ __forceinline__ void cp16(uint32_t dst, const void* src) {
    asm volatile("cp.async.cg.shared.global [%0], [%1], 16;" :: "r"(dst), "l"(src));
}
__device__ __forceinline__ void cp_commit() { asm volatile("cp.async.commit_group;"); }
__device__ __forceinline__ void cp_wait1()  { asm volatile("cp.async.wait_group 1;"); }
#define LDSM4(r, a) \
    asm volatile("ldmatrix.sync.aligned.m8n8.x4.shared.b16 {%0,%1,%2,%3}, [%4];" \
        : "=r"((r)[0]), "=r"((r)[1]), "=r"((r)[2]), "=r"((r)[3]) : "r"(a))
// fp16 mma with fp32 accumulate: D(16x8) += A(16x16) * B(16x8)
__device__ __forceinline__ void mma_f16(float* c, const uint32_t* a, uint32_t b0, uint32_t b1) {
    asm volatile(
        "mma.sync.aligned.m16n8k16.row.col.f32.f16.f16.f32 "
        "{%0,%1,%2,%3}, {%4,%5,%6,%7}, {%8,%9}, {%0,%1,%2,%3};"
        : "+f"(c[0]), "+f"(c[1]), "+f"(c[2]), "+f"(c[3])
        : "r"(a[0]), "r"(a[1]), "r"(a[2]), "r"(a[3]), "r"(b0), "r"(b1));
}
__device__ __forceinline__ uint32_t pack_h2(float x, float y) {
    __half2 h = __floats2half2_rn(x, y);
    return *(uint32_t*)&h;
}
// XOR-swizzled smem address: 128 rows x 128B; chunk = 16B unit (0..7) within row.
// chunk' = chunk ^ (row & 7) — geometry validated in R9 (tf32 run, passed).
__device__ __forceinline__ uint32_t swz(uint32_t base, int row, int chunk) {
    return base + (uint32_t)row * 128u + ((uint32_t)(chunk ^ (row & 7)) << 4);
}

// ---------------- weight conversion: fp32 -> fp16 ----------------
__global__ void cvt_f16(const float4* __restrict__ src, uint2* __restrict__ dst, int n4) {
    for (int i = blockIdx.x * blockDim.x + threadIdx.x; i < n4; i += gridDim.x * blockDim.x) {
        float4 v = src[i];
        dst[i] = make_uint2(pack_h2(v.x, v.y), pack_h2(v.z, v.w));
    }
}

// ---------------- router stage 1: gate scores (16 tokens/block, rolled K-loop) ----
#define RTOK 16
#define RSTAGE_ITERS (RTOK * (H_ / 4) / 256)   // 16
__global__ __launch_bounds__(256) void score_kernel(const float* __restrict__ x,
                                                    const float* __restrict__ gate_w) {
    extern __shared__ float xs[];
    int tid = threadIdx.x, lane = tid & 31, w = tid >> 5;
    int tb = blockIdx.x * RTOK;

    const float4* xg = (const float4*)(x + (size_t)tb * H_);
    float4* xs4 = (float4*)xs;
    #pragma unroll
    for (int i = 0; i < RSTAGE_ITERS; i++) xs4[tid + i * 256] = xg[tid + i * 256];
    __syncthreads();

    #pragma unroll
    for (int j = 0; j < 4; j++) {
        int e = w * 4 + j;
        const float4* g4 = (const float4*)(gate_w + (size_t)e * H_);
        float acc[RTOK];
        #pragma unroll
        for (int t = 0; t < RTOK; t++) acc[t] = 0.f;
        for (int it = 0; it < 8; it++) {   // rolled: keep regs sane
            float4 gv = g4[it * 32 + lane];
            #pragma unroll
            for (int t = 0; t < RTOK; t++) {
                float4 xv = *(const float4*)&xs[t * H_ + (it * 32 + lane) * 4];
                acc[t] += gv.x * xv.x + gv.y * xv.y + gv.z * xv.z + gv.w * xv.w;
            }
        }
        #pragma unroll
        for (int t = 0; t < RTOK; t++) {
            float v = acc[t];
            #pragma unroll
            for (int o = 16; o; o >>= 1) v += __shfl_xor_sync(0xffffffffu, v, o);
            if (lane == 0) g_sc[(size_t)(tb + t) * E_ + e] = v;
        }
    }
}

// ---------------- router stage 2: top-k, register-only bitmask selection ----------------
__global__ __launch_bounds__(256) void route_kernel(const float* __restrict__ bias) {
    int t = blockIdx.x * blockDim.x + threadIdx.x;
    if (t >= T_) return;

    float s[E_], sfc[E_];
    #pragma unroll
    for (int e = 0; e < E_; e++) {
        float v = g_sc[(size_t)t * E_ + e];
        s[e]   = 1.f / (1.f + expf(-v));
        sfc[e] = s[e] + bias[e];
    }
    float gs[NGROUP];
    #pragma unroll
    for (int g = 0; g < NGROUP; g++) {
        float m1 = -1e30f, m2 = -1e30f;
        #pragma unroll
        for (int j = 0; j < 4; j++) {
            float v = sfc[g * 4 + j];
            if (v > m1) { m2 = m1; m1 = v; }
            else if (v > m2) m2 = v;
        }
        gs[g] = m1 + m2;
    }
    uint32_t gmask = 0;
    #pragma unroll
    for (int it = 0; it < TOPKG; it++) {
        float best = -1e30f; int bi = 0;
        #pragma unroll
        for (int g = 0; g < NGROUP; g++) {
            bool c = !((gmask >> g) & 1u) && gs[g] > best;
            if (c) { best = gs[g]; bi = g; }
        }
        gmask |= 1u << bi;
    }
    uint32_t emask = 0;
    int   sel[KSEL];
    float rw[KSEL];
    #pragma unroll
    for (int k = 0; k < KSEL; k++) {
        float best = -1e30f, braw = 0.f; int bi = 0;
        #pragma unroll
        for (int e = 0; e < E_; e++) {
            float v = ((gmask >> (e >> 2)) & 1u) ? sfc[e] : 0.f;
            bool c = !((emask >> e) & 1u) && v > best;
            if (c) { best = v; bi = e; braw = s[e]; }
        }
        emask |= 1u << bi;
        sel[k] = bi;
        rw[k]  = braw;
    }
    float inv = 1.f / (rw[0] + rw[1] + rw[2] + rw[3]);
    #pragma unroll
    for (int k = 0; k < KSEL; k++) {
        int a = t * KSEL + k;
        g_expi[a] = sel[k];
        g_gw[a]   = rw[k] * inv;
    }
}

// ---------------- deterministic slot assignment ----------------
__global__ __launch_bounds__(1024) void slot_kernel() {
    int e = blockIdx.x, tid = threadIdx.x;
    int lane = tid & 31, warp = tid >> 5;
    __shared__ int warp_sums[32];
    int base = 0;
    for (int c0 = 0; c0 < NASSIGN; c0 += 1024) {
        int a = c0 + tid;
        bool flag = (g_expi[a] == e);
        unsigned bal = __ballot_sync(0xffffffffu, flag);
        int wprefix = __popc(bal & ((1u << lane) - 1u));
        if (lane == 31) warp_sums[warp] = __popc(bal);
        __syncthreads();
        if (warp == 0) {
            int v = warp_sums[lane];
            #pragma unroll
            for (int o = 1; o < 32; o <<= 1) {
                int n = __shfl_up_sync(0xffffffffu, v, o);
                if (lane >= o) v += n;
            }
            warp_sums[lane] = v;
        }
        __syncthreads();
        int woff  = (warp == 0) ? 0 : warp_sums[warp - 1];
        int total = warp_sums[31];
        if (flag) {
            int slot = base + woff + wprefix;
            if (slot < CAP) {
                g_slot[a] = slot;
                g_tok[e * CAP + slot] = a >> 2;
            } else {
                g_slot[a] = -1;
            }
        }
        base += total;
        __syncthreads();
    }
    if (tid == 0) g_cnt[e] = base < CAP ? base : CAP;
}

// gather: token rows -> per-expert fp16 buffers
__global__ void gather_kernel(const float* __restrict__ x) {
    int e = blockIdx.y, slot = blockIdx.x;
    if (slot >= g_cnt[e]) return;
    int t = g_tok[e * CAP + slot];
    const float4* src = (const float4*)(x + (size_t)t * H_);
    uint2* dst = (uint2*)(g_bufh + ((size_t)e * CAP + slot) * H_);
    for (int i = threadIdx.x; i < H_ / 4; i += blockDim.x) {
        float4 v = src[i];
        dst[i] = make_uint2(pack_h2(v.x, v.y), pack_h2(v.z, v.w));
    }
}

// ---------------- GEMM common ----------------
#define PS      16384         // plane: 128 rows x 128B (64 fp16), XOR-swizzled
#define NSTG    3

// ---------------- GEMM1: h1/h3 fp16 + fused SiLU (BK=64 stages) ----------------
#define G1_STAGE  (3 * PS)           // 49152
#define G1_SMEM   (NSTG * G1_STAGE)  // 147456

__global__ __launch_bounds__(256) void gemm1_mma(void) {
    int e   = blockIdx.z;
    int cnt = g_cnt[e];
    int m0  = blockIdx.y * 128;
    if (m0 >= cnt) return;
    int n0  = blockIdx.x * 128;

    extern __shared__ char sm[];
    uint32_t sb = smem_u32(sm);
    int tid = threadIdx.x, lane = tid & 31, wid = tid >> 5;
    int wm = (wid & 1) * 64, wn = (wid >> 1) * 32;
    int g = lane >> 2, tg = lane & 3;
    int lane15 = lane & 15;
    int lchunk = lane >> 4;

    const __half* srcs[3] = {
        g_bufh + ((size_t)e * CAP  + m0) * H_,
        g_w1h  + ((size_t)e * IDIM + n0) * H_,
        g_w3h  + ((size_t)e * IDIM + n0) * H_
    };
    int lrow = tid >> 1;
    int half = tid & 1;

    // prologue: stages 0..1 (each stage = 64 K)
    #pragma unroll
    for (int st = 0; st < NSTG - 1; st++) {
        uint32_t s0 = sb + st * G1_STAGE;
        int k0 = st * 64;
        #pragma unroll
        for (int p = 0; p < 3; p++) {
            const __half* gp = srcs[p] + (size_t)lrow * H_ + k0;
            #pragma unroll
            for (int j = 0; j < 4; j++) {
                int ch = half * 4 + j;
                cp16(swz(s0 + p * PS, lrow, ch), gp + ch * 8);
            }
        }
        cp_commit();
    }

    float c1[4][4][4] = {}, c3[4][4][4] = {};

    const int NK = H_ / 64;  // 16
    for (int kt = 0; kt < NK; kt++) {
        cp_wait1();
        __syncthreads();
        if (kt + NSTG - 1 < NK) {
            uint32_t s0 = sb + ((kt + NSTG - 1) % NSTG) * G1_STAGE;
            int k0 = (kt + NSTG - 1) * 64;
            #pragma unroll
            for (int p = 0; p < 3; p++) {
                const __half* gp = srcs[p] + (size_t)lrow * H_ + k0;
                #pragma unroll
                for (int j = 0; j < 4; j++) {
                    int ch = half * 4 + j;
                    cp16(swz(s0 + p * PS, lrow, ch), gp + ch * 8);
                }
            }
        }
        cp_commit();

        uint32_t bs = sb + (kt % NSTG) * G1_STAGE;
        #pragma unroll
        for (int kb = 0; kb < 4; kb++) {
            int ch = kb * 2 + lchunk;
            uint32_t Af[4][4];
            #pragma unroll
            for (int mi = 0; mi < 4; mi++)
                LDSM4(Af[mi], swz(bs, wm + lane15 + mi * 16, ch));
            uint32_t t_[4], Bf[4][2];
            #pragma unroll
            for (int n2 = 0; n2 < 2; n2++) {
                LDSM4(t_, swz(bs + PS, wn + lane15 + n2 * 16, ch));
                Bf[2 * n2][0] = t_[0]; Bf[2 * n2][1] = t_[2];
                Bf[2 * n2 + 1][0] = t_[1]; Bf[2 * n2 + 1][1] = t_[3];
            }
            #pragma unroll
            for (int mi = 0; mi < 4; mi++)
                #pragma unroll
                for (int ni = 0; ni < 4; ni++)
                    mma_f16(c1[mi][ni], Af[mi], Bf[ni][0], Bf[ni][1]);
            #pragma unroll
            for (int n2 = 0; n2 < 2; n2++) {
                LDSM4(t_, swz(bs + 2 * PS, wn + lane15 + n2 * 16, ch));
                Bf[2 * n2][0] = t_[0]; Bf[2 * n2][1] = t_[2];
                Bf[2 * n2 + 1][0] = t_[1]; Bf[2 * n2 + 1][1] = t_[3];
            }
            #pragma unroll
            for (int mi = 0; mi < 4; mi++)
                #pragma unroll
                for (int ni = 0; ni < 4; ni++)
                    mma_f16(c3[mi][ni], Af[mi], Bf[ni][0], Bf[ni][1]);
        }
    }

    // epilogue: act = silu(h1)*h3 -> fp16
    #pragma unroll
    for (int mi = 0; mi < 4; mi++) {
        int r0 = m0 + wm + mi * 16 + g;
        #pragma unroll
        for (int ni = 0; ni < 4; ni++) {
            int cb = n0 + wn + ni * 8 + tg * 2;
            float h1a = c1[mi][ni][0], h1b = c1[mi][ni][1];
            float v0 = h1a / (1.f + expf(-h1a)) * c3[mi][ni][0];
            float v1 = h1b / (1.f + expf(-h1b)) * c3[mi][ni][1];
            float h1c = c1[mi][ni][2], h1d = c1[mi][ni][3];
            float v2 = h1c / (1.f + expf(-h1c)) * c3[mi][ni][2];
            float v3 = h1d / (1.f + expf(-h1d)) * c3[mi][ni][3];
            size_t o0 = ((size_t)e * CAP + r0) * IDIM + cb;
            *(uint32_t*)(g_acth + o0) = pack_h2(v0, v1);
            size_t o1 = ((size_t)e * CAP + r0 + 8) * IDIM + cb;
            *(uint32_t*)(g_acth + o1) = pack_h2(v2, v3);
        }
    }
}

// ---------------- GEMM2: y = act @ w2^T (BK=64, 2 CTAs/SM) ----------------
#define G2_STAGE  (2 * PS)           // 32768
#define G2_SMEM   (NSTG * G2_STAGE)  // 98304

__global__ __launch_bounds__(256, 2) void gemm2_mma(void) {
    int e   = blockIdx.z;
    int cnt = g_cnt[e];
    int m0  = blockIdx.y * 128;
    if (m0 >= cnt) return;
    int n0  = blockIdx.x * 128;

    extern __shared__ char sm[];
    uint32_t sb = smem_u32(sm);
    int tid = threadIdx.x, lane = tid & 31, wid = tid >> 5;
    int wm = (wid & 1) * 64, wn = (wid >> 1) * 32;
    int g = lane >> 2, tg = lane & 3;
    int lane15 = lane & 15;
    int lchunk = lane >> 4;

    const __half* srcs[2] = {
        g_acth + ((size_t)e * CAP + m0) * IDIM,
        g_w2h  + ((size_t)e * H_  + n0) * IDIM
    };
    int lrow = tid >> 1;
    int half = tid & 1;

    #pragma unroll
    for (int st = 0; st < NSTG - 1; st++) {
        uint32_t s0 = sb + st * G2_STAGE;
        int k0 = st * 64;
        #pragma unroll
        for (int p = 0; p < 2; p++) {
            const __half* gp = srcs[p] + (size_t)lrow * IDIM + k0;
            #pragma unroll
            for (int j = 0; j < 4; j++) {
                int ch = half * 4 + j;
                cp16(swz(s0 + p * PS, lrow, ch), gp + ch * 8);
            }
        }
        cp_commit();
    }

    float cc[4][4][4] = {};

    const int NK = IDIM / 64;  // 12
    for (int kt = 0; kt < NK; kt++) {
        cp_wait1();
        __syncthreads();
        if (kt + NSTG - 1 < NK) {
            uint32_t s0 = sb + ((kt + NSTG - 1) % NSTG) * G2_STAGE;
            int k0 = (kt + NSTG - 1) * 64;
            #pragma unroll
            for (int p = 0; p < 2; p++) {
                const __half* gp = srcs[p] + (size_t)lrow * IDIM + k0;
                #pragma unroll
                for (int j = 0; j < 4; j++) {
                    int ch = half * 4 + j;
                    cp16(swz(s0 + p * PS, lrow, ch), gp + ch * 8);
                }
            }
        }
        cp_commit();

        uint32_t bs = sb + (kt % NSTG) * G2_STAGE;
        #pragma unroll
        for (int kb = 0; kb < 4; kb++) {
            int ch = kb * 2 + lchunk;
            uint32_t Af[4][4];
            #pragma unroll
            for (int mi = 0; mi < 4; mi++)
                LDSM4(Af[mi], swz(bs, wm + lane15 + mi * 16, ch));
            uint32_t t_[4], Bf[4][2];
            #pragma unroll
            for (int n2 = 0; n2 < 2; n2++) {
                LDSM4(t_, swz(bs + PS, wn + lane15 + n2 * 16, ch));
                Bf[2 * n2][0] = t_[0]; Bf[2 * n2][1] = t_[2];
                Bf[2 * n2 + 1][0] = t_[1]; Bf[2 * n2 + 1][1] = t_[3];
            }
            #pragma unroll
            for (int mi = 0; mi < 4; mi++)
                #pragma unroll
                for (int ni = 0; ni < 4; ni++)
                    mma_f16(cc[mi][ni], Af[mi], Bf[ni][0], Bf[ni][1]);
        }
    }

    #pragma unroll
    for (int mi = 0; mi < 4; mi++) {
        int r0 = m0 + wm + mi * 16 + g;
        #pragma unroll
        for (int ni = 0; ni < 4; ni++) {
            int cb = n0 + wn + ni * 8 + tg * 2;
            *(float2*)(g_y + ((size_t)e * CAP + r0) * H_ + cb) =
                make_float2(cc[mi][ni][0], cc[mi][ni][1]);
            *(float2*)(g_y + ((size_t)e * CAP + r0 + 8) * H_ + cb) =
                make_float2(cc[mi][ni][2], cc[mi][ni][3]);
        }
    }
}

// ---------------- combine ----------------
__global__ void combine_kernel(float* __restrict__ out) {
    int t = blockIdx.x;
    int i = threadIdx.x;
    float4 acc = make_float4(0.f, 0.f, 0.f, 0.f);
    #pragma unroll
    for (int k = 0; k < KSEL; k++) {
        int a = t * KSEL + k;
        int slot = g_slot[a];
        if (slot < 0) continue;
        int e = g_expi[a];
        float w = g_gw[a];
        const float4* yr = (const float4*)(g_y + ((size_t)e * CAP + slot) * H_);
        float4 v = yr[i];
        acc.x += w * v.x; acc.y += w * v.y; acc.z += w * v.z; acc.w += w * v.w;
    }
    ((float4*)(out + (size_t)t * H_))[i] = acc;
}

// ---------------- launch ----------------
extern "C" void kernel_launch(void* const* d_in, const int* in_sizes, int n_in,
                              void* d_out, int out_size) {
    (void)in_sizes; (void)n_in; (void)out_size;
    const float* x      = (const float*)d_in[0];
    const float* gate_w = (const float*)d_in[1];
    const float* w1     = (const float*)d_in[2];
    const float* w3     = (const float*)d_in[3];
    const float* w2     = (const float*)d_in[4];
    const float* bias   = (const float*)d_in[5];
    float*       out    = (float*)d_out;

    const int RSMEM = RTOK * H_ * 4;
    cudaFuncSetAttribute(score_kernel, cudaFuncAttributeMaxDynamicSharedMemorySize, RSMEM);
    cudaFuncSetAttribute(gemm1_mma, cudaFuncAttributeMaxDynamicSharedMemorySize, G1_SMEM);
    cudaFuncSetAttribute(gemm2_mma, cudaFuncAttributeMaxDynamicSharedMemorySize, G2_SMEM);

    void *p_w1h, *p_w3h, *p_w2h;
    cudaGetSymbolAddress(&p_w1h, g_w1h);
    cudaGetSymbolAddress(&p_w3h, g_w3h);
    cudaGetSymbolAddress(&p_w2h, g_w2h);

    const int n4 = E_ * IDIM * H_ / 4;
    cvt_f16<<<4096, 256>>>((const float4*)w1, (uint2*)p_w1h, n4);
    cvt_f16<<<4096, 256>>>((const float4*)w3, (uint2*)p_w3h, n4);
    cvt_f16<<<4096, 256>>>((const float4*)w2, (uint2*)p_w2h, n4);

    score_kernel<<<T_ / RTOK, 256, RSMEM>>>(x, gate_w);
    route_kernel<<<T_ / 256, 256>>>(bias);
    slot_kernel<<<E_, 1024>>>();
    gather_kernel<<<dim3(CAP, E_), 256>>>(x);
    gemm1_mma<<<dim3(IDIM / 128, CAP / 128, E_), 256, G1_SMEM>>>();
    gemm2_mma<<<dim3(H_ / 128, CAP / 128, E_), 256, G2_SMEM>>>();
    combine_kernel<<<T_, 256>>>(out);
}

// round 13
// speedup vs baseline: 2.7115x; 1.0167x over previous
#include <cuda_runtime.h>
#include <cuda_fp16.h>
#include <math.h>
#include <stdint.h>

#define E_      32
#define KSEL    4
#define H_      1024
#define IDIM    768
#define T_      4096
#define NGROUP  8
#define TOPKG   4
#define CAP     1024
#define NASSIGN (T_ * KSEL)

// ---------------- scratch (device globals; no allocations) ----------------
__device__ __half g_bufh[(size_t)E_ * CAP * H_];    // gathered tokens (fp16)
__device__ __half g_acth[(size_t)E_ * CAP * IDIM];  // act (fp16; |act|<~16k, fits)
__device__ __half g_w1h[(size_t)E_ * IDIM * H_];
__device__ __half g_w3h[(size_t)E_ * IDIM * H_];
__device__ __half g_w2h[(size_t)E_ * H_ * IDIM];
__device__ float  g_y[(size_t)E_ * CAP * H_];       // fp32: |y| reaches ~1e6 (no-cancel sums)
__device__ float  g_sc[(size_t)T_ * E_];
__device__ int    g_cnt [E_];
__device__ int    g_tok [E_ * CAP];
__device__ int    g_expi[NASSIGN];
__device__ int    g_slot[NASSIGN];
__device__ float  g_gw  [NASSIGN];

// ---------------- helpers ----------------
__device__ __forceinline__ uint32_t smem_u32(const void* p) {
    uint32_t a;
    asm("{ .reg .u64 t; cvta.to.shared.u64 t, %1; cvt.u32.u64 %0, t; }" : "=r"(a) : "l"(p));
    return a;
}
__device__ __forceinline__ void cp16(uint32_t dst, const void* src) {
    asm volatile("cp.async.cg.shared.global [%0], [%1], 16;" :: "r"(dst), "l"(src));
}
__device__ __forceinline__ void cp_commit() { asm volatile("cp.async.commit_group;"); }
__device__ __forceinline__ void cp_wait1()  { asm volatile("cp.async.wait_group 1;"); }
#define LDSM4(r, a) \
    asm volatile("ldmatrix.sync.aligned.m8n8.x4.shared.b16 {%0,%1,%2,%3}, [%4];" \
        : "=r"((r)[0]), "=r"((r)[1]), "=r"((r)[2]), "=r"((r)[3]) : "r"(a))
__device__ __forceinline__ void mma_f16(float* c, const uint32_t* a, uint32_t b0, uint32_t b1) {
    asm volatile(
        "mma.sync.aligned.m16n8k16.row.col.f32.f16.f16.f32 "
        "{%0,%1,%2,%3}, {%4,%5,%6,%7}, {%8,%9}, {%0,%1,%2,%3};"
        : "+f"(c[0]), "+f"(c[1]), "+f"(c[2]), "+f"(c[3])
        : "r"(a[0]), "r"(a[1]), "r"(a[2]), "r"(a[3]), "r"(b0), "r"(b1));
}
__device__ __forceinline__ uint32_t pack_h2(float x, float y) {
    __half2 h = __floats2half2_rn(x, y);
    return *(uint32_t*)&h;
}
// XOR-swizzled smem address: 128 rows x 128B; chunk = 16B unit (0..7) within row.
__device__ __forceinline__ uint32_t swz(uint32_t base, int row, int chunk) {
    return base + (uint32_t)row * 128u + ((uint32_t)(chunk ^ (row & 7)) << 4);
}

// ---------------- fused weight conversion: w1, w3, w2 in ONE launch ----------------
__global__ void cvt_all(const float4* __restrict__ w1, const float4* __restrict__ w3,
                        const float4* __restrict__ w2,
                        uint2* __restrict__ o1, uint2* __restrict__ o3,
                        uint2* __restrict__ o2, int n4) {
    int stride = gridDim.x * blockDim.x;
    for (int i = blockIdx.x * blockDim.x + threadIdx.x; i < n4; i += stride) {
        float4 v = w1[i];
        o1[i] = make_uint2(pack_h2(v.x, v.y), pack_h2(v.z, v.w));
    }
    for (int i = blockIdx.x * blockDim.x + threadIdx.x; i < n4; i += stride) {
        float4 v = w3[i];
        o3[i] = make_uint2(pack_h2(v.x, v.y), pack_h2(v.z, v.w));
    }
    for (int i = blockIdx.x * blockDim.x + threadIdx.x; i < n4; i += stride) {
        float4 v = w2[i];
        o2[i] = make_uint2(pack_h2(v.x, v.y), pack_h2(v.z, v.w));
    }
}

// ---------------- router stage 1: gate scores (16 tokens/block, rolled K-loop) ----
#define RTOK 16
#define RSTAGE_ITERS (RTOK * (H_ / 4) / 256)
__global__ __launch_bounds__(256) void score_kernel(const float* __restrict__ x,
                                                    const float* __restrict__ gate_w) {
    extern __shared__ float xs[];
    int tid = threadIdx.x, lane = tid & 31, w = tid >> 5;
    int tb = blockIdx.x * RTOK;

    const float4* xg = (const float4*)(x + (size_t)tb * H_);
    float4* xs4 = (float4*)xs;
    #pragma unroll
    for (int i = 0; i < RSTAGE_ITERS; i++) xs4[tid + i * 256] = xg[tid + i * 256];
    __syncthreads();

    #pragma unroll
    for (int j = 0; j < 4; j++) {
        int e = w * 4 + j;
        const float4* g4 = (const float4*)(gate_w + (size_t)e * H_);
        float acc[RTOK];
        #pragma unroll
        for (int t = 0; t < RTOK; t++) acc[t] = 0.f;
        for (int it = 0; it < 8; it++) {
            float4 gv = g4[it * 32 + lane];
            #pragma unroll
            for (int t = 0; t < RTOK; t++) {
                float4 xv = *(const float4*)&xs[t * H_ + (it * 32 + lane) * 4];
                acc[t] += gv.x * xv.x + gv.y * xv.y + gv.z * xv.z + gv.w * xv.w;
            }
        }
        #pragma unroll
        for (int t = 0; t < RTOK; t++) {
            float v = acc[t];
            #pragma unroll
            for (int o = 16; o; o >>= 1) v += __shfl_xor_sync(0xffffffffu, v, o);
            if (lane == 0) g_sc[(size_t)(tb + t) * E_ + e] = v;
        }
    }
}

// ---------------- router stage 2: top-k, register-only bitmask selection ----------------
__global__ __launch_bounds__(256) void route_kernel(const float* __restrict__ bias) {
    int t = blockIdx.x * blockDim.x + threadIdx.x;
    if (t >= T_) return;

    float s[E_], sfc[E_];
    #pragma unroll
    for (int e = 0; e < E_; e++) {
        float v = g_sc[(size_t)t * E_ + e];
        s[e]   = 1.f / (1.f + expf(-v));
        sfc[e] = s[e] + bias[e];
    }
    float gs[NGROUP];
    #pragma unroll
    for (int g = 0; g < NGROUP; g++) {
        float m1 = -1e30f, m2 = -1e30f;
        #pragma unroll
        for (int j = 0; j < 4; j++) {
            float v = sfc[g * 4 + j];
            if (v > m1) { m2 = m1; m1 = v; }
            else if (v > m2) m2 = v;
        }
        gs[g] = m1 + m2;
    }
    uint32_t gmask = 0;
    #pragma unroll
    for (int it = 0; it < TOPKG; it++) {
        float best = -1e30f; int bi = 0;
        #pragma unroll
        for (int g = 0; g < NGROUP; g++) {
            bool c = !((gmask >> g) & 1u) && gs[g] > best;
            if (c) { best = gs[g]; bi = g; }
        }
        gmask |= 1u << bi;
    }
    uint32_t emask = 0;
    int   sel[KSEL];
    float rw[KSEL];
    #pragma unroll
    for (int k = 0; k < KSEL; k++) {
        float best = -1e30f, braw = 0.f; int bi = 0;
        #pragma unroll
        for (int e = 0; e < E_; e++) {
            float v = ((gmask >> (e >> 2)) & 1u) ? sfc[e] : 0.f;
            bool c = !((emask >> e) & 1u) && v > best;
            if (c) { best = v; bi = e; braw = s[e]; }
        }
        emask |= 1u << bi;
        sel[k] = bi;
        rw[k]  = braw;
    }
    float inv = 1.f / (rw[0] + rw[1] + rw[2] + rw[3]);
    #pragma unroll
    for (int k = 0; k < KSEL; k++) {
        int a = t * KSEL + k;
        g_expi[a] = sel[k];
        g_gw[a]   = rw[k] * inv;
    }
}

// ---------------- deterministic slot assignment ----------------
__global__ __launch_bounds__(1024) void slot_kernel() {
    int e = blockIdx.x, tid = threadIdx.x;
    int lane = tid & 31, warp = tid >> 5;
    __shared__ int warp_sums[32];
    int base = 0;
    for (int c0 = 0; c0 < NASSIGN; c0 += 1024) {
        int a = c0 + tid;
        bool flag = (g_expi[a] == e);
        unsigned bal = __ballot_sync(0xffffffffu, flag);
        int wprefix = __popc(bal & ((1u << lane) - 1u));
        if (lane == 31) warp_sums[warp] = __popc(bal);
        __syncthreads();
        if (warp == 0) {
            int v = warp_sums[lane];
            #pragma unroll
            for (int o = 1; o < 32; o <<= 1) {
                int n = __shfl_up_sync(0xffffffffu, v, o);
                if (lane >= o) v += n;
            }
            warp_sums[lane] = v;
        }
        __syncthreads();
        int woff  = (warp == 0) ? 0 : warp_sums[warp - 1];
        int total = warp_sums[31];
        if (flag) {
            int slot = base + woff + wprefix;
            if (slot < CAP) {
                g_slot[a] = slot;
                g_tok[e * CAP + slot] = a >> 2;
            } else {
                g_slot[a] = -1;
            }
        }
        base += total;
        __syncthreads();
    }
    if (tid == 0) g_cnt[e] = base < CAP ? base : CAP;
}

// gather: token rows -> per-expert fp16 buffers
__global__ void gather_kernel(const float* __restrict__ x) {
    int e = blockIdx.y, slot = blockIdx.x;
    if (slot >= g_cnt[e]) return;
    int t = g_tok[e * CAP + slot];
    const float4* src = (const float4*)(x + (size_t)t * H_);
    uint2* dst = (uint2*)(g_bufh + ((size_t)e * CAP + slot) * H_);
    for (int i = threadIdx.x; i < H_ / 4; i += blockDim.x) {
        float4 v = src[i];
        dst[i] = make_uint2(pack_h2(v.x, v.y), pack_h2(v.z, v.w));
    }
}

// ---------------- GEMM common ----------------
#define PS      16384         // plane: 128 rows x 128B (64 fp16), XOR-swizzled
#define NSTG    3

// ---------------- GEMM1: h1/h3 fp16 + fused SiLU (BK=64 stages) ----------------
#define G1_STAGE  (3 * PS)           // 49152
#define G1_SMEM   (NSTG * G1_STAGE)  // 147456

__global__ __launch_bounds__(256) void gemm1_mma(void) {
    int e   = blockIdx.z;
    int cnt = g_cnt[e];
    int m0  = blockIdx.y * 128;
    if (m0 >= cnt) return;
    int n0  = blockIdx.x * 128;

    extern __shared__ char sm[];
    uint32_t sb = smem_u32(sm);
    int tid = threadIdx.x, lane = tid & 31, wid = tid >> 5;
    int wm = (wid & 1) * 64, wn = (wid >> 1) * 32;
    int g = lane >> 2, tg = lane & 3;
    int lane15 = lane & 15;
    int lchunk = lane >> 4;

    const __half* srcs[3] = {
        g_bufh + ((size_t)e * CAP  + m0) * H_,
        g_w1h  + ((size_t)e * IDIM + n0) * H_,
        g_w3h  + ((size_t)e * IDIM + n0) * H_
    };
    int lrow = tid >> 1;
    int half = tid & 1;

    #pragma unroll
    for (int st = 0; st < NSTG - 1; st++) {
        uint32_t s0 = sb + st * G1_STAGE;
        int k0 = st * 64;
        #pragma unroll
        for (int p = 0; p < 3; p++) {
            const __half* gp = srcs[p] + (size_t)lrow * H_ + k0;
            #pragma unroll
            for (int j = 0; j < 4; j++) {
                int ch = half * 4 + j;
                cp16(swz(s0 + p * PS, lrow, ch), gp + ch * 8);
            }
        }
        cp_commit();
    }

    float c1[4][4][4] = {}, c3[4][4][4] = {};

    const int NK = H_ / 64;  // 16
    for (int kt = 0; kt < NK; kt++) {
        cp_wait1();
        __syncthreads();
        if (kt + NSTG - 1 < NK) {
            uint32_t s0 = sb + ((kt + NSTG - 1) % NSTG) * G1_STAGE;
            int k0 = (kt + NSTG - 1) * 64;
            #pragma unroll
            for (int p = 0; p < 3; p++) {
                const __half* gp = srcs[p] + (size_t)lrow * H_ + k0;
                #pragma unroll
                for (int j = 0; j < 4; j++) {
                    int ch = half * 4 + j;
                    cp16(swz(s0 + p * PS, lrow, ch), gp + ch * 8);
                }
            }
        }
        cp_commit();

        uint32_t bs = sb + (kt % NSTG) * G1_STAGE;
        #pragma unroll
        for (int kb = 0; kb < 4; kb++) {
            int ch = kb * 2 + lchunk;
            uint32_t Af[4][4];
            #pragma unroll
            for (int mi = 0; mi < 4; mi++)
                LDSM4(Af[mi], swz(bs, wm + lane15 + mi * 16, ch));
            uint32_t t_[4], Bf[4][2];
            #pragma unroll
            for (int n2 = 0; n2 < 2; n2++) {
                LDSM4(t_, swz(bs + PS, wn + lane15 + n2 * 16, ch));
                Bf[2 * n2][0] = t_[0]; Bf[2 * n2][1] = t_[2];
                Bf[2 * n2 + 1][0] = t_[1]; Bf[2 * n2 + 1][1] = t_[3];
            }
            #pragma unroll
            for (int mi = 0; mi < 4; mi++)
                #pragma unroll
                for (int ni = 0; ni < 4; ni++)
                    mma_f16(c1[mi][ni], Af[mi], Bf[ni][0], Bf[ni][1]);
            #pragma unroll
            for (int n2 = 0; n2 < 2; n2++) {
                LDSM4(t_, swz(bs + 2 * PS, wn + lane15 + n2 * 16, ch));
                Bf[2 * n2][0] = t_[0]; Bf[2 * n2][1] = t_[2];
                Bf[2 * n2 + 1][0] = t_[1]; Bf[2 * n2 + 1][1] = t_[3];
            }
            #pragma unroll
            for (int mi = 0; mi < 4; mi++)
                #pragma unroll
                for (int ni = 0; ni < 4; ni++)
                    mma_f16(c3[mi][ni], Af[mi], Bf[ni][0], Bf[ni][1]);
        }
    }

    // epilogue: act = silu(h1)*h3 -> fp16
    #pragma unroll
    for (int mi = 0; mi < 4; mi++) {
        int r0 = m0 + wm + mi * 16 + g;
        #pragma unroll
        for (int ni = 0; ni < 4; ni++) {
            int cb = n0 + wn + ni * 8 + tg * 2;
            float h1a = c1[mi][ni][0], h1b = c1[mi][ni][1];
            float v0 = h1a / (1.f + expf(-h1a)) * c3[mi][ni][0];
            float v1 = h1b / (1.f + expf(-h1b)) * c3[mi][ni][1];
            float h1c = c1[mi][ni][2], h1d = c1[mi][ni][3];
            float v2 = h1c / (1.f + expf(-h1c)) * c3[mi][ni][2];
            float v3 = h1d / (1.f + expf(-h1d)) * c3[mi][ni][3];
            size_t o0 = ((size_t)e * CAP + r0) * IDIM + cb;
            *(uint32_t*)(g_acth + o0) = pack_h2(v0, v1);
            size_t o1 = ((size_t)e * CAP + r0 + 8) * IDIM + cb;
            *(uint32_t*)(g_acth + o1) = pack_h2(v2, v3);
        }
    }
}

// ---------------- GEMM2: y = act @ w2^T (BK=64, 2 CTAs/SM), fp32 output ----------------
#define G2_STAGE  (2 * PS)           // 32768
#define G2_SMEM   (NSTG * G2_STAGE)  // 98304

__global__ __launch_bounds__(256, 2) void gemm2_mma(void) {
    int e   = blockIdx.z;
    int cnt = g_cnt[e];
    int m0  = blockIdx.y * 128;
    if (m0 >= cnt) return;
    int n0  = blockIdx.x * 128;

    extern __shared__ char sm[];
    uint32_t sb = smem_u32(sm);
    int tid = threadIdx.x, lane = tid & 31, wid = tid >> 5;
    int wm = (wid & 1) * 64, wn = (wid >> 1) * 32;
    int g = lane >> 2, tg = lane & 3;
    int lane15 = lane & 15;
    int lchunk = lane >> 4;

    const __half* srcs[2] = {
        g_acth + ((size_t)e * CAP + m0) * IDIM,
        g_w2h  + ((size_t)e * H_  + n0) * IDIM
    };
    int lrow = tid >> 1;
    int half = tid & 1;

    #pragma unroll
    for (int st = 0; st < NSTG - 1; st++) {
        uint32_t s0 = sb + st * G2_STAGE;
        int k0 = st * 64;
        #pragma unroll
        for (int p = 0; p < 2; p++) {
            const __half* gp = srcs[p] + (size_t)lrow * IDIM + k0;
            #pragma unroll
            for (int j = 0; j < 4; j++) {
                int ch = half * 4 + j;
                cp16(swz(s0 + p * PS, lrow, ch), gp + ch * 8);
            }
        }
        cp_commit();
    }

    float cc[4][4][4] = {};

    const int NK = IDIM / 64;  // 12
    for (int kt = 0; kt < NK; kt++) {
        cp_wait1();
        __syncthreads();
        if (kt + NSTG - 1 < NK) {
            uint32_t s0 = sb + ((kt + NSTG - 1) % NSTG) * G2_STAGE;
            int k0 = (kt + NSTG - 1) * 64;
            #pragma unroll
            for (int p = 0; p < 2; p++) {
                const __half* gp = srcs[p] + (size_t)lrow * IDIM + k0;
                #pragma unroll
                for (int j = 0; j < 4; j++) {
                    int ch = half * 4 + j;
                    cp16(swz(s0 + p * PS, lrow, ch), gp + ch * 8);
                }
            }
        }
        cp_commit();

        uint32_t bs = sb + (kt % NSTG) * G2_STAGE;
        #pragma unroll
        for (int kb = 0; kb < 4; kb++) {
            int ch = kb * 2 + lchunk;
            uint32_t Af[4][4];
            #pragma unroll
            for (int mi = 0; mi < 4; mi++)
                LDSM4(Af[mi], swz(bs, wm + lane15 + mi * 16, ch));
            uint32_t t_[4], Bf[4][2];
            #pragma unroll
            for (int n2 = 0; n2 < 2; n2++) {
                LDSM4(t_, swz(bs + PS, wn + lane15 + n2 * 16, ch));
                Bf[2 * n2][0] = t_[0]; Bf[2 * n2][1] = t_[2];
                Bf[2 * n2 + 1][0] = t_[1]; Bf[2 * n2 + 1][1] = t_[3];
            }
            #pragma unroll
            for (int mi = 0; mi < 4; mi++)
                #pragma unroll
                for (int ni = 0; ni < 4; ni++)
                    mma_f16(cc[mi][ni], Af[mi], Bf[ni][0], Bf[ni][1]);
        }
    }

    #pragma unroll
    for (int mi = 0; mi < 4; mi++) {
        int r0 = m0 + wm + mi * 16 + g;
        #pragma unroll
        for (int ni = 0; ni < 4; ni++) {
            int cb = n0 + wn + ni * 8 + tg * 2;
            *(float2*)(g_y + ((size_t)e * CAP + r0) * H_ + cb) =
                make_float2(cc[mi][ni][0], cc[mi][ni][1]);
            *(float2*)(g_y + ((size_t)e * CAP + r0 + 8) * H_ + cb) =
                make_float2(cc[mi][ni][2], cc[mi][ni][3]);
        }
    }
}

// ---------------- combine: fp32 y -> fp32 out ----------------
__global__ void combine_kernel(float* __restrict__ out) {
    int t = blockIdx.x;
    int i = threadIdx.x;
    float4 acc = make_float4(0.f, 0.f, 0.f, 0.f);
    #pragma unroll
    for (int k = 0; k < KSEL; k++) {
        int a = t * KSEL + k;
        int slot = g_slot[a];
        if (slot < 0) continue;
        int e = g_expi[a];
        float w = g_gw[a];
        const float4* yr = (const float4*)(g_y + ((size_t)e * CAP + slot) * H_);
        float4 v = yr[i];
        acc.x += w * v.x; acc.y += w * v.y; acc.z += w * v.z; acc.w += w * v.w;
    }
    ((float4*)(out + (size_t)t * H_))[i] = acc;
}

// ---------------- launch ----------------
extern "C" void kernel_launch(void* const* d_in, const int* in_sizes, int n_in,
                              void* d_out, int out_size) {
    (void)in_sizes; (void)n_in; (void)out_size;
    const float* x      = (const float*)d_in[0];
    const float* gate_w = (const float*)d_in[1];
    const float* w1     = (const float*)d_in[2];
    const float* w3     = (const float*)d_in[3];
    const float* w2     = (const float*)d_in[4];
    const float* bias   = (const float*)d_in[5];
    float*       out    = (float*)d_out;

    const int RSMEM = RTOK * H_ * 4;
    cudaFuncSetAttribute(score_kernel, cudaFuncAttributeMaxDynamicSharedMemorySize, RSMEM);
    cudaFuncSetAttribute(gemm1_mma, cudaFuncAttributeMaxDynamicSharedMemorySize, G1_SMEM);
    cudaFuncSetAttribute(gemm2_mma, cudaFuncAttributeMaxDynamicSharedMemorySize, G2_SMEM);

    void *p_w1h, *p_w3h, *p_w2h;
    cudaGetSymbolAddress(&p_w1h, g_w1h);
    cudaGetSymbolAddress(&p_w3h, g_w3h);
    cudaGetSymbolAddress(&p_w2h, g_w2h);

    const int n4 = E_ * IDIM * H_ / 4;
    cvt_all<<<4096, 256>>>((const float4*)w1, (const float4*)w3, (const float4*)w2,
                           (uint2*)p_w1h, (uint2*)p_w3h, (uint2*)p_w2h, n4);  // #1

    score_kernel<<<T_ / RTOK, 256, RSMEM>>>(x, gate_w);        // #2
    route_kernel<<<T_ / 256, 256>>>(bias);                     // #3
    slot_kernel<<<E_, 1024>>>();                               // #4
    gather_kernel<<<dim3(CAP, E_), 256>>>(x);                  // #5
    gemm1_mma<<<dim3(IDIM / 128, CAP / 128, E_), 256, G1_SMEM>>>();  // #6 <- ncu window
    gemm2_mma<<<dim3(H_ / 128, CAP / 128, E_), 256, G2_SMEM>>>();    // #7
    combine_kernel<<<T_, 256>>>(out);                          // #8
}

// round 14
// speedup vs baseline: 2.7999x; 1.0326x over previous
#include <cuda_runtime.h>
#include <cuda_fp16.h>
#include <math.h>
#include <stdint.h>

#define E_      32
#define KSEL    4
#define H_      1024
#define IDIM    768
#define T_      4096
#define NGROUP  8
#define TOPKG   4
#define CAP     1024
#define NASSIGN (T_ * KSEL)

// ---------------- scratch (device globals; no allocations) ----------------
__device__ __half g_bufh[(size_t)E_ * CAP * H_];
__device__ __half g_acth[(size_t)E_ * CAP * IDIM];
__device__ __half g_w1h[(size_t)E_ * IDIM * H_];
__device__ __half g_w3h[(size_t)E_ * IDIM * H_];
__device__ __half g_w2h[(size_t)E_ * H_ * IDIM];
__device__ float  g_y[(size_t)E_ * CAP * H_];       // fp32: |y| reaches ~1e6
__device__ float  g_sc[(size_t)T_ * E_];
__device__ int    g_cnt [E_];
__device__ int    g_tok [E_ * CAP];
__device__ int    g_expi[NASSIGN];
__device__ int    g_slot[NASSIGN];
__device__ float  g_gw  [NASSIGN];

// ---------------- helpers ----------------
__device__ __forceinline__ uint32_t smem_u32(const void* p) {
    uint32_t a;
    asm("{ .reg .u64 t; cvta.to.shared.u64 t, %1; cvt.u32.u64 %0, t; }" : "=r"(a) : "l"(p));
    return a;
}
__device__ __forceinline__ void cp16(uint32_t dst, const void* src) {
    asm volatile("cp.async.cg.shared.global [%0], [%1], 16;" :: "r"(dst), "l"(src));
}
__device__ __forceinline__ void cp_commit() { asm volatile("cp.async.commit_group;"); }
__device__ __forceinline__ void cp_wait1()  { asm volatile("cp.async.wait_group 1;"); }
#define LDSM4(r, a) \
    asm volatile("ldmatrix.sync.aligned.m8n8.x4.shared.b16 {%0,%1,%2,%3}, [%4];" \
        : "=r"((r)[0]), "=r"((r)[1]), "=r"((r)[2]), "=r"((r)[3]) : "r"(a))
__device__ __forceinline__ void mma_f16(float* c, const uint32_t* a, uint32_t b0, uint32_t b1) {
    asm volatile(
        "mma.sync.aligned.m16n8k16.row.col.f32.f16.f16.f32 "
        "{%0,%1,%2,%3}, {%4,%5,%6,%7}, {%8,%9}, {%0,%1,%2,%3};"
        : "+f"(c[0]), "+f"(c[1]), "+f"(c[2]), "+f"(c[3])
        : "r"(a[0]), "r"(a[1]), "r"(a[2]), "r"(a[3]), "r"(b0), "r"(b1));
}
__device__ __forceinline__ uint32_t pack_h2(float x, float y) {
    __half2 h = __floats2half2_rn(x, y);
    return *(uint32_t*)&h;
}
__device__ __forceinline__ uint32_t swz(uint32_t base, int row, int chunk) {
    return base + (uint32_t)row * 128u + ((uint32_t)(chunk ^ (row & 7)) << 4);
}

// ---------------- merged kernel: score (blocks 0..255) + weight cvt (blocks 256+) ----
#define RTOK 16
#define SCORE_BLKS (T_ / RTOK)      // 256
#define CVT_BLKS   2048
__global__ __launch_bounds__(256) void cvt_score(
    const float* __restrict__ x, const float* __restrict__ gate_w,
    const float4* __restrict__ w1, const float4* __restrict__ w3,
    const float4* __restrict__ w2,
    uint2* __restrict__ o1, uint2* __restrict__ o3, uint2* __restrict__ o2, int n4) {
    int tid = threadIdx.x;
    if (blockIdx.x < SCORE_BLKS) {
        // ----- gate scores: 16 tokens/block -----
        extern __shared__ float xs[];
        int lane = tid & 31, w = tid >> 5;
        int tb = blockIdx.x * RTOK;
        const float4* xg = (const float4*)(x + (size_t)tb * H_);
        float4* xs4 = (float4*)xs;
        #pragma unroll
        for (int i = 0; i < RTOK * (H_ / 4) / 256; i++) xs4[tid + i * 256] = xg[tid + i * 256];
        __syncthreads();
        #pragma unroll
        for (int j = 0; j < 4; j++) {
            int e = w * 4 + j;
            const float4* g4 = (const float4*)(gate_w + (size_t)e * H_);
            float acc[RTOK];
            #pragma unroll
            for (int t = 0; t < RTOK; t++) acc[t] = 0.f;
            for (int it = 0; it < 8; it++) {
                float4 gv = g4[it * 32 + lane];
                #pragma unroll
                for (int t = 0; t < RTOK; t++) {
                    float4 xv = *(const float4*)&xs[t * H_ + (it * 32 + lane) * 4];
                    acc[t] += gv.x * xv.x + gv.y * xv.y + gv.z * xv.z + gv.w * xv.w;
                }
            }
            #pragma unroll
            for (int t = 0; t < RTOK; t++) {
                float v = acc[t];
                #pragma unroll
                for (int o = 16; o; o >>= 1) v += __shfl_xor_sync(0xffffffffu, v, o);
                if (lane == 0) g_sc[(size_t)(tb + t) * E_ + e] = v;
            }
        }
    } else {
        // ----- weight conversion fp32 -> fp16 (DRAM-bound; overlaps with score) -----
        int b = blockIdx.x - SCORE_BLKS;
        int stride = CVT_BLKS * 256;
        for (int i = b * 256 + tid; i < n4; i += stride) {
            float4 v = w1[i];
            o1[i] = make_uint2(pack_h2(v.x, v.y), pack_h2(v.z, v.w));
        }
        for (int i = b * 256 + tid; i < n4; i += stride) {
            float4 v = w3[i];
            o3[i] = make_uint2(pack_h2(v.x, v.y), pack_h2(v.z, v.w));
        }
        for (int i = b * 256 + tid; i < n4; i += stride) {
            float4 v = w2[i];
            o2[i] = make_uint2(pack_h2(v.x, v.y), pack_h2(v.z, v.w));
        }
    }
}

// ---------------- router stage 2: top-k, register-only bitmask selection ----------------
__global__ __launch_bounds__(256) void route_kernel(const float* __restrict__ bias) {
    int t = blockIdx.x * blockDim.x + threadIdx.x;
    if (t >= T_) return;

    float s[E_], sfc[E_];
    #pragma unroll
    for (int e = 0; e < E_; e++) {
        float v = g_sc[(size_t)t * E_ + e];
        s[e]   = 1.f / (1.f + expf(-v));
        sfc[e] = s[e] + bias[e];
    }
    float gs[NGROUP];
    #pragma unroll
    for (int g = 0; g < NGROUP; g++) {
        float m1 = -1e30f, m2 = -1e30f;
        #pragma unroll
        for (int j = 0; j < 4; j++) {
            float v = sfc[g * 4 + j];
            if (v > m1) { m2 = m1; m1 = v; }
            else if (v > m2) m2 = v;
        }
        gs[g] = m1 + m2;
    }
    uint32_t gmask = 0;
    #pragma unroll
    for (int it = 0; it < TOPKG; it++) {
        float best = -1e30f; int bi = 0;
        #pragma unroll
        for (int g = 0; g < NGROUP; g++) {
            bool c = !((gmask >> g) & 1u) && gs[g] > best;
            if (c) { best = gs[g]; bi = g; }
        }
        gmask |= 1u << bi;
    }
    uint32_t emask = 0;
    int   sel[KSEL];
    float rw[KSEL];
    #pragma unroll
    for (int k = 0; k < KSEL; k++) {
        float best = -1e30f, braw = 0.f; int bi = 0;
        #pragma unroll
        for (int e = 0; e < E_; e++) {
            float v = ((gmask >> (e >> 2)) & 1u) ? sfc[e] : 0.f;
            bool c = !((emask >> e) & 1u) && v > best;
            if (c) { best = v; bi = e; braw = s[e]; }
        }
        emask |= 1u << bi;
        sel[k] = bi;
        rw[k]  = braw;
    }
    float inv = 1.f / (rw[0] + rw[1] + rw[2] + rw[3]);
    #pragma unroll
    for (int k = 0; k < KSEL; k++) {
        int a = t * KSEL + k;
        g_expi[a] = sel[k];
        g_gw[a]   = rw[k] * inv;
    }
}

// ---------------- slot: single-pass scan (16 assignments/thread, 2 syncs total) ----
__global__ __launch_bounds__(1024) void slot_kernel() {
    int e = blockIdx.x, tid = threadIdx.x;
    int lane = tid & 31, warp = tid >> 5;
    __shared__ int wsum[32];

    int a0 = tid * 16;
    int ex[16];
    int cnt = 0;
    #pragma unroll
    for (int j = 0; j < 16; j++) {
        ex[j] = g_expi[a0 + j];
        cnt += (ex[j] == e);
    }
    // block-wide exclusive prefix of cnt (thread order == assignment order)
    int inc = cnt;
    #pragma unroll
    for (int o = 1; o < 32; o <<= 1) {
        int n = __shfl_up_sync(0xffffffffu, inc, o);
        if (lane >= o) inc += n;
    }
    if (lane == 31) wsum[warp] = inc;
    __syncthreads();
    if (warp == 0) {
        int v = wsum[lane];
        #pragma unroll
        for (int o = 1; o < 32; o <<= 1) {
            int n = __shfl_up_sync(0xffffffffu, v, o);
            if (lane >= o) v += n;
        }
        wsum[lane] = v;
    }
    __syncthreads();
    int woff  = (warp == 0) ? 0 : wsum[warp - 1];
    int start = woff + inc - cnt;   // exclusive prefix for this thread's chunk
    #pragma unroll
    for (int j = 0; j < 16; j++) {
        if (ex[j] == e) {
            int a = a0 + j;
            if (start < CAP) {
                g_slot[a] = start;
                g_tok[e * CAP + start] = a >> 2;
            } else {
                g_slot[a] = -1;
            }
            start++;
        }
    }
    if (tid == 1023) g_cnt[e] = (woff + inc) < CAP ? (woff + inc) : CAP;
}

// gather: token rows -> per-expert fp16 buffers
__global__ void gather_kernel(const float* __restrict__ x) {
    int e = blockIdx.y, slot = blockIdx.x;
    if (slot >= g_cnt[e]) return;
    int t = g_tok[e * CAP + slot];
    const float4* src = (const float4*)(x + (size_t)t * H_);
    uint2* dst = (uint2*)(g_bufh + ((size_t)e * CAP + slot) * H_);
    for (int i = threadIdx.x; i < H_ / 4; i += blockDim.x) {
        float4 v = src[i];
        dst[i] = make_uint2(pack_h2(v.x, v.y), pack_h2(v.z, v.w));
    }
}

// ---------------- GEMM common ----------------
#define PS      16384
#define NSTG    3

// ---------------- GEMM1: h1/h3 fp16 + fused SiLU (BK=64) ----------------
#define G1_STAGE  (3 * PS)
#define G1_SMEM   (NSTG * G1_STAGE)

__global__ __launch_bounds__(256) void gemm1_mma(void) {
    int e   = blockIdx.z;
    int cnt = g_cnt[e];
    int m0  = blockIdx.y * 128;
    if (m0 >= cnt) return;
    int n0  = blockIdx.x * 128;

    extern __shared__ char sm[];
    uint32_t sb = smem_u32(sm);
    int tid = threadIdx.x, lane = tid & 31, wid = tid >> 5;
    int wm = (wid & 1) * 64, wn = (wid >> 1) * 32;
    int g = lane >> 2, tg = lane & 3;
    int lane15 = lane & 15;
    int lchunk = lane >> 4;

    const __half* srcs[3] = {
        g_bufh + ((size_t)e * CAP  + m0) * H_,
        g_w1h  + ((size_t)e * IDIM + n0) * H_,
        g_w3h  + ((size_t)e * IDIM + n0) * H_
    };
    int lrow = tid >> 1;
    int half = tid & 1;

    #pragma unroll
    for (int st = 0; st < NSTG - 1; st++) {
        uint32_t s0 = sb + st * G1_STAGE;
        int k0 = st * 64;
        #pragma unroll
        for (int p = 0; p < 3; p++) {
            const __half* gp = srcs[p] + (size_t)lrow * H_ + k0;
            #pragma unroll
            for (int j = 0; j < 4; j++) {
                int ch = half * 4 + j;
                cp16(swz(s0 + p * PS, lrow, ch), gp + ch * 8);
            }
        }
        cp_commit();
    }

    float c1[4][4][4] = {}, c3[4][4][4] = {};

    const int NK = H_ / 64;
    for (int kt = 0; kt < NK; kt++) {
        cp_wait1();
        __syncthreads();
        if (kt + NSTG - 1 < NK) {
            uint32_t s0 = sb + ((kt + NSTG - 1) % NSTG) * G1_STAGE;
            int k0 = (kt + NSTG - 1) * 64;
            #pragma unroll
            for (int p = 0; p < 3; p++) {
                const __half* gp = srcs[p] + (size_t)lrow * H_ + k0;
                #pragma unroll
                for (int j = 0; j < 4; j++) {
                    int ch = half * 4 + j;
                    cp16(swz(s0 + p * PS, lrow, ch), gp + ch * 8);
                }
            }
        }
        cp_commit();

        uint32_t bs = sb + (kt % NSTG) * G1_STAGE;
        #pragma unroll
        for (int kb = 0; kb < 4; kb++) {
            int ch = kb * 2 + lchunk;
            uint32_t Af[4][4];
            #pragma unroll
            for (int mi = 0; mi < 4; mi++)
                LDSM4(Af[mi], swz(bs, wm + lane15 + mi * 16, ch));
            uint32_t t_[4], Bf[4][2];
            #pragma unroll
            for (int n2 = 0; n2 < 2; n2++) {
                LDSM4(t_, swz(bs + PS, wn + lane15 + n2 * 16, ch));
                Bf[2 * n2][0] = t_[0]; Bf[2 * n2][1] = t_[2];
                Bf[2 * n2 + 1][0] = t_[1]; Bf[2 * n2 + 1][1] = t_[3];
            }
            #pragma unroll
            for (int mi = 0; mi < 4; mi++)
                #pragma unroll
                for (int ni = 0; ni < 4; ni++)
                    mma_f16(c1[mi][ni], Af[mi], Bf[ni][0], Bf[ni][1]);
            #pragma unroll
            for (int n2 = 0; n2 < 2; n2++) {
                LDSM4(t_, swz(bs + 2 * PS, wn + lane15 + n2 * 16, ch));
                Bf[2 * n2][0] = t_[0]; Bf[2 * n2][1] = t_[2];
                Bf[2 * n2 + 1][0] = t_[1]; Bf[2 * n2 + 1][1] = t_[3];
            }
            #pragma unroll
            for (int mi = 0; mi < 4; mi++)
                #pragma unroll
                for (int ni = 0; ni < 4; ni++)
                    mma_f16(c3[mi][ni], Af[mi], Bf[ni][0], Bf[ni][1]);
        }
    }

    #pragma unroll
    for (int mi = 0; mi < 4; mi++) {
        int r0 = m0 + wm + mi * 16 + g;
        #pragma unroll
        for (int ni = 0; ni < 4; ni++) {
            int cb = n0 + wn + ni * 8 + tg * 2;
            float h1a = c1[mi][ni][0], h1b = c1[mi][ni][1];
            float v0 = h1a / (1.f + expf(-h1a)) * c3[mi][ni][0];
            float v1 = h1b / (1.f + expf(-h1b)) * c3[mi][ni][1];
            float h1c = c1[mi][ni][2], h1d = c1[mi][ni][3];
            float v2 = h1c / (1.f + expf(-h1c)) * c3[mi][ni][2];
            float v3 = h1d / (1.f + expf(-h1d)) * c3[mi][ni][3];
            size_t o0 = ((size_t)e * CAP + r0) * IDIM + cb;
            *(uint32_t*)(g_acth + o0) = pack_h2(v0, v1);
            size_t o1 = ((size_t)e * CAP + r0 + 8) * IDIM + cb;
            *(uint32_t*)(g_acth + o1) = pack_h2(v2, v3);
        }
    }
}

// ---------------- GEMM2: y = act @ w2^T (BK=64, 2 CTAs/SM), fp32 output ----------------
#define G2_STAGE  (2 * PS)
#define G2_SMEM   (NSTG * G2_STAGE)

__global__ __launch_bounds__(256, 2) void gemm2_mma(void) {
    int e   = blockIdx.z;
    int cnt = g_cnt[e];
    int m0  = blockIdx.y * 128;
    if (m0 >= cnt) return;
    int n0  = blockIdx.x * 128;

    extern __shared__ char sm[];
    uint32_t sb = smem_u32(sm);
    int tid = threadIdx.x, lane = tid & 31, wid = tid >> 5;
    int wm = (wid & 1) * 64, wn = (wid >> 1) * 32;
    int g = lane >> 2, tg = lane & 3;
    int lane15 = lane & 15;
    int lchunk = lane >> 4;

    const __half* srcs[2] = {
        g_acth + ((size_t)e * CAP + m0) * IDIM,
        g_w2h  + ((size_t)e * H_  + n0) * IDIM
    };
    int lrow = tid >> 1;
    int half = tid & 1;

    #pragma unroll
    for (int st = 0; st < NSTG - 1; st++) {
        uint32_t s0 = sb + st * G2_STAGE;
        int k0 = st * 64;
        #pragma unroll
        for (int p = 0; p < 2; p++) {
            const __half* gp = srcs[p] + (size_t)lrow * IDIM + k0;
            #pragma unroll
            for (int j = 0; j < 4; j++) {
                int ch = half * 4 + j;
                cp16(swz(s0 + p * PS, lrow, ch), gp + ch * 8);
            }
        }
        cp_commit();
    }

    float cc[4][4][4] = {};

    const int NK = IDIM / 64;
    for (int kt = 0; kt < NK; kt++) {
        cp_wait1();
        __syncthreads();
        if (kt + NSTG - 1 < NK) {
            uint32_t s0 = sb + ((kt + NSTG - 1) % NSTG) * G2_STAGE;
            int k0 = (kt + NSTG - 1) * 64;
            #pragma unroll
            for (int p = 0; p < 2; p++) {
                const __half* gp = srcs[p] + (size_t)lrow * IDIM + k0;
                #pragma unroll
                for (int j = 0; j < 4; j++) {
                    int ch = half * 4 + j;
                    cp16(swz(s0 + p * PS, lrow, ch), gp + ch * 8);
                }
            }
        }
        cp_commit();

        uint32_t bs = sb + (kt % NSTG) * G2_STAGE;
        #pragma unroll
        for (int kb = 0; kb < 4; kb++) {
            int ch = kb * 2 + lchunk;
            uint32_t Af[4][4];
            #pragma unroll
            for (int mi = 0; mi < 4; mi++)
                LDSM4(Af[mi], swz(bs, wm + lane15 + mi * 16, ch));
            uint32_t t_[4], Bf[4][2];
            #pragma unroll
            for (int n2 = 0; n2 < 2; n2++) {
                LDSM4(t_, swz(bs + PS, wn + lane15 + n2 * 16, ch));
                Bf[2 * n2][0] = t_[0]; Bf[2 * n2][1] = t_[2];
                Bf[2 * n2 + 1][0] = t_[1]; Bf[2 * n2 + 1][1] = t_[3];
            }
            #pragma unroll
            for (int mi = 0; mi < 4; mi++)
                #pragma unroll
                for (int ni = 0; ni < 4; ni++)
                    mma_f16(cc[mi][ni], Af[mi], Bf[ni][0], Bf[ni][1]);
        }
    }

    #pragma unroll
    for (int mi = 0; mi < 4; mi++) {
        int r0 = m0 + wm + mi * 16 + g;
        #pragma unroll
        for (int ni = 0; ni < 4; ni++) {
            int cb = n0 + wn + ni * 8 + tg * 2;
            *(float2*)(g_y + ((size_t)e * CAP + r0) * H_ + cb) =
                make_float2(cc[mi][ni][0], cc[mi][ni][1]);
            *(float2*)(g_y + ((size_t)e * CAP + r0 + 8) * H_ + cb) =
                make_float2(cc[mi][ni][2], cc[mi][ni][3]);
        }
    }
}

// ---------------- combine ----------------
__global__ void combine_kernel(float* __restrict__ out) {
    int t = blockIdx.x;
    int i = threadIdx.x;
    float4 acc = make_float4(0.f, 0.f, 0.f, 0.f);
    #pragma unroll
    for (int k = 0; k < KSEL; k++) {
        int a = t * KSEL + k;
        int slot = g_slot[a];
        if (slot < 0) continue;
        int e = g_expi[a];
        float w = g_gw[a];
        const float4* yr = (const float4*)(g_y + ((size_t)e * CAP + slot) * H_);
        float4 v = yr[i];
        acc.x += w * v.x; acc.y += w * v.y; acc.z += w * v.z; acc.w += w * v.w;
    }
    ((float4*)(out + (size_t)t * H_))[i] = acc;
}

// ---------------- launch ----------------
extern "C" void kernel_launch(void* const* d_in, const int* in_sizes, int n_in,
                              void* d_out, int out_size) {
    (void)in_sizes; (void)n_in; (void)out_size;
    const float* x      = (const float*)d_in[0];
    const float* gate_w = (const float*)d_in[1];
    const float* w1     = (const float*)d_in[2];
    const float* w3     = (const float*)d_in[3];
    const float* w2     = (const float*)d_in[4];
    const float* bias   = (const float*)d_in[5];
    float*       out    = (float*)d_out;

    const int RSMEM = RTOK * H_ * 4;   // 64 KB for score blocks
    cudaFuncSetAttribute(cvt_score, cudaFuncAttributeMaxDynamicSharedMemorySize, RSMEM);
    cudaFuncSetAttribute(gemm1_mma, cudaFuncAttributeMaxDynamicSharedMemorySize, G1_SMEM);
    cudaFuncSetAttribute(gemm2_mma, cudaFuncAttributeMaxDynamicSharedMemorySize, G2_SMEM);

    void *p_w1h, *p_w3h, *p_w2h;
    cudaGetSymbolAddress(&p_w1h, g_w1h);
    cudaGetSymbolAddress(&p_w3h, g_w3h);
    cudaGetSymbolAddress(&p_w2h, g_w2h);

    const int n4 = E_ * IDIM * H_ / 4;
    cvt_score<<<SCORE_BLKS + CVT_BLKS, 256, RSMEM>>>(
        x, gate_w, (const float4*)w1, (const float4*)w3, (const float4*)w2,
        (uint2*)p_w1h, (uint2*)p_w3h, (uint2*)p_w2h, n4);

    route_kernel<<<T_ / 256, 256>>>(bias);
    slot_kernel<<<E_, 1024>>>();
    gather_kernel<<<dim3(CAP, E_), 256>>>(x);
    gemm1_mma<<<dim3(IDIM / 128, CAP / 128, E_), 256, G1_SMEM>>>();
    gemm2_mma<<<dim3(H_ / 128, CAP / 128, E_), 256, G2_SMEM>>>();
    combine_kernel<<<T_, 256>>>(out);
}

// round 15
// speedup vs baseline: 2.8108x; 1.0039x over previous
#include <cuda_runtime.h>
#include <cuda_fp16.h>
#include <math.h>
#include <stdint.h>

#define E_      32
#define KSEL    4
#define H_      1024
#define IDIM    768
#define T_      4096
#define NGROUP  8
#define TOPKG   4
#define CAP     1024
#define NASSIGN (T_ * KSEL)

#define YSCALE     0.00390625f   // 1/256: |y|<~1e6 -> <~4e3, 16x under fp16 max
#define YSCALE_INV 256.0f

// ---------------- scratch (device globals; no allocations) ----------------
__device__ __half g_bufh[(size_t)E_ * CAP * H_];
__device__ __half g_acth[(size_t)E_ * CAP * IDIM];
__device__ __half g_w1h[(size_t)E_ * IDIM * H_];
__device__ __half g_w3h[(size_t)E_ * IDIM * H_];
__device__ __half g_w2h[(size_t)E_ * H_ * IDIM];
__device__ __half g_y[(size_t)E_ * CAP * H_];       // y/256 in fp16
__device__ float  g_sc[(size_t)T_ * E_];
__device__ int    g_cnt [E_];
__device__ int    g_tok [E_ * CAP];
__device__ int    g_expi[NASSIGN];
__device__ int    g_slot[NASSIGN];
__device__ float  g_gw  [NASSIGN];

// ---------------- helpers ----------------
__device__ __forceinline__ uint32_t smem_u32(const void* p) {
    uint32_t a;
    asm("{ .reg .u64 t; cvta.to.shared.u64 t, %1; cvt.u32.u64 %0, t; }" : "=r"(a) : "l"(p));
    return a;
}
__device__ __forceinline__ void cp16(uint32_t dst, const void* src) {
    asm volatile("cp.async.cg.shared.global [%0], [%1], 16;" :: "r"(dst), "l"(src));
}
__device__ __forceinline__ void cp_commit() { asm volatile("cp.async.commit_group;"); }
__device__ __forceinline__ void cp_wait1()  { asm volatile("cp.async.wait_group 1;"); }
#define LDSM4(r, a) \
    asm volatile("ldmatrix.sync.aligned.m8n8.x4.shared.b16 {%0,%1,%2,%3}, [%4];" \
        : "=r"((r)[0]), "=r"((r)[1]), "=r"((r)[2]), "=r"((r)[3]) : "r"(a))
__device__ __forceinline__ void mma_f16(float* c, const uint32_t* a, uint32_t b0, uint32_t b1) {
    asm volatile(
        "mma.sync.aligned.m16n8k16.row.col.f32.f16.f16.f32 "
        "{%0,%1,%2,%3}, {%4,%5,%6,%7}, {%8,%9}, {%0,%1,%2,%3};"
        : "+f"(c[0]), "+f"(c[1]), "+f"(c[2]), "+f"(c[3])
        : "r"(a[0]), "r"(a[1]), "r"(a[2]), "r"(a[3]), "r"(b0), "r"(b1));
}
__device__ __forceinline__ uint32_t pack_h2(float x, float y) {
    __half2 h = __floats2half2_rn(x, y);
    return *(uint32_t*)&h;
}
__device__ __forceinline__ uint32_t swz(uint32_t base, int row, int chunk) {
    return base + (uint32_t)row * 128u + ((uint32_t)(chunk ^ (row & 7)) << 4);
}

// ---------------- merged kernel: score (blocks 0..255) + weight cvt (blocks 256+) ----
#define RTOK 16
#define SCORE_BLKS (T_ / RTOK)
#define CVT_BLKS   2048
__global__ __launch_bounds__(256) void cvt_score(
    const float* __restrict__ x, const float* __restrict__ gate_w,
    const float4* __restrict__ w1, const float4* __restrict__ w3,
    const float4* __restrict__ w2,
    uint2* __restrict__ o1, uint2* __restrict__ o3, uint2* __restrict__ o2, int n4) {
    int tid = threadIdx.x;
    if (blockIdx.x < SCORE_BLKS) {
        extern __shared__ float xs[];
        int lane = tid & 31, w = tid >> 5;
        int tb = blockIdx.x * RTOK;
        const float4* xg = (const float4*)(x + (size_t)tb * H_);
        float4* xs4 = (float4*)xs;
        #pragma unroll
        for (int i = 0; i < RTOK * (H_ / 4) / 256; i++) xs4[tid + i * 256] = xg[tid + i * 256];
        __syncthreads();
        #pragma unroll
        for (int j = 0; j < 4; j++) {
            int e = w * 4 + j;
            const float4* g4 = (const float4*)(gate_w + (size_t)e * H_);
            float acc[RTOK];
            #pragma unroll
            for (int t = 0; t < RTOK; t++) acc[t] = 0.f;
            for (int it = 0; it < 8; it++) {
                float4 gv = g4[it * 32 + lane];
                #pragma unroll
                for (int t = 0; t < RTOK; t++) {
                    float4 xv = *(const float4*)&xs[t * H_ + (it * 32 + lane) * 4];
                    acc[t] += gv.x * xv.x + gv.y * xv.y + gv.z * xv.z + gv.w * xv.w;
                }
            }
            #pragma unroll
            for (int t = 0; t < RTOK; t++) {
                float v = acc[t];
                #pragma unroll
                for (int o = 16; o; o >>= 1) v += __shfl_xor_sync(0xffffffffu, v, o);
                if (lane == 0) g_sc[(size_t)(tb + t) * E_ + e] = v;
            }
        }
    } else {
        int b = blockIdx.x - SCORE_BLKS;
        int stride = CVT_BLKS * 256;
        for (int i = b * 256 + tid; i < n4; i += stride) {
            float4 v = w1[i];
            o1[i] = make_uint2(pack_h2(v.x, v.y), pack_h2(v.z, v.w));
        }
        for (int i = b * 256 + tid; i < n4; i += stride) {
            float4 v = w3[i];
            o3[i] = make_uint2(pack_h2(v.x, v.y), pack_h2(v.z, v.w));
        }
        for (int i = b * 256 + tid; i < n4; i += stride) {
            float4 v = w2[i];
            o2[i] = make_uint2(pack_h2(v.x, v.y), pack_h2(v.z, v.w));
        }
    }
}

// ---------------- router stage 2: top-k, register-only bitmask selection ----------------
__global__ __launch_bounds__(256) void route_kernel(const float* __restrict__ bias) {
    int t = blockIdx.x * blockDim.x + threadIdx.x;
    if (t >= T_) return;

    float s[E_], sfc[E_];
    #pragma unroll
    for (int e = 0; e < E_; e++) {
        float v = g_sc[(size_t)t * E_ + e];
        s[e]   = 1.f / (1.f + expf(-v));
        sfc[e] = s[e] + bias[e];
    }
    float gs[NGROUP];
    #pragma unroll
    for (int g = 0; g < NGROUP; g++) {
        float m1 = -1e30f, m2 = -1e30f;
        #pragma unroll
        for (int j = 0; j < 4; j++) {
            float v = sfc[g * 4 + j];
            if (v > m1) { m2 = m1; m1 = v; }
            else if (v > m2) m2 = v;
        }
        gs[g] = m1 + m2;
    }
    uint32_t gmask = 0;
    #pragma unroll
    for (int it = 0; it < TOPKG; it++) {
        float best = -1e30f; int bi = 0;
        #pragma unroll
        for (int g = 0; g < NGROUP; g++) {
            bool c = !((gmask >> g) & 1u) && gs[g] > best;
            if (c) { best = gs[g]; bi = g; }
        }
        gmask |= 1u << bi;
    }
    uint32_t emask = 0;
    int   sel[KSEL];
    float rw[KSEL];
    #pragma unroll
    for (int k = 0; k < KSEL; k++) {
        float best = -1e30f, braw = 0.f; int bi = 0;
        #pragma unroll
        for (int e = 0; e < E_; e++) {
            float v = ((gmask >> (e >> 2)) & 1u) ? sfc[e] : 0.f;
            bool c = !((emask >> e) & 1u) && v > best;
            if (c) { best = v; bi = e; braw = s[e]; }
        }
        emask |= 1u << bi;
        sel[k] = bi;
        rw[k]  = braw;
    }
    float inv = 1.f / (rw[0] + rw[1] + rw[2] + rw[3]);
    #pragma unroll
    for (int k = 0; k < KSEL; k++) {
        int a = t * KSEL + k;
        g_expi[a] = sel[k];
        g_gw[a]   = rw[k] * inv;
    }
}

// ---------------- slot: single-pass scan ----------------
__global__ __launch_bounds__(1024) void slot_kernel() {
    int e = blockIdx.x, tid = threadIdx.x;
    int lane = tid & 31, warp = tid >> 5;
    __shared__ int wsum[32];

    int a0 = tid * 16;
    int ex[16];
    int cnt = 0;
    #pragma unroll
    for (int j = 0; j < 16; j++) {
        ex[j] = g_expi[a0 + j];
        cnt += (ex[j] == e);
    }
    int inc = cnt;
    #pragma unroll
    for (int o = 1; o < 32; o <<= 1) {
        int n = __shfl_up_sync(0xffffffffu, inc, o);
        if (lane >= o) inc += n;
    }
    if (lane == 31) wsum[warp] = inc;
    __syncthreads();
    if (warp == 0) {
        int v = wsum[lane];
        #pragma unroll
        for (int o = 1; o < 32; o <<= 1) {
            int n = __shfl_up_sync(0xffffffffu, v, o);
            if (lane >= o) v += n;
        }
        wsum[lane] = v;
    }
    __syncthreads();
    int woff  = (warp == 0) ? 0 : wsum[warp - 1];
    int start = woff + inc - cnt;
    #pragma unroll
    for (int j = 0; j < 16; j++) {
        if (ex[j] == e) {
            int a = a0 + j;
            if (start < CAP) {
                g_slot[a] = start;
                g_tok[e * CAP + start] = a >> 2;
            } else {
                g_slot[a] = -1;
            }
            start++;
        }
    }
    if (tid == 1023) g_cnt[e] = (woff + inc) < CAP ? (woff + inc) : CAP;
}

// gather: token rows -> per-expert fp16 buffers
__global__ void gather_kernel(const float* __restrict__ x) {
    int e = blockIdx.y, slot = blockIdx.x;
    if (slot >= g_cnt[e]) return;
    int t = g_tok[e * CAP + slot];
    const float4* src = (const float4*)(x + (size_t)t * H_);
    uint2* dst = (uint2*)(g_bufh + ((size_t)e * CAP + slot) * H_);
    for (int i = threadIdx.x; i < H_ / 4; i += blockDim.x) {
        float4 v = src[i];
        dst[i] = make_uint2(pack_h2(v.x, v.y), pack_h2(v.z, v.w));
    }
}

// ---------------- GEMM common ----------------
#define PS      16384
#define NSTG    3

// ---------------- GEMM1: h1/h3 fp16 + fused SiLU (BK=64) ----------------
#define G1_STAGE  (3 * PS)
#define G1_SMEM   (NSTG * G1_STAGE)

__global__ __launch_bounds__(256) void gemm1_mma(void) {
    int e   = blockIdx.z;
    int cnt = g_cnt[e];
    int m0  = blockIdx.y * 128;
    if (m0 >= cnt) return;
    int n0  = blockIdx.x * 128;

    extern __shared__ char sm[];
    uint32_t sb = smem_u32(sm);
    int tid = threadIdx.x, lane = tid & 31, wid = tid >> 5;
    int wm = (wid & 1) * 64, wn = (wid >> 1) * 32;
    int g = lane >> 2, tg = lane & 3;
    int lane15 = lane & 15;
    int lchunk = lane >> 4;

    const __half* srcs[3] = {
        g_bufh + ((size_t)e * CAP  + m0) * H_,
        g_w1h  + ((size_t)e * IDIM + n0) * H_,
        g_w3h  + ((size_t)e * IDIM + n0) * H_
    };
    int lrow = tid >> 1;
    int half = tid & 1;

    #pragma unroll
    for (int st = 0; st < NSTG - 1; st++) {
        uint32_t s0 = sb + st * G1_STAGE;
        int k0 = st * 64;
        #pragma unroll
        for (int p = 0; p < 3; p++) {
            const __half* gp = srcs[p] + (size_t)lrow * H_ + k0;
            #pragma unroll
            for (int j = 0; j < 4; j++) {
                int ch = half * 4 + j;
                cp16(swz(s0 + p * PS, lrow, ch), gp + ch * 8);
            }
        }
        cp_commit();
    }

    float c1[4][4][4] = {}, c3[4][4][4] = {};

    const int NK = H_ / 64;
    for (int kt = 0; kt < NK; kt++) {
        cp_wait1();
        __syncthreads();
        if (kt + NSTG - 1 < NK) {
            uint32_t s0 = sb + ((kt + NSTG - 1) % NSTG) * G1_STAGE;
            int k0 = (kt + NSTG - 1) * 64;
            #pragma unroll
            for (int p = 0; p < 3; p++) {
                const __half* gp = srcs[p] + (size_t)lrow * H_ + k0;
                #pragma unroll
                for (int j = 0; j < 4; j++) {
                    int ch = half * 4 + j;
                    cp16(swz(s0 + p * PS, lrow, ch), gp + ch * 8);
                }
            }
        }
        cp_commit();

        uint32_t bs = sb + (kt % NSTG) * G1_STAGE;
        #pragma unroll
        for (int kb = 0; kb < 4; kb++) {
            int ch = kb * 2 + lchunk;
            uint32_t Af[4][4];
            #pragma unroll
            for (int mi = 0; mi < 4; mi++)
                LDSM4(Af[mi], swz(bs, wm + lane15 + mi * 16, ch));
            uint32_t t_[4], Bf[4][2];
            #pragma unroll
            for (int n2 = 0; n2 < 2; n2++) {
                LDSM4(t_, swz(bs + PS, wn + lane15 + n2 * 16, ch));
                Bf[2 * n2][0] = t_[0]; Bf[2 * n2][1] = t_[2];
                Bf[2 * n2 + 1][0] = t_[1]; Bf[2 * n2 + 1][1] = t_[3];
            }
            #pragma unroll
            for (int mi = 0; mi < 4; mi++)
                #pragma unroll
                for (int ni = 0; ni < 4; ni++)
                    mma_f16(c1[mi][ni], Af[mi], Bf[ni][0], Bf[ni][1]);
            #pragma unroll
            for (int n2 = 0; n2 < 2; n2++) {
                LDSM4(t_, swz(bs + 2 * PS, wn + lane15 + n2 * 16, ch));
                Bf[2 * n2][0] = t_[0]; Bf[2 * n2][1] = t_[2];
                Bf[2 * n2 + 1][0] = t_[1]; Bf[2 * n2 + 1][1] = t_[3];
            }
            #pragma unroll
            for (int mi = 0; mi < 4; mi++)
                #pragma unroll
                for (int ni = 0; ni < 4; ni++)
                    mma_f16(c3[mi][ni], Af[mi], Bf[ni][0], Bf[ni][1]);
        }
    }

    #pragma unroll
    for (int mi = 0; mi < 4; mi++) {
        int r0 = m0 + wm + mi * 16 + g;
        #pragma unroll
        for (int ni = 0; ni < 4; ni++) {
            int cb = n0 + wn + ni * 8 + tg * 2;
            float h1a = c1[mi][ni][0], h1b = c1[mi][ni][1];
            float v0 = h1a / (1.f + expf(-h1a)) * c3[mi][ni][0];
            float v1 = h1b / (1.f + expf(-h1b)) * c3[mi][ni][1];
            float h1c = c1[mi][ni][2], h1d = c1[mi][ni][3];
            float v2 = h1c / (1.f + expf(-h1c)) * c3[mi][ni][2];
            float v3 = h1d / (1.f + expf(-h1d)) * c3[mi][ni][3];
            size_t o0 = ((size_t)e * CAP + r0) * IDIM + cb;
            *(uint32_t*)(g_acth + o0) = pack_h2(v0, v1);
            size_t o1 = ((size_t)e * CAP + r0 + 8) * IDIM + cb;
            *(uint32_t*)(g_acth + o1) = pack_h2(v2, v3);
        }
    }
}

// ---------------- GEMM2: y = act @ w2^T (BK=64, 2 CTAs/SM), scaled fp16 output ----------------
#define G2_STAGE  (2 * PS)
#define G2_SMEM   (NSTG * G2_STAGE)

__global__ __launch_bounds__(256, 2) void gemm2_mma(void) {
    int e   = blockIdx.z;
    int cnt = g_cnt[e];
    int m0  = blockIdx.y * 128;
    if (m0 >= cnt) return;
    int n0  = blockIdx.x * 128;

    extern __shared__ char sm[];
    uint32_t sb = smem_u32(sm);
    int tid = threadIdx.x, lane = tid & 31, wid = tid >> 5;
    int wm = (wid & 1) * 64, wn = (wid >> 1) * 32;
    int g = lane >> 2, tg = lane & 3;
    int lane15 = lane & 15;
    int lchunk = lane >> 4;

    const __half* srcs[2] = {
        g_acth + ((size_t)e * CAP + m0) * IDIM,
        g_w2h  + ((size_t)e * H_  + n0) * IDIM
    };
    int lrow = tid >> 1;
    int half = tid & 1;

    #pragma unroll
    for (int st = 0; st < NSTG - 1; st++) {
        uint32_t s0 = sb + st * G2_STAGE;
        int k0 = st * 64;
        #pragma unroll
        for (int p = 0; p < 2; p++) {
            const __half* gp = srcs[p] + (size_t)lrow * IDIM + k0;
            #pragma unroll
            for (int j = 0; j < 4; j++) {
                int ch = half * 4 + j;
                cp16(swz(s0 + p * PS, lrow, ch), gp + ch * 8);
            }
        }
        cp_commit();
    }

    float cc[4][4][4] = {};

    const int NK = IDIM / 64;
    for (int kt = 0; kt < NK; kt++) {
        cp_wait1();
        __syncthreads();
        if (kt + NSTG - 1 < NK) {
            uint32_t s0 = sb + ((kt + NSTG - 1) % NSTG) * G2_STAGE;
            int k0 = (kt + NSTG - 1) * 64;
            #pragma unroll
            for (int p = 0; p < 2; p++) {
                const __half* gp = srcs[p] + (size_t)lrow * IDIM + k0;
                #pragma unroll
                for (int j = 0; j < 4; j++) {
                    int ch = half * 4 + j;
                    cp16(swz(s0 + p * PS, lrow, ch), gp + ch * 8);
                }
            }
        }
        cp_commit();

        uint32_t bs = sb + (kt % NSTG) * G2_STAGE;
        #pragma unroll
        for (int kb = 0; kb < 4; kb++) {
            int ch = kb * 2 + lchunk;
            uint32_t Af[4][4];
            #pragma unroll
            for (int mi = 0; mi < 4; mi++)
                LDSM4(Af[mi], swz(bs, wm + lane15 + mi * 16, ch));
            uint32_t t_[4], Bf[4][2];
            #pragma unroll
            for (int n2 = 0; n2 < 2; n2++) {
                LDSM4(t_, swz(bs + PS, wn + lane15 + n2 * 16, ch));
                Bf[2 * n2][0] = t_[0]; Bf[2 * n2][1] = t_[2];
                Bf[2 * n2 + 1][0] = t_[1]; Bf[2 * n2 + 1][1] = t_[3];
            }
            #pragma unroll
            for (int mi = 0; mi < 4; mi++)
                #pragma unroll
                for (int ni = 0; ni < 4; ni++)
                    mma_f16(cc[mi][ni], Af[mi], Bf[ni][0], Bf[ni][1]);
        }
    }

    // epilogue: y/256 -> fp16 (max |y|~1e6 -> ~4e3, safe)
    #pragma unroll
    for (int mi = 0; mi < 4; mi++) {
        int r0 = m0 + wm + mi * 16 + g;
        #pragma unroll
        for (int ni = 0; ni < 4; ni++) {
            int cb = n0 + wn + ni * 8 + tg * 2;
            *(uint32_t*)(g_y + ((size_t)e * CAP + r0) * H_ + cb) =
                pack_h2(cc[mi][ni][0] * YSCALE, cc[mi][ni][1] * YSCALE);
            *(uint32_t*)(g_y + ((size_t)e * CAP + r0 + 8) * H_ + cb) =
                pack_h2(cc[mi][ni][2] * YSCALE, cc[mi][ni][3] * YSCALE);
        }
    }
}

// ---------------- combine: scaled-fp16 y -> fp32 out ----------------
__global__ void combine_kernel(float* __restrict__ out) {
    int t = blockIdx.x;
    int i = threadIdx.x;
    float4 acc = make_float4(0.f, 0.f, 0.f, 0.f);
    #pragma unroll
    for (int k = 0; k < KSEL; k++) {
        int a = t * KSEL + k;
        int slot = g_slot[a];
        if (slot < 0) continue;
        int e = g_expi[a];
        float w = g_gw[a] * YSCALE_INV;
        const uint2* yr = (const uint2*)(g_y + ((size_t)e * CAP + slot) * H_);
        uint2 v = yr[i];
        float2 f01 = __half22float2(*(__half2*)&v.x);
        float2 f23 = __half22float2(*(__half2*)&v.y);
        acc.x += w * f01.x; acc.y += w * f01.y;
        acc.z += w * f23.x; acc.w += w * f23.y;
    }
    ((float4*)(out + (size_t)t * H_))[i] = acc;
}

// ---------------- launch ----------------
extern "C" void kernel_launch(void* const* d_in, const int* in_sizes, int n_in,
                              void* d_out, int out_size) {
    (void)in_sizes; (void)n_in; (void)out_size;
    const float* x      = (const float*)d_in[0];
    const float* gate_w = (const float*)d_in[1];
    const float* w1     = (const float*)d_in[2];
    const float* w3     = (const float*)d_in[3];
    const float* w2     = (const float*)d_in[4];
    const float* bias   = (const float*)d_in[5];
    float*       out    = (float*)d_out;

    const int RSMEM = RTOK * H_ * 4;
    cudaFuncSetAttribute(cvt_score, cudaFuncAttributeMaxDynamicSharedMemorySize, RSMEM);
    cudaFuncSetAttribute(gemm1_mma, cudaFuncAttributeMaxDynamicSharedMemorySize, G1_SMEM);
    cudaFuncSetAttribute(gemm2_mma, cudaFuncAttributeMaxDynamicSharedMemorySize, G2_SMEM);

    void *p_w1h, *p_w3h, *p_w2h;
    cudaGetSymbolAddress(&p_w1h, g_w1h);
    cudaGetSymbolAddress(&p_w3h, g_w3h);
    cudaGetSymbolAddress(&p_w2h, g_w2h);

    const int n4 = E_ * IDIM * H_ / 4;
    cvt_score<<<SCORE_BLKS + CVT_BLKS, 256, RSMEM>>>(
        x, gate_w, (const float4*)w1, (const float4*)w3, (const float4*)w2,
        (uint2*)p_w1h, (uint2*)p_w3h, (uint2*)p_w2h, n4);

    route_kernel<<<T_ / 256, 256>>>(bias);
    slot_kernel<<<E_, 1024>>>();
    gather_kernel<<<dim3(CAP, E_), 256>>>(x);
    gemm1_mma<<<dim3(IDIM / 128, CAP / 128, E_), 256, G1_SMEM>>>();
    gemm2_mma<<<dim3(H_ / 128, CAP / 128, E_), 256, G2_SMEM>>>();
    combine_kernel<<<T_, 256>>>(out);
}